// round 3
// baseline (speedup 1.0000x reference)
#include <cuda_runtime.h>
#include <math.h>

#define EMBED 768
#define HEADS 12
#define HDIM  64
#define BATCH 2
#define SEQ   2048
#define MROWS (BATCH * SEQ)      // 4096
#define BH    (BATCH * HEADS)    // 24
#define NX (MROWS * EMBED)
#define NW (EMBED * EMBED)

typedef unsigned long long u64;

// packed fp32x2 helpers (sm_103a FFMA2 path — only reachable via PTX)
#define FMA2(d, a, b, c) asm("fma.rn.f32x2 %0, %1, %2, %3;" : "=l"(d) : "l"(a), "l"(b), "l"(c))
#define MUL2(d, a, b)    asm("mul.rn.f32x2 %0, %1, %2;" : "=l"(d) : "l"(a), "l"(b))
#define DUP2(d, s)       asm("mov.b64 %0, {%1, %1};" : "=l"(d) : "f"(s))
#define UNPK2(lo, hi, v) asm("mov.b64 {%0, %1}, %2;" : "=f"(lo), "=f"(hi) : "l"(v))

// ---------------- scratch ----------------
__device__ float g_Q[BH * SEQ * HDIM];     // [bh][s][d], pre-scaled by 1/sqrt(d)
__device__ float g_K[BH * SEQ * HDIM];
__device__ float g_V[BH * SEQ * HDIM];
__device__ float g_A[MROWS * EMBED];       // attention output, [b*S+s][e]

// ---------------- GEMM: Y = X @ W^T + b  (f32x2 inner) ----------------
#define BM 128
#define BN 64
#define BK 16

__global__ void __launch_bounds__(256)
gemm_bias_kernel(const float* __restrict__ X, const float* __restrict__ W,
                 const float* __restrict__ bias, float* __restrict__ Y,
                 int mode, float scale)
{
    __shared__ float Xs[BK][BM];   // [k][m]
    __shared__ float Ws[BK][BN];   // [k][n]

    const int tid = threadIdx.x;
    const int tx  = tid & 15;      // n = tx*4
    const int ty  = tid >> 4;      // m = ty*8
    const int m0  = blockIdx.y * BM;
    const int n0  = blockIdx.x * BN;

    const int xlrow = tid >> 1;          // 0..127
    const int xlcol = (tid & 1) * 8;
    const int wlrow = tid >> 2;          // 0..63
    const int wlcol = (tid & 3) * 4;

    // acc2[p][j]: rows (2p, 2p+1) of the 8-row micro-tile, col j
    u64 acc2[4][4];
#pragma unroll
    for (int p = 0; p < 4; p++)
#pragma unroll
        for (int j = 0; j < 4; j++) acc2[p][j] = 0ULL;

    for (int k0 = 0; k0 < EMBED; k0 += BK) {
        float4 x0 = *(const float4*)&X[(size_t)(m0 + xlrow) * EMBED + k0 + xlcol];
        float4 x1 = *(const float4*)&X[(size_t)(m0 + xlrow) * EMBED + k0 + xlcol + 4];
        float4 wv = *(const float4*)&W[(size_t)(n0 + wlrow) * EMBED + k0 + wlcol];
        __syncthreads();
        Xs[xlcol + 0][xlrow] = x0.x;
        Xs[xlcol + 1][xlrow] = x0.y;
        Xs[xlcol + 2][xlrow] = x0.z;
        Xs[xlcol + 3][xlrow] = x0.w;
        Xs[xlcol + 4][xlrow] = x1.x;
        Xs[xlcol + 5][xlrow] = x1.y;
        Xs[xlcol + 6][xlrow] = x1.z;
        Xs[xlcol + 7][xlrow] = x1.w;
        Ws[wlcol + 0][wlrow] = wv.x;
        Ws[wlcol + 1][wlrow] = wv.y;
        Ws[wlcol + 2][wlrow] = wv.z;
        Ws[wlcol + 3][wlrow] = wv.w;
        __syncthreads();
#pragma unroll
        for (int kk = 0; kk < BK; kk++) {
            // a-side: 8 rows as 4 packed pairs (free packing via 16B loads)
            ulonglong2 aa0 = *(const ulonglong2*)&Xs[kk][ty * 8];
            ulonglong2 aa1 = *(const ulonglong2*)&Xs[kk][ty * 8 + 4];
            u64 ap[4] = {aa0.x, aa0.y, aa1.x, aa1.y};
            // b-side: 4 scalar cols, duplicated
            float4 b = *(const float4*)&Ws[kk][tx * 4];
            u64 bd[4];
            DUP2(bd[0], b.x); DUP2(bd[1], b.y); DUP2(bd[2], b.z); DUP2(bd[3], b.w);
#pragma unroll
            for (int p = 0; p < 4; p++)
#pragma unroll
                for (int j = 0; j < 4; j++)
                    FMA2(acc2[p][j], ap[p], bd[j], acc2[p][j]);
        }
    }

    const int nb = n0 + tx * 4;
    float4 bv = *(const float4*)&bias[nb];

    // unpack to rows
    float acc[8][4];
#pragma unroll
    for (int p = 0; p < 4; p++)
#pragma unroll
        for (int j = 0; j < 4; j++) {
            float lo, hi;
            UNPK2(lo, hi, acc2[p][j]);
            acc[2 * p][j]     = lo;
            acc[2 * p + 1][j] = hi;
        }

    if (mode == 0) {
        const int h  = nb >> 6;
        const int d0 = nb & 63;
#pragma unroll
        for (int i = 0; i < 8; i++) {
            int m = m0 + ty * 8 + i;
            int b = m >> 11;
            int s = m & 2047;
            float4 r;
            r.x = (acc[i][0] + bv.x) * scale;
            r.y = (acc[i][1] + bv.y) * scale;
            r.z = (acc[i][2] + bv.z) * scale;
            r.w = (acc[i][3] + bv.w) * scale;
            *(float4*)&Y[((size_t)(b * HEADS + h) * SEQ + s) * HDIM + d0] = r;
        }
    } else {
#pragma unroll
        for (int i = 0; i < 8; i++) {
            int m = m0 + ty * 8 + i;
            float4 r;
            r.x = acc[i][0] + bv.x;
            r.y = acc[i][1] + bv.y;
            r.z = acc[i][2] + bv.z;
            r.w = acc[i][3] + bv.w;
            *(float4*)&Y[(size_t)m * EMBED + nb] = r;
        }
    }
}

// ---------------- Flash attention v2 (f32x2, BR=128 x BC=64) ----------------
#define BR 128
#define BC 64

__global__ void __launch_bounds__(256, 2)
flash_attn_kernel(const float* __restrict__ Q, const float* __restrict__ K,
                  const float* __restrict__ V, float* __restrict__ Aout)
{
    extern __shared__ float sm[];
    float* Qs = sm;             // [d][r]  64 x 128
    float* Ks = sm + 8192;      // [d][c]  64 x 64
    float* Vs = sm + 12288;     // [k][d]  64 x 64
    float* Ps = sm + 16384;     // [r][k]  128 x 64
    // total 24576 floats = 96 KB

    const int tid = threadIdx.x;
    const int tx  = tid & 7;    // 8 d/k cols each
    const int ty  = tid >> 3;   // 0..31, 4 rows each
    const int bh  = blockIdx.y;
    const int q0  = blockIdx.x * BR;

    const float* Qb = Q + (size_t)bh * SEQ * HDIM;
    const float* Kb = K + (size_t)bh * SEQ * HDIM;
    const float* Vb = V + (size_t)bh * SEQ * HDIM;

    // load 128x64 Q tile transposed: Qs[d][r]
    {
        const int qrow = tid >> 1;            // 0..127
        const int qc0  = (tid & 1) * 32;      // 0 or 32
#pragma unroll
        for (int j = 0; j < 8; j++) {
            int c = qc0 + j * 4;
            float4 qv = *(const float4*)&Qb[(size_t)(q0 + qrow) * HDIM + c];
            Qs[(c + 0) * BR + qrow] = qv.x;
            Qs[(c + 1) * BR + qrow] = qv.y;
            Qs[(c + 2) * BR + qrow] = qv.z;
            Qs[(c + 3) * BR + qrow] = qv.w;
        }
    }

    float m_run[4], l_run[4];
    u64 o2[4][4];
#pragma unroll
    for (int i = 0; i < 4; i++) {
        m_run[i] = -INFINITY;
        l_run[i] = 0.f;
#pragma unroll
        for (int j = 0; j < 4; j++) o2[i][j] = 0ULL;
    }

    const int krow = tid >> 2;        // 0..63
    const int kc0  = (tid & 3) * 4;   // 0,4,8,12

    __syncthreads();

    for (int kt = 0; kt < SEQ / BC; kt++) {
        const int k0 = kt * BC;
        // load K/V tiles (K transposed, V direct)
#pragma unroll
        for (int j = 0; j < 4; j++) {
            int c = kc0 + j * 16;
            float4 kv = *(const float4*)&Kb[(size_t)(k0 + krow) * HDIM + c];
            float4 vv = *(const float4*)&Vb[(size_t)(k0 + krow) * HDIM + c];
            Ks[(c + 0) * BC + krow] = kv.x;
            Ks[(c + 1) * BC + krow] = kv.y;
            Ks[(c + 2) * BC + krow] = kv.z;
            Ks[(c + 3) * BC + krow] = kv.w;
            *(float4*)&Vs[krow * 64 + c] = vv;
        }
        __syncthreads();

        // S = Q K^T : 4 rows x 8 cols per thread (cols as 4 packed pairs)
        u64 sacc2[4][4];
#pragma unroll
        for (int i = 0; i < 4; i++)
#pragma unroll
            for (int j = 0; j < 4; j++) sacc2[i][j] = 0ULL;

#pragma unroll 8
        for (int d = 0; d < HDIM; d++) {
            float4 a = *(const float4*)&Qs[d * BR + ty * 4];
            ulonglong2 b0 = *(const ulonglong2*)&Ks[d * BC + tx * 8];
            ulonglong2 b1 = *(const ulonglong2*)&Ks[d * BC + tx * 8 + 4];
            u64 bb[4] = {b0.x, b0.y, b1.x, b1.y};
            u64 ad[4];
            DUP2(ad[0], a.x); DUP2(ad[1], a.y); DUP2(ad[2], a.z); DUP2(ad[3], a.w);
#pragma unroll
            for (int i = 0; i < 4; i++)
#pragma unroll
                for (int j = 0; j < 4; j++)
                    FMA2(sacc2[i][j], ad[i], bb[j], sacc2[i][j]);
        }

        // online softmax; row = 8 lanes (tx 0..7 share ty)
#pragma unroll
        for (int i = 0; i < 4; i++) {
            float s[8];
            UNPK2(s[0], s[1], sacc2[i][0]);
            UNPK2(s[2], s[3], sacc2[i][1]);
            UNPK2(s[4], s[5], sacc2[i][2]);
            UNPK2(s[6], s[7], sacc2[i][3]);
            float pm = s[0];
#pragma unroll
            for (int j = 1; j < 8; j++) pm = fmaxf(pm, s[j]);
#pragma unroll
            for (int off = 4; off >= 1; off >>= 1)
                pm = fmaxf(pm, __shfl_xor_sync(0xffffffffu, pm, off, 8));
            float mn = fmaxf(m_run[i], pm);
            float alpha = __expf(m_run[i] - mn);
            float ps = 0.f;
#pragma unroll
            for (int j = 0; j < 8; j++) {
                s[j] = __expf(s[j] - mn);
                ps += s[j];
            }
#pragma unroll
            for (int off = 4; off >= 1; off >>= 1)
                ps += __shfl_xor_sync(0xffffffffu, ps, off, 8);
            l_run[i] = l_run[i] * alpha + ps;
            m_run[i] = mn;
            u64 al2;
            DUP2(al2, alpha);
#pragma unroll
            for (int j = 0; j < 4; j++) MUL2(o2[i][j], o2[i][j], al2);
            *(float4*)&Ps[(ty * 4 + i) * BC + tx * 8]     = make_float4(s[0], s[1], s[2], s[3]);
            *(float4*)&Ps[(ty * 4 + i) * BC + tx * 8 + 4] = make_float4(s[4], s[5], s[6], s[7]);
        }
        __syncthreads();

        // O += P V : 4 rows x 8 d-cols per thread
#pragma unroll 8
        for (int k = 0; k < BC; k++) {
            ulonglong2 v0 = *(const ulonglong2*)&Vs[k * 64 + tx * 8];
            ulonglong2 v1 = *(const ulonglong2*)&Vs[k * 64 + tx * 8 + 4];
            u64 vb[4] = {v0.x, v0.y, v1.x, v1.y};
            u64 pd[4];
            DUP2(pd[0], Ps[(ty * 4 + 0) * BC + k]);
            DUP2(pd[1], Ps[(ty * 4 + 1) * BC + k]);
            DUP2(pd[2], Ps[(ty * 4 + 2) * BC + k]);
            DUP2(pd[3], Ps[(ty * 4 + 3) * BC + k]);
#pragma unroll
            for (int i = 0; i < 4; i++)
#pragma unroll
                for (int j = 0; j < 4; j++)
                    FMA2(o2[i][j], pd[i], vb[j], o2[i][j]);
        }
        __syncthreads();   // Ps/Ks/Vs fully consumed before next tile overwrites
    }

    // finalize: scatter to [b][s][e], e = h*64 + d
    const int b = bh / HEADS;
    const int h = bh % HEADS;
#pragma unroll
    for (int i = 0; i < 4; i++) {
        int s = q0 + ty * 4 + i;
        float inv = 1.f / l_run[i];
        u64 inv2;
        DUP2(inv2, inv);
        float r[8];
#pragma unroll
        for (int j = 0; j < 4; j++) {
            u64 t;
            MUL2(t, o2[i][j], inv2);
            UNPK2(r[2 * j], r[2 * j + 1], t);
        }
        float* dst = &Aout[((size_t)(b * SEQ + s)) * EMBED + h * HDIM + tx * 8];
        *(float4*)dst       = make_float4(r[0], r[1], r[2], r[3]);
        *(float4*)(dst + 4) = make_float4(r[4], r[5], r[6], r[7]);
    }
}

// ---------------- driver ----------------
extern "C" void kernel_launch(void* const* d_in, const int* in_sizes, int n_in,
                              void* d_out, int out_size)
{
    const float *x, *w_q, *b_q, *w_k, *b_k, *w_v, *b_v, *w_o, *b_o;
    if (n_in == 9 && in_sizes[0] == EMBED && in_sizes[8] == NX) {
        b_k = (const float*)d_in[0]; b_o = (const float*)d_in[1];
        b_q = (const float*)d_in[2]; b_v = (const float*)d_in[3];
        w_k = (const float*)d_in[4]; w_o = (const float*)d_in[5];
        w_q = (const float*)d_in[6]; w_v = (const float*)d_in[7];
        x   = (const float*)d_in[8];
    } else if (n_in == 9 && in_sizes[0] == NX && in_sizes[2] == NW) {
        x   = (const float*)d_in[0];
        w_q = (const float*)d_in[1]; w_k = (const float*)d_in[2];
        w_v = (const float*)d_in[3]; w_o = (const float*)d_in[4];
        b_q = (const float*)d_in[5]; b_k = (const float*)d_in[6];
        b_v = (const float*)d_in[7]; b_o = (const float*)d_in[8];
    } else {
        x   = (const float*)d_in[0];
        w_q = (const float*)d_in[1]; b_q = (const float*)d_in[2];
        w_k = (const float*)d_in[3]; b_k = (const float*)d_in[4];
        w_v = (const float*)d_in[5]; b_v = (const float*)d_in[6];
        w_o = (const float*)d_in[7]; b_o = (const float*)d_in[8];
    }
    float* out = (float*)d_out;

    float *gQ, *gK, *gV, *gA;
    cudaGetSymbolAddress((void**)&gQ, g_Q);
    cudaGetSymbolAddress((void**)&gK, g_K);
    cudaGetSymbolAddress((void**)&gV, g_V);
    cudaGetSymbolAddress((void**)&gA, g_A);

    cudaFuncSetAttribute(flash_attn_kernel,
                         cudaFuncAttributeMaxDynamicSharedMemorySize, 98304);

    dim3 ggrid(EMBED / BN, MROWS / BM);   // (12, 32)
    const float qscale = 0.125f;          // 1/sqrt(HDIM)

    gemm_bias_kernel<<<ggrid, 256>>>(x, w_q, b_q, gQ, 0, qscale);
    gemm_bias_kernel<<<ggrid, 256>>>(x, w_k, b_k, gK, 0, 1.0f);
    gemm_bias_kernel<<<ggrid, 256>>>(x, w_v, b_v, gV, 0, 1.0f);

    dim3 agrid(SEQ / BR, BH);             // (16, 24)
    flash_attn_kernel<<<agrid, 256, 98304>>>(gQ, gK, gV, gA);

    gemm_bias_kernel<<<ggrid, 256>>>(gA, w_o, b_o, out, 1, 1.0f);
}

// round 5
// speedup vs baseline: 1.4306x; 1.4306x over previous
#include <cuda_runtime.h>
#include <cuda_bf16.h>
#include <math.h>

#define EMBED 768
#define HEADS 12
#define HDIM  64
#define BATCH 2
#define SEQ   2048
#define MROWS (BATCH * SEQ)      // 4096
#define BH    (BATCH * HEADS)    // 24
#define NX (MROWS * EMBED)
#define NW (EMBED * EMBED)

// ---------------- scratch ----------------
__device__ float g_Q[BH * SEQ * HDIM];
__device__ float g_K[BH * SEQ * HDIM];
__device__ float g_V[BH * SEQ * HDIM];
__device__ float g_A[MROWS * EMBED];

__device__ __nv_bfloat16 g_Xhi[NX], g_Xlo[NX];
__device__ __nv_bfloat16 g_W0hi[NW], g_W0lo[NW];
__device__ __nv_bfloat16 g_W1hi[NW], g_W1lo[NW];
__device__ __nv_bfloat16 g_W2hi[NW], g_W2lo[NW];
__device__ __nv_bfloat16 g_W3hi[NW], g_W3lo[NW];
__device__ __nv_bfloat16 g_Ahi[NX], g_Alo[NX];

// ---------------- PTX helpers (all family-portable: sm_80+) ----------------
__device__ __forceinline__ unsigned smem_u32(const void* p) {
    unsigned a;
    asm("{ .reg .u64 t; cvta.to.shared.u64 t, %1; cvt.u32.u64 %0, t; }" : "=r"(a) : "l"(p));
    return a;
}
__device__ __forceinline__ void cp16(unsigned s, const void* g) {
    asm volatile("cp.async.cg.shared.global [%0], [%1], 16;" :: "r"(s), "l"(g));
}
__device__ __forceinline__ void cp_commit() { asm volatile("cp.async.commit_group;" ::: "memory"); }
template <int N> __device__ __forceinline__ void cp_wait() {
    asm volatile("cp.async.wait_group %0;" :: "n"(N) : "memory");
}
__device__ __forceinline__ void ldx4(unsigned* r, unsigned addr) {
    asm volatile("ldmatrix.sync.aligned.m8n8.x4.shared.b16 {%0,%1,%2,%3}, [%4];"
        : "=r"(r[0]), "=r"(r[1]), "=r"(r[2]), "=r"(r[3]) : "r"(addr));
}
__device__ __forceinline__ void mma16816(float* d, const unsigned* a, const unsigned* b) {
    asm volatile(
        "mma.sync.aligned.m16n8k16.row.col.f32.bf16.bf16.f32 "
        "{%0,%1,%2,%3}, {%4,%5,%6,%7}, {%8,%9}, {%0,%1,%2,%3};"
        : "+f"(d[0]), "+f"(d[1]), "+f"(d[2]), "+f"(d[3])
        : "r"(a[0]), "r"(a[1]), "r"(a[2]), "r"(a[3]), "r"(b[0]), "r"(b[1]));
}

// ---------------- fp32 -> bf16 hi/lo split ----------------
struct alignas(8) B4 { __nv_bfloat16 v[4]; };

__global__ void __launch_bounds__(256)
convert_kernel(const float* __restrict__ src, __nv_bfloat16* __restrict__ hi,
               __nv_bfloat16* __restrict__ lo, int n)
{
    int i = (blockIdx.x * 256 + threadIdx.x) * 4;
    if (i >= n) return;
    float4 v = *(const float4*)&src[i];
    B4 h, l;
    float f[4] = {v.x, v.y, v.z, v.w};
#pragma unroll
    for (int j = 0; j < 4; j++) {
        h.v[j] = __float2bfloat16(f[j]);
        l.v[j] = __float2bfloat16(f[j] - __bfloat162float(h.v[j]));
    }
    *(B4*)&hi[i] = h;
    *(B4*)&lo[i] = l;
}

// ---------------- HMMA GEMM: Y = X @ W^T + b  (bf16x3) ----------------
// CTA tile 128x64, BK=32, 8 warps (4 along M x 2 along N), warp tile 32x32.
#define GBM 128
#define GBN 64
#define GBK 32
#define KITERS (EMBED / GBK)     // 24
#define ASTR 80                  // bytes per smem row (32 bf16 + 8 pad)
#define A_SZ (128 * ASTR)        // 10240
#define B_SZ (64 * ASTR)         // 5120
#define STAGE (2 * A_SZ + 2 * B_SZ)   // 30720
#define SMEM_GEMM (2 * STAGE)         // 61440

__global__ void __launch_bounds__(256)
mma_gemm_kernel(const __nv_bfloat16* __restrict__ Ahi, const __nv_bfloat16* __restrict__ Alo,
                const __nv_bfloat16* __restrict__ Bhi, const __nv_bfloat16* __restrict__ Blo,
                const float* __restrict__ bias, float* __restrict__ Y,
                int mode, float scale)
{
    extern __shared__ char smraw[];
    const unsigned sb = smem_u32(smraw);

    const int tid  = threadIdx.x;
    const int lane = tid & 31;
    const int wid  = tid >> 5;
    const int warpM = wid & 3;
    const int warpN = wid >> 2;
    const int m0 = blockIdx.y * GBM;
    const int n0 = blockIdx.x * GBN;

    // per-stage sub-bases
    auto sA_hi = [&](int s) { return sb + s * STAGE; };
    auto sA_lo = [&](int s) { return sb + s * STAGE + A_SZ; };
    auto sB_hi = [&](int s) { return sb + s * STAGE + 2 * A_SZ; };
    auto sB_lo = [&](int s) { return sb + s * STAGE + 2 * A_SZ + B_SZ; };

    // loader indices: A 512 16B-chunks (2/thread), B 256 (1/thread)
    const int ar0 = (tid * 2) >> 2, ac0 = (tid * 2) & 3;        // task 2*tid
    const int ar1 = (tid * 2 + 1) >> 2, ac1 = (tid * 2 + 1) & 3;
    const int br = tid >> 2, bc = tid & 3;

    auto load_stage = [&](int kt, int s) {
        const int k0 = kt * GBK;
        const __nv_bfloat16* pah = Ahi + (size_t)m0 * EMBED + k0;
        const __nv_bfloat16* pal = Alo + (size_t)m0 * EMBED + k0;
        const __nv_bfloat16* pbh = Bhi + (size_t)n0 * EMBED + k0;
        const __nv_bfloat16* pbl = Blo + (size_t)n0 * EMBED + k0;
        cp16(sA_hi(s) + ar0 * ASTR + ac0 * 16, pah + (size_t)ar0 * EMBED + ac0 * 8);
        cp16(sA_hi(s) + ar1 * ASTR + ac1 * 16, pah + (size_t)ar1 * EMBED + ac1 * 8);
        cp16(sA_lo(s) + ar0 * ASTR + ac0 * 16, pal + (size_t)ar0 * EMBED + ac0 * 8);
        cp16(sA_lo(s) + ar1 * ASTR + ac1 * 16, pal + (size_t)ar1 * EMBED + ac1 * 8);
        cp16(sB_hi(s) + br * ASTR + bc * 16,   pbh + (size_t)br * EMBED + bc * 8);
        cp16(sB_lo(s) + br * ASTR + bc * 16,   pbl + (size_t)br * EMBED + bc * 8);
    };

    // ldmatrix per-lane offsets
    const unsigned aOff = (unsigned)((warpM * 32 + ((lane >> 3) & 1) * 8 + (lane & 7)) * ASTR
                                     + (lane >> 4) * 16);
    const unsigned bOff = (unsigned)((warpN * 32 + ((lane >> 4) & 1) * 8 + (lane & 7)) * ASTR
                                     + ((lane >> 3) & 1) * 16);

    float acc[2][4][4];
#pragma unroll
    for (int mt = 0; mt < 2; mt++)
#pragma unroll
        for (int nt = 0; nt < 4; nt++)
#pragma unroll
            for (int j = 0; j < 4; j++) acc[mt][nt][j] = 0.f;

    load_stage(0, 0);
    cp_commit();

    for (int kt = 0; kt < KITERS; kt++) {
        const int s = kt & 1;
        if (kt + 1 < KITERS) {
            load_stage(kt + 1, s ^ 1);
            cp_commit();
            cp_wait<1>();
        } else {
            cp_wait<0>();
        }
        __syncthreads();

#pragma unroll
        for (int ks = 0; ks < 2; ks++) {
            unsigned a_h[2][4], a_l[2][4], b_h[2][4], b_l[2][4];
#pragma unroll
            for (int mt = 0; mt < 2; mt++) {
                ldx4(a_h[mt], sA_hi(s) + aOff + mt * (16 * ASTR) + ks * 32);
                ldx4(a_l[mt], sA_lo(s) + aOff + mt * (16 * ASTR) + ks * 32);
            }
#pragma unroll
            for (int p = 0; p < 2; p++) {
                ldx4(b_h[p], sB_hi(s) + bOff + p * (16 * ASTR) + ks * 32);
                ldx4(b_l[p], sB_lo(s) + bOff + p * (16 * ASTR) + ks * 32);
            }
#pragma unroll
            for (int mt = 0; mt < 2; mt++)
#pragma unroll
                for (int p = 0; p < 2; p++)
#pragma unroll
                    for (int j = 0; j < 2; j++) {
                        const int nt = p * 2 + j;
                        mma16816(acc[mt][nt], a_h[mt], &b_h[p][j * 2]);
                        mma16816(acc[mt][nt], a_h[mt], &b_l[p][j * 2]);
                        mma16816(acc[mt][nt], a_l[mt], &b_h[p][j * 2]);
                    }
        }
        __syncthreads();
    }

    // epilogue
    const int g  = lane >> 2;
    const int tg = lane & 3;
#pragma unroll
    for (int mt = 0; mt < 2; mt++) {
#pragma unroll
        for (int nt = 0; nt < 4; nt++) {
            const int nl = warpN * 32 + nt * 8 + tg * 2;
            const int n  = n0 + nl;
            float2 bv = *(const float2*)&bias[n];
#pragma unroll
            for (int half = 0; half < 2; half++) {
                const int ml = warpM * 32 + mt * 16 + g + half * 8;
                const int m  = m0 + ml;
                float c0 = acc[mt][nt][half * 2 + 0] + bv.x;
                float c1 = acc[mt][nt][half * 2 + 1] + bv.y;
                if (mode == 0) {
                    const int h = n0 >> 6;
                    const int bb = m >> 11;
                    const int ss = m & 2047;
                    float2 r = make_float2(c0 * scale, c1 * scale);
                    *(float2*)&Y[((size_t)(bb * HEADS + h) * SEQ + ss) * HDIM + (n & 63)] = r;
                } else {
                    *(float2*)&Y[(size_t)m * EMBED + n] = make_float2(c0, c1);
                }
            }
        }
    }
}

// ---------------- Flash attention (R2-proven fp32 scalar) ----------------
__global__ void __launch_bounds__(256)
flash_attn_kernel(const float* __restrict__ Q, const float* __restrict__ K,
                  const float* __restrict__ V, float* __restrict__ Aout)
{
    extern __shared__ float sm[];
    float* Qs = sm;            // [d][r]  64x64
    float* Ks = sm + 4096;     // [d][c]  64x64
    float* Vs = sm + 8192;     // [k][d]  64x64
    float* Ps = sm + 12288;    // [r][k]  64x64

    const int tid = threadIdx.x;
    const int tx  = tid & 15;
    const int ty  = tid >> 4;
    const int bh  = blockIdx.y;
    const int q0  = blockIdx.x * 64;

    const float* Qb = Q + (size_t)bh * SEQ * HDIM;
    const float* Kb = K + (size_t)bh * SEQ * HDIM;
    const float* Vb = V + (size_t)bh * SEQ * HDIM;

    const int lrow = tid >> 2;
    const int lc0  = (tid & 3) * 4;

#pragma unroll
    for (int j = 0; j < 4; j++) {
        int c = lc0 + j * 16;
        float4 qv = *(const float4*)&Qb[(size_t)(q0 + lrow) * HDIM + c];
        Qs[(c + 0) * 64 + lrow] = qv.x;
        Qs[(c + 1) * 64 + lrow] = qv.y;
        Qs[(c + 2) * 64 + lrow] = qv.z;
        Qs[(c + 3) * 64 + lrow] = qv.w;
    }

    float m_run[4], l_run[4], o[4][4];
#pragma unroll
    for (int i = 0; i < 4; i++) {
        m_run[i] = -INFINITY;
        l_run[i] = 0.f;
#pragma unroll
        for (int j = 0; j < 4; j++) o[i][j] = 0.f;
    }
    __syncthreads();

    for (int kt = 0; kt < SEQ / 64; kt++) {
        const int k0 = kt * 64;
        float4 kv[4], vv[4];
#pragma unroll
        for (int j = 0; j < 4; j++) {
            int c = lc0 + j * 16;
            kv[j] = *(const float4*)&Kb[(size_t)(k0 + lrow) * HDIM + c];
            vv[j] = *(const float4*)&Vb[(size_t)(k0 + lrow) * HDIM + c];
        }
        __syncthreads();
#pragma unroll
        for (int j = 0; j < 4; j++) {
            int c = lc0 + j * 16;
            Ks[(c + 0) * 64 + lrow] = kv[j].x;
            Ks[(c + 1) * 64 + lrow] = kv[j].y;
            Ks[(c + 2) * 64 + lrow] = kv[j].z;
            Ks[(c + 3) * 64 + lrow] = kv[j].w;
            *(float4*)&Vs[lrow * 64 + c] = vv[j];
        }
        __syncthreads();

        float sacc[4][4];
#pragma unroll
        for (int i = 0; i < 4; i++)
#pragma unroll
            for (int j = 0; j < 4; j++) sacc[i][j] = 0.f;

#pragma unroll
        for (int d = 0; d < HDIM; d++) {
            float4 a = *(const float4*)&Qs[d * 64 + ty * 4];
            float4 b = *(const float4*)&Ks[d * 64 + tx * 4];
            sacc[0][0] += a.x * b.x; sacc[0][1] += a.x * b.y; sacc[0][2] += a.x * b.z; sacc[0][3] += a.x * b.w;
            sacc[1][0] += a.y * b.x; sacc[1][1] += a.y * b.y; sacc[1][2] += a.y * b.z; sacc[1][3] += a.y * b.w;
            sacc[2][0] += a.z * b.x; sacc[2][1] += a.z * b.y; sacc[2][2] += a.z * b.z; sacc[2][3] += a.z * b.w;
            sacc[3][0] += a.w * b.x; sacc[3][1] += a.w * b.y; sacc[3][2] += a.w * b.z; sacc[3][3] += a.w * b.w;
        }

#pragma unroll
        for (int i = 0; i < 4; i++) {
            float pm = fmaxf(fmaxf(sacc[i][0], sacc[i][1]), fmaxf(sacc[i][2], sacc[i][3]));
#pragma unroll
            for (int off = 8; off >= 1; off >>= 1)
                pm = fmaxf(pm, __shfl_xor_sync(0xffffffffu, pm, off, 16));
            float mn = fmaxf(m_run[i], pm);
            float alpha = __expf(m_run[i] - mn);
            float ps = 0.f;
#pragma unroll
            for (int j = 0; j < 4; j++) {
                float p = __expf(sacc[i][j] - mn);
                sacc[i][j] = p;
                ps += p;
            }
#pragma unroll
            for (int off = 8; off >= 1; off >>= 1)
                ps += __shfl_xor_sync(0xffffffffu, ps, off, 16);
            l_run[i] = l_run[i] * alpha + ps;
            m_run[i] = mn;
#pragma unroll
            for (int j = 0; j < 4; j++) o[i][j] *= alpha;
            float4 pr = make_float4(sacc[i][0], sacc[i][1], sacc[i][2], sacc[i][3]);
            *(float4*)&Ps[(ty * 4 + i) * 64 + tx * 4] = pr;
        }
        __syncthreads();

#pragma unroll
        for (int k = 0; k < 64; k += 4) {
            float4 v0 = *(const float4*)&Vs[(k + 0) * 64 + tx * 4];
            float4 v1 = *(const float4*)&Vs[(k + 1) * 64 + tx * 4];
            float4 v2 = *(const float4*)&Vs[(k + 2) * 64 + tx * 4];
            float4 v3 = *(const float4*)&Vs[(k + 3) * 64 + tx * 4];
#pragma unroll
            for (int i = 0; i < 4; i++) {
                float4 p = *(const float4*)&Ps[(ty * 4 + i) * 64 + k];
                o[i][0] += p.x * v0.x + p.y * v1.x + p.z * v2.x + p.w * v3.x;
                o[i][1] += p.x * v0.y + p.y * v1.y + p.z * v2.y + p.w * v3.y;
                o[i][2] += p.x * v0.z + p.y * v1.z + p.z * v2.z + p.w * v3.z;
                o[i][3] += p.x * v0.w + p.y * v1.w + p.z * v2.w + p.w * v3.w;
            }
        }
    }

    const int b = bh / HEADS;
    const int h = bh % HEADS;
#pragma unroll
    for (int i = 0; i < 4; i++) {
        int s = q0 + ty * 4 + i;
        float inv = 1.f / l_run[i];
        float4 r;
        r.x = o[i][0] * inv;
        r.y = o[i][1] * inv;
        r.z = o[i][2] * inv;
        r.w = o[i][3] * inv;
        *(float4*)&Aout[((size_t)(b * SEQ + s)) * EMBED + h * HDIM + tx * 4] = r;
    }
}

// ---------------- driver ----------------
extern "C" void kernel_launch(void* const* d_in, const int* in_sizes, int n_in,
                              void* d_out, int out_size)
{
    const float *x, *w_q, *b_q, *w_k, *b_k, *w_v, *b_v, *w_o, *b_o;
    if (n_in == 9 && in_sizes[0] == EMBED && in_sizes[8] == NX) {
        b_k = (const float*)d_in[0]; b_o = (const float*)d_in[1];
        b_q = (const float*)d_in[2]; b_v = (const float*)d_in[3];
        w_k = (const float*)d_in[4]; w_o = (const float*)d_in[5];
        w_q = (const float*)d_in[6]; w_v = (const float*)d_in[7];
        x   = (const float*)d_in[8];
    } else if (n_in == 9 && in_sizes[0] == NX && in_sizes[2] == NW) {
        x   = (const float*)d_in[0];
        w_q = (const float*)d_in[1]; w_k = (const float*)d_in[2];
        w_v = (const float*)d_in[3]; w_o = (const float*)d_in[4];
        b_q = (const float*)d_in[5]; b_k = (const float*)d_in[6];
        b_v = (const float*)d_in[7]; b_o = (const float*)d_in[8];
    } else {
        x   = (const float*)d_in[0];
        w_q = (const float*)d_in[1]; b_q = (const float*)d_in[2];
        w_k = (const float*)d_in[3]; b_k = (const float*)d_in[4];
        w_v = (const float*)d_in[5]; b_v = (const float*)d_in[6];
        w_o = (const float*)d_in[7]; b_o = (const float*)d_in[8];
    }
    float* out = (float*)d_out;

    float *gQ, *gK, *gV, *gA;
    cudaGetSymbolAddress((void**)&gQ, g_Q);
    cudaGetSymbolAddress((void**)&gK, g_K);
    cudaGetSymbolAddress((void**)&gV, g_V);
    cudaGetSymbolAddress((void**)&gA, g_A);

    __nv_bfloat16 *xh, *xl, *w0h, *w0l, *w1h, *w1l, *w2h, *w2l, *w3h, *w3l, *ah, *al;
    cudaGetSymbolAddress((void**)&xh,  g_Xhi);  cudaGetSymbolAddress((void**)&xl,  g_Xlo);
    cudaGetSymbolAddress((void**)&w0h, g_W0hi); cudaGetSymbolAddress((void**)&w0l, g_W0lo);
    cudaGetSymbolAddress((void**)&w1h, g_W1hi); cudaGetSymbolAddress((void**)&w1l, g_W1lo);
    cudaGetSymbolAddress((void**)&w2h, g_W2hi); cudaGetSymbolAddress((void**)&w2l, g_W2lo);
    cudaGetSymbolAddress((void**)&w3h, g_W3hi); cudaGetSymbolAddress((void**)&w3l, g_W3lo);
    cudaGetSymbolAddress((void**)&ah,  g_Ahi);  cudaGetSymbolAddress((void**)&al,  g_Alo);

    cudaFuncSetAttribute(flash_attn_kernel,
                         cudaFuncAttributeMaxDynamicSharedMemorySize, 65536);
    cudaFuncSetAttribute(mma_gemm_kernel,
                         cudaFuncAttributeMaxDynamicSharedMemorySize, SMEM_GEMM);

    convert_kernel<<<NX / 1024, 256>>>(x,   xh,  xl,  NX);
    convert_kernel<<<NW / 1024, 256>>>(w_q, w0h, w0l, NW);
    convert_kernel<<<NW / 1024, 256>>>(w_k, w1h, w1l, NW);
    convert_kernel<<<NW / 1024, 256>>>(w_v, w2h, w2l, NW);
    convert_kernel<<<NW / 1024, 256>>>(w_o, w3h, w3l, NW);

    dim3 ggrid(EMBED / GBN, MROWS / GBM);   // (12, 32)
    const float qscale = 0.125f;

    mma_gemm_kernel<<<ggrid, 256, SMEM_GEMM>>>(xh, xl, w0h, w0l, b_q, gQ, 0, qscale);
    mma_gemm_kernel<<<ggrid, 256, SMEM_GEMM>>>(xh, xl, w1h, w1l, b_k, gK, 0, 1.0f);
    mma_gemm_kernel<<<ggrid, 256, SMEM_GEMM>>>(xh, xl, w2h, w2l, b_v, gV, 0, 1.0f);

    dim3 agrid(SEQ / 64, BH);               // (32, 24)
    flash_attn_kernel<<<agrid, 256, 65536>>>(gQ, gK, gV, gA);

    convert_kernel<<<NX / 1024, 256>>>(gA, ah, al, NX);
    mma_gemm_kernel<<<ggrid, 256, SMEM_GEMM>>>(ah, al, w3h, w3l, b_o, out, 1, 1.0f);
}

// round 6
// speedup vs baseline: 2.8458x; 1.9892x over previous
#include <cuda_runtime.h>
#include <cuda_bf16.h>
#include <math.h>

#define EMBED 768
#define HEADS 12
#define HDIM  64
#define BATCH 2
#define SEQ   2048
#define MROWS (BATCH * SEQ)      // 4096
#define BH    (BATCH * HEADS)    // 24
#define NX (MROWS * EMBED)
#define NW (EMBED * EMBED)

// ---------------- scratch ----------------
__device__ __nv_bfloat16 g_Xhi[NX], g_Xlo[NX];
__device__ __nv_bfloat16 g_W0hi[NW], g_W0lo[NW];
__device__ __nv_bfloat16 g_W1hi[NW], g_W1lo[NW];
__device__ __nv_bfloat16 g_W2hi[NW], g_W2lo[NW];
__device__ __nv_bfloat16 g_W3hi[NW], g_W3lo[NW];
__device__ __nv_bfloat16 g_Qh[NX], g_Ql[NX];   // [bh][s][d] hi/lo, pre-scaled
__device__ __nv_bfloat16 g_Kh[NX], g_Kl[NX];
__device__ __nv_bfloat16 g_Vh[NX], g_Vl[NX];
__device__ __nv_bfloat16 g_Ahi[NX], g_Alo[NX]; // attention out, [m][e]

// ---------------- PTX helpers (family-portable sm_80+) ----------------
__device__ __forceinline__ unsigned smem_u32(const void* p) {
    unsigned a;
    asm("{ .reg .u64 t; cvta.to.shared.u64 t, %1; cvt.u32.u64 %0, t; }" : "=r"(a) : "l"(p));
    return a;
}
__device__ __forceinline__ void cp16(unsigned s, const void* g) {
    asm volatile("cp.async.cg.shared.global [%0], [%1], 16;" :: "r"(s), "l"(g));
}
__device__ __forceinline__ void cp_commit() { asm volatile("cp.async.commit_group;" ::: "memory"); }
template <int N> __device__ __forceinline__ void cp_wait() {
    asm volatile("cp.async.wait_group %0;" :: "n"(N) : "memory");
}
__device__ __forceinline__ void ldx4(unsigned* r, unsigned addr) {
    asm volatile("ldmatrix.sync.aligned.m8n8.x4.shared.b16 {%0,%1,%2,%3}, [%4];"
        : "=r"(r[0]), "=r"(r[1]), "=r"(r[2]), "=r"(r[3]) : "r"(addr));
}
__device__ __forceinline__ void ldx4t(unsigned* r, unsigned addr) {
    asm volatile("ldmatrix.sync.aligned.m8n8.x4.trans.shared.b16 {%0,%1,%2,%3}, [%4];"
        : "=r"(r[0]), "=r"(r[1]), "=r"(r[2]), "=r"(r[3]) : "r"(addr));
}
__device__ __forceinline__ void mma16816(float* d, const unsigned* a, const unsigned* b) {
    asm volatile(
        "mma.sync.aligned.m16n8k16.row.col.f32.bf16.bf16.f32 "
        "{%0,%1,%2,%3}, {%4,%5,%6,%7}, {%8,%9}, {%0,%1,%2,%3};"
        : "+f"(d[0]), "+f"(d[1]), "+f"(d[2]), "+f"(d[3])
        : "r"(a[0]), "r"(a[1]), "r"(a[2]), "r"(a[3]), "r"(b[0]), "r"(b[1]));
}
__device__ __forceinline__ unsigned pack_bf2(float a, float b) {
    __nv_bfloat162 t = __float22bfloat162_rn(make_float2(a, b));
    return *(unsigned*)&t;
}
// pack hi pair, return residuals
__device__ __forceinline__ unsigned pack_hi_res(float a, float b, float& ra, float& rb) {
    __nv_bfloat162 t = __float22bfloat162_rn(make_float2(a, b));
    ra = a - __bfloat162float(t.x);
    rb = b - __bfloat162float(t.y);
    return *(unsigned*)&t;
}

// ---------------- fp32 -> bf16 hi/lo split ----------------
struct alignas(8) B4 { __nv_bfloat16 v[4]; };

__global__ void __launch_bounds__(256)
convert_kernel(const float* __restrict__ src, __nv_bfloat16* __restrict__ hi,
               __nv_bfloat16* __restrict__ lo, int n)
{
    int i = (blockIdx.x * 256 + threadIdx.x) * 4;
    if (i >= n) return;
    float4 v = *(const float4*)&src[i];
    B4 h, l;
    float f[4] = {v.x, v.y, v.z, v.w};
#pragma unroll
    for (int j = 0; j < 4; j++) {
        h.v[j] = __float2bfloat16(f[j]);
        l.v[j] = __float2bfloat16(f[j] - __bfloat162float(h.v[j]));
    }
    *(B4*)&hi[i] = h;
    *(B4*)&lo[i] = l;
}

// ---------------- HMMA GEMM: Y = X @ W^T + b  (bf16x3) ----------------
#define GBM 128
#define GBN 64
#define GBK 32
#define KITERS (EMBED / GBK)     // 24
#define ASTR 80
#define A_SZ (128 * ASTR)
#define B_SZ (64 * ASTR)
#define STAGE (2 * A_SZ + 2 * B_SZ)
#define SMEM_GEMM (2 * STAGE)

__global__ void __launch_bounds__(256)
mma_gemm_kernel(const __nv_bfloat16* __restrict__ Ahi, const __nv_bfloat16* __restrict__ Alo,
                const __nv_bfloat16* __restrict__ Bhi, const __nv_bfloat16* __restrict__ Blo,
                const float* __restrict__ bias, float* __restrict__ Yf,
                __nv_bfloat16* __restrict__ Yhi, __nv_bfloat16* __restrict__ Ylo,
                int mode, float scale)
{
    extern __shared__ char smraw[];
    const unsigned sb = smem_u32(smraw);

    const int tid  = threadIdx.x;
    const int lane = tid & 31;
    const int wid  = tid >> 5;
    const int warpM = wid & 3;
    const int warpN = wid >> 2;
    const int m0 = blockIdx.y * GBM;
    const int n0 = blockIdx.x * GBN;

    auto sA_hi = [&](int s) { return sb + s * STAGE; };
    auto sA_lo = [&](int s) { return sb + s * STAGE + A_SZ; };
    auto sB_hi = [&](int s) { return sb + s * STAGE + 2 * A_SZ; };
    auto sB_lo = [&](int s) { return sb + s * STAGE + 2 * A_SZ + B_SZ; };

    const int ar0 = (tid * 2) >> 2, ac0 = (tid * 2) & 3;
    const int ar1 = (tid * 2 + 1) >> 2, ac1 = (tid * 2 + 1) & 3;
    const int br = tid >> 2, bc = tid & 3;

    auto load_stage = [&](int kt, int s) {
        const int k0 = kt * GBK;
        const __nv_bfloat16* pah = Ahi + (size_t)m0 * EMBED + k0;
        const __nv_bfloat16* pal = Alo + (size_t)m0 * EMBED + k0;
        const __nv_bfloat16* pbh = Bhi + (size_t)n0 * EMBED + k0;
        const __nv_bfloat16* pbl = Blo + (size_t)n0 * EMBED + k0;
        cp16(sA_hi(s) + ar0 * ASTR + ac0 * 16, pah + (size_t)ar0 * EMBED + ac0 * 8);
        cp16(sA_hi(s) + ar1 * ASTR + ac1 * 16, pah + (size_t)ar1 * EMBED + ac1 * 8);
        cp16(sA_lo(s) + ar0 * ASTR + ac0 * 16, pal + (size_t)ar0 * EMBED + ac0 * 8);
        cp16(sA_lo(s) + ar1 * ASTR + ac1 * 16, pal + (size_t)ar1 * EMBED + ac1 * 8);
        cp16(sB_hi(s) + br * ASTR + bc * 16,   pbh + (size_t)br * EMBED + bc * 8);
        cp16(sB_lo(s) + br * ASTR + bc * 16,   pbl + (size_t)br * EMBED + bc * 8);
    };

    const unsigned aOff = (unsigned)((warpM * 32 + ((lane >> 3) & 1) * 8 + (lane & 7)) * ASTR
                                     + (lane >> 4) * 16);
    const unsigned bOff = (unsigned)((warpN * 32 + ((lane >> 4) & 1) * 8 + (lane & 7)) * ASTR
                                     + ((lane >> 3) & 1) * 16);

    float acc[2][4][4];
#pragma unroll
    for (int mt = 0; mt < 2; mt++)
#pragma unroll
        for (int nt = 0; nt < 4; nt++)
#pragma unroll
            for (int j = 0; j < 4; j++) acc[mt][nt][j] = 0.f;

    load_stage(0, 0);
    cp_commit();

    for (int kt = 0; kt < KITERS; kt++) {
        const int s = kt & 1;
        if (kt + 1 < KITERS) {
            load_stage(kt + 1, s ^ 1);
            cp_commit();
            cp_wait<1>();
        } else {
            cp_wait<0>();
        }
        __syncthreads();

#pragma unroll
        for (int ks = 0; ks < 2; ks++) {
            unsigned a_h[2][4], a_l[2][4], b_h[2][4], b_l[2][4];
#pragma unroll
            for (int mt = 0; mt < 2; mt++) {
                ldx4(a_h[mt], sA_hi(s) + aOff + mt * (16 * ASTR) + ks * 32);
                ldx4(a_l[mt], sA_lo(s) + aOff + mt * (16 * ASTR) + ks * 32);
            }
#pragma unroll
            for (int p = 0; p < 2; p++) {
                ldx4(b_h[p], sB_hi(s) + bOff + p * (16 * ASTR) + ks * 32);
                ldx4(b_l[p], sB_lo(s) + bOff + p * (16 * ASTR) + ks * 32);
            }
#pragma unroll
            for (int mt = 0; mt < 2; mt++)
#pragma unroll
                for (int p = 0; p < 2; p++)
#pragma unroll
                    for (int j = 0; j < 2; j++) {
                        const int nt = p * 2 + j;
                        mma16816(acc[mt][nt], a_h[mt], &b_h[p][j * 2]);
                        mma16816(acc[mt][nt], a_h[mt], &b_l[p][j * 2]);
                        mma16816(acc[mt][nt], a_l[mt], &b_h[p][j * 2]);
                    }
        }
        __syncthreads();
    }

    const int g  = lane >> 2;
    const int tg = lane & 3;
#pragma unroll
    for (int mt = 0; mt < 2; mt++) {
#pragma unroll
        for (int nt = 0; nt < 4; nt++) {
            const int nl = warpN * 32 + nt * 8 + tg * 2;
            const int n  = n0 + nl;
            float2 bv = *(const float2*)&bias[n];
#pragma unroll
            for (int half = 0; half < 2; half++) {
                const int ml = warpM * 32 + mt * 16 + g + half * 8;
                const int m  = m0 + ml;
                float c0 = acc[mt][nt][half * 2 + 0] + bv.x;
                float c1 = acc[mt][nt][half * 2 + 1] + bv.y;
                if (mode == 0) {
                    const int h = n0 >> 6;
                    const int bb = m >> 11;
                    const int ss = m & 2047;
                    float v0 = c0 * scale, v1 = c1 * scale;
                    float r0, r1;
                    unsigned hp = pack_hi_res(v0, v1, r0, r1);
                    unsigned lp = pack_bf2(r0, r1);
                    size_t idx = ((size_t)(bb * HEADS + h) * SEQ + ss) * HDIM + (n & 63);
                    *(unsigned*)&Yhi[idx] = hp;
                    *(unsigned*)&Ylo[idx] = lp;
                } else {
                    *(float2*)&Yf[(size_t)m * EMBED + n] = make_float2(c0, c1);
                }
            }
        }
    }
}

// ---------------- Flash attention, HMMA bf16x3 ----------------
// BR=128 q rows per CTA, BC=64 kv per tile; 8 warps x 16 q-rows.
#define QSTR 144                  // 64 bf16 + 8 pad = 144 bytes
#define F_oQh 0
#define F_oQl 18432
#define F_oKh 36864
#define F_oKl 46080
#define F_oVh 55296
#define F_oVl 64512
#define SMEM_FLASH 73728

__global__ void __launch_bounds__(256)
flash_mma_kernel(const __nv_bfloat16* __restrict__ Qh, const __nv_bfloat16* __restrict__ Ql,
                 const __nv_bfloat16* __restrict__ Kh, const __nv_bfloat16* __restrict__ Kl,
                 const __nv_bfloat16* __restrict__ Vh, const __nv_bfloat16* __restrict__ Vl,
                 __nv_bfloat16* __restrict__ Ahi, __nv_bfloat16* __restrict__ Alo)
{
    extern __shared__ char smf[];
    const unsigned sb = smem_u32(smf);
    const int tid  = threadIdx.x;
    const int lane = tid & 31;
    const int wid  = tid >> 5;
    const int bh   = blockIdx.y;
    const int q0   = blockIdx.x * 128;

    const size_t qoff = ((size_t)bh * SEQ + q0) * HDIM;
    const size_t koff = (size_t)bh * SEQ * HDIM;
    const __nv_bfloat16* pQh = Qh + qoff;
    const __nv_bfloat16* pQl = Ql + qoff;
    const __nv_bfloat16* pKh = Kh + koff;
    const __nv_bfloat16* pKl = Kl + koff;
    const __nv_bfloat16* pVh = Vh + koff;
    const __nv_bfloat16* pVl = Vl + koff;

    // load 128x64 Q hi/lo
#pragma unroll
    for (int i = 0; i < 4; i++) {
        int task = tid + i * 256;
        int r = task >> 3, c = task & 7;
        cp16(sb + F_oQh + r * QSTR + c * 16, pQh + (size_t)r * HDIM + c * 8);
        cp16(sb + F_oQl + r * QSTR + c * 16, pQl + (size_t)r * HDIM + c * 8);
    }
    cp_commit();

    const int g  = lane >> 2;
    const int tg = lane & 3;
    const unsigned aAddr = sb + (unsigned)((wid * 16 + ((lane >> 3) & 1) * 8 + (lane & 7)) * QSTR
                                           + (lane >> 4) * 16);
    const unsigned kAddr = sb + (unsigned)((((lane >> 4) & 1) * 8 + (lane & 7)) * QSTR
                                           + ((lane >> 3) & 1) * 16);
    const unsigned vAddr = sb + (unsigned)((((lane >> 3) & 1) * 8 + (lane & 7)) * QSTR
                                           + (lane >> 4) * 16);

    float m0 = -INFINITY, m1 = -INFINITY, l0 = 0.f, l1 = 0.f;
    float o[8][4];
#pragma unroll
    for (int nf = 0; nf < 8; nf++)
#pragma unroll
        for (int j = 0; j < 4; j++) o[nf][j] = 0.f;

    for (int kt = 0; kt < SEQ / 64; kt++) {
        const int k0 = kt * 64;
        __syncthreads();   // all warps done with previous KV tile
#pragma unroll
        for (int i = 0; i < 2; i++) {
            int task = tid + i * 256;
            int r = task >> 3, c = task & 7;
            size_t go = (size_t)(k0 + r) * HDIM + c * 8;
            unsigned so = r * QSTR + c * 16;
            cp16(sb + F_oKh + so, pKh + go);
            cp16(sb + F_oKl + so, pKl + go);
            cp16(sb + F_oVh + so, pVh + go);
            cp16(sb + F_oVl + so, pVl + go);
        }
        cp_commit();
        cp_wait<0>();
        __syncthreads();

        // ---- S = Q K^T (16 x 64 per warp) ----
        float s[8][4];
#pragma unroll
        for (int nf = 0; nf < 8; nf++)
#pragma unroll
            for (int j = 0; j < 4; j++) s[nf][j] = 0.f;

#pragma unroll
        for (int ks = 0; ks < 4; ks++) {
            unsigned qhf[4], qlf[4];
            ldx4(qhf, aAddr + F_oQh + ks * 32);
            ldx4(qlf, aAddr + F_oQl + ks * 32);
#pragma unroll
            for (int p = 0; p < 4; p++) {
                unsigned khf[4], klf[4];
                ldx4(khf, kAddr + F_oKh + p * (16 * QSTR) + ks * 32);
                ldx4(klf, kAddr + F_oKl + p * (16 * QSTR) + ks * 32);
                mma16816(s[2 * p],     qhf, &khf[0]);
                mma16816(s[2 * p],     qhf, &klf[0]);
                mma16816(s[2 * p],     qlf, &khf[0]);
                mma16816(s[2 * p + 1], qhf, &khf[2]);
                mma16816(s[2 * p + 1], qhf, &klf[2]);
                mma16816(s[2 * p + 1], qlf, &khf[2]);
            }
        }

        // ---- online softmax (rows g and g+8; 16 cols/thread/row) ----
        float pm0 = s[0][0], pm1 = s[0][2];
#pragma unroll
        for (int nf = 0; nf < 8; nf++) {
            pm0 = fmaxf(pm0, fmaxf(s[nf][0], s[nf][1]));
            pm1 = fmaxf(pm1, fmaxf(s[nf][2], s[nf][3]));
        }
        pm0 = fmaxf(pm0, __shfl_xor_sync(0xffffffffu, pm0, 1, 4));
        pm0 = fmaxf(pm0, __shfl_xor_sync(0xffffffffu, pm0, 2, 4));
        pm1 = fmaxf(pm1, __shfl_xor_sync(0xffffffffu, pm1, 1, 4));
        pm1 = fmaxf(pm1, __shfl_xor_sync(0xffffffffu, pm1, 2, 4));
        const float mn0 = fmaxf(m0, pm0);
        const float mn1 = fmaxf(m1, pm1);
        const float al0 = __expf(m0 - mn0);
        const float al1 = __expf(m1 - mn1);
        m0 = mn0; m1 = mn1;
        float ps0 = 0.f, ps1 = 0.f;
#pragma unroll
        for (int nf = 0; nf < 8; nf++) {
            s[nf][0] = __expf(s[nf][0] - mn0);
            s[nf][1] = __expf(s[nf][1] - mn0);
            s[nf][2] = __expf(s[nf][2] - mn1);
            s[nf][3] = __expf(s[nf][3] - mn1);
            ps0 += s[nf][0] + s[nf][1];
            ps1 += s[nf][2] + s[nf][3];
        }
        ps0 += __shfl_xor_sync(0xffffffffu, ps0, 1, 4);
        ps0 += __shfl_xor_sync(0xffffffffu, ps0, 2, 4);
        ps1 += __shfl_xor_sync(0xffffffffu, ps1, 1, 4);
        ps1 += __shfl_xor_sync(0xffffffffu, ps1, 2, 4);
        l0 = l0 * al0 + ps0;
        l1 = l1 * al1 + ps1;
#pragma unroll
        for (int nf = 0; nf < 8; nf++) {
            o[nf][0] *= al0; o[nf][1] *= al0;
            o[nf][2] *= al1; o[nf][3] *= al1;
        }

        // ---- O += P V (bf16x3; P acc layout == A-frag layout) ----
#pragma unroll
        for (int kb = 0; kb < 4; kb++) {
            float r0, r1, r2, r3, r4, r5, r6, r7;
            unsigned pa_h[4], pa_l[4];
            pa_h[0] = pack_hi_res(s[2 * kb][0],     s[2 * kb][1],     r0, r1);
            pa_h[1] = pack_hi_res(s[2 * kb][2],     s[2 * kb][3],     r2, r3);
            pa_h[2] = pack_hi_res(s[2 * kb + 1][0], s[2 * kb + 1][1], r4, r5);
            pa_h[3] = pack_hi_res(s[2 * kb + 1][2], s[2 * kb + 1][3], r6, r7);
            pa_l[0] = pack_bf2(r0, r1);
            pa_l[1] = pack_bf2(r2, r3);
            pa_l[2] = pack_bf2(r4, r5);
            pa_l[3] = pack_bf2(r6, r7);
#pragma unroll
            for (int du = 0; du < 4; du++) {
                unsigned vhf[4], vlf[4];
                ldx4t(vhf, vAddr + F_oVh + kb * (16 * QSTR) + du * 32);
                ldx4t(vlf, vAddr + F_oVl + kb * (16 * QSTR) + du * 32);
                mma16816(o[du * 2],     pa_h, &vhf[0]);
                mma16816(o[du * 2],     pa_h, &vlf[0]);
                mma16816(o[du * 2],     pa_l, &vhf[0]);
                mma16816(o[du * 2 + 1], pa_h, &vhf[2]);
                mma16816(o[du * 2 + 1], pa_h, &vlf[2]);
                mma16816(o[du * 2 + 1], pa_l, &vhf[2]);
            }
        }
    }

    // ---- finalize: write bf16 hi/lo to [m][e] ----
    const float inv0 = 1.f / l0;
    const float inv1 = 1.f / l1;
    const int b = bh / HEADS;
    const int h = bh % HEADS;
    const int s0r = q0 + wid * 16 + g;
    const size_t row0 = (size_t)(b * SEQ + s0r) * EMBED;
    const size_t row1 = (size_t)(b * SEQ + s0r + 8) * EMBED;
#pragma unroll
    for (int nf = 0; nf < 8; nf++) {
        const int e = h * HDIM + nf * 8 + tg * 2;
        float a0 = o[nf][0] * inv0, a1 = o[nf][1] * inv0;
        float b0 = o[nf][2] * inv1, b1 = o[nf][3] * inv1;
        float ra0, ra1, rb0, rb1;
        unsigned h0 = pack_hi_res(a0, a1, ra0, ra1);
        unsigned h1 = pack_hi_res(b0, b1, rb0, rb1);
        *(unsigned*)&Ahi[row0 + e] = h0;
        *(unsigned*)&Alo[row0 + e] = pack_bf2(ra0, ra1);
        *(unsigned*)&Ahi[row1 + e] = h1;
        *(unsigned*)&Alo[row1 + e] = pack_bf2(rb0, rb1);
    }
}

// ---------------- driver ----------------
extern "C" void kernel_launch(void* const* d_in, const int* in_sizes, int n_in,
                              void* d_out, int out_size)
{
    const float *x, *w_q, *b_q, *w_k, *b_k, *w_v, *b_v, *w_o, *b_o;
    if (n_in == 9 && in_sizes[0] == EMBED && in_sizes[8] == NX) {
        b_k = (const float*)d_in[0]; b_o = (const float*)d_in[1];
        b_q = (const float*)d_in[2]; b_v = (const float*)d_in[3];
        w_k = (const float*)d_in[4]; w_o = (const float*)d_in[5];
        w_q = (const float*)d_in[6]; w_v = (const float*)d_in[7];
        x   = (const float*)d_in[8];
    } else if (n_in == 9 && in_sizes[0] == NX && in_sizes[2] == NW) {
        x   = (const float*)d_in[0];
        w_q = (const float*)d_in[1]; w_k = (const float*)d_in[2];
        w_v = (const float*)d_in[3]; w_o = (const float*)d_in[4];
        b_q = (const float*)d_in[5]; b_k = (const float*)d_in[6];
        b_v = (const float*)d_in[7]; b_o = (const float*)d_in[8];
    } else {
        x   = (const float*)d_in[0];
        w_q = (const float*)d_in[1]; b_q = (const float*)d_in[2];
        w_k = (const float*)d_in[3]; b_k = (const float*)d_in[4];
        w_v = (const float*)d_in[5]; b_v = (const float*)d_in[6];
        w_o = (const float*)d_in[7]; b_o = (const float*)d_in[8];
    }
    float* out = (float*)d_out;

    __nv_bfloat16 *xh, *xl, *w0h, *w0l, *w1h, *w1l, *w2h, *w2l, *w3h, *w3l;
    __nv_bfloat16 *qh, *ql, *kh, *kl, *vh, *vl, *ah, *al;
    cudaGetSymbolAddress((void**)&xh,  g_Xhi);  cudaGetSymbolAddress((void**)&xl,  g_Xlo);
    cudaGetSymbolAddress((void**)&w0h, g_W0hi); cudaGetSymbolAddress((void**)&w0l, g_W0lo);
    cudaGetSymbolAddress((void**)&w1h, g_W1hi); cudaGetSymbolAddress((void**)&w1l, g_W1lo);
    cudaGetSymbolAddress((void**)&w2h, g_W2hi); cudaGetSymbolAddress((void**)&w2l, g_W2lo);
    cudaGetSymbolAddress((void**)&w3h, g_W3hi); cudaGetSymbolAddress((void**)&w3l, g_W3lo);
    cudaGetSymbolAddress((void**)&qh,  g_Qh);   cudaGetSymbolAddress((void**)&ql,  g_Ql);
    cudaGetSymbolAddress((void**)&kh,  g_Kh);   cudaGetSymbolAddress((void**)&kl,  g_Kl);
    cudaGetSymbolAddress((void**)&vh,  g_Vh);   cudaGetSymbolAddress((void**)&vl,  g_Vl);
    cudaGetSymbolAddress((void**)&ah,  g_Ahi);  cudaGetSymbolAddress((void**)&al,  g_Alo);

    cudaFuncSetAttribute(mma_gemm_kernel,
                         cudaFuncAttributeMaxDynamicSharedMemorySize, SMEM_GEMM);
    cudaFuncSetAttribute(flash_mma_kernel,
                         cudaFuncAttributeMaxDynamicSharedMemorySize, SMEM_FLASH);

    convert_kernel<<<NX / 1024, 256>>>(x,   xh,  xl,  NX);
    convert_kernel<<<NW / 1024, 256>>>(w_q, w0h, w0l, NW);
    convert_kernel<<<NW / 1024, 256>>>(w_k, w1h, w1l, NW);
    convert_kernel<<<NW / 1024, 256>>>(w_v, w2h, w2l, NW);
    convert_kernel<<<NW / 1024, 256>>>(w_o, w3h, w3l, NW);

    dim3 ggrid(EMBED / GBN, MROWS / GBM);   // (12, 32)

    mma_gemm_kernel<<<ggrid, 256, SMEM_GEMM>>>(xh, xl, w0h, w0l, b_q, nullptr, qh, ql, 0, 0.125f);
    mma_gemm_kernel<<<ggrid, 256, SMEM_GEMM>>>(xh, xl, w1h, w1l, b_k, nullptr, kh, kl, 0, 1.0f);
    mma_gemm_kernel<<<ggrid, 256, SMEM_GEMM>>>(xh, xl, w2h, w2l, b_v, nullptr, vh, vl, 0, 1.0f);

    dim3 agrid(SEQ / 128, BH);              // (16, 24)
    flash_mma_kernel<<<agrid, 256, SMEM_FLASH>>>(qh, ql, kh, kl, vh, vl, ah, al);

    mma_gemm_kernel<<<ggrid, 256, SMEM_GEMM>>>(ah, al, w3h, w3l, b_o, out, nullptr, nullptr, 1, 1.0f);
}

// round 7
// speedup vs baseline: 3.0752x; 1.0806x over previous
#include <cuda_runtime.h>
#include <cuda_bf16.h>
#include <math.h>

#define EMBED 768
#define HEADS 12
#define HDIM  64
#define BATCH 2
#define SEQ   2048
#define MROWS (BATCH * SEQ)      // 4096
#define BH    (BATCH * HEADS)    // 24
#define NX (MROWS * EMBED)
#define NW (EMBED * EMBED)

// ---------------- scratch ----------------
__device__ __nv_bfloat16 g_Xhi[NX], g_Xlo[NX];
__device__ __nv_bfloat16 g_W0hi[NW], g_W0lo[NW];
__device__ __nv_bfloat16 g_W1hi[NW], g_W1lo[NW];
__device__ __nv_bfloat16 g_W2hi[NW], g_W2lo[NW];
__device__ __nv_bfloat16 g_W3hi[NW], g_W3lo[NW];
__device__ __nv_bfloat16 g_Qh[NX], g_Ql[NX];   // [bh][s][d] hi/lo, pre-scaled
__device__ __nv_bfloat16 g_Kh[NX], g_Kl[NX];
__device__ __nv_bfloat16 g_Vh[NX], g_Vl[NX];
__device__ __nv_bfloat16 g_Ahi[NX], g_Alo[NX]; // attention out, [m][e]

// ---------------- PTX helpers (family-portable sm_80+) ----------------
__device__ __forceinline__ unsigned smem_u32(const void* p) {
    unsigned a;
    asm("{ .reg .u64 t; cvta.to.shared.u64 t, %1; cvt.u32.u64 %0, t; }" : "=r"(a) : "l"(p));
    return a;
}
__device__ __forceinline__ void cp16(unsigned s, const void* g) {
    asm volatile("cp.async.cg.shared.global [%0], [%1], 16;" :: "r"(s), "l"(g));
}
__device__ __forceinline__ void cp_commit() { asm volatile("cp.async.commit_group;" ::: "memory"); }
template <int N> __device__ __forceinline__ void cp_wait() {
    asm volatile("cp.async.wait_group %0;" :: "n"(N) : "memory");
}
__device__ __forceinline__ void ldx4(unsigned* r, unsigned addr) {
    asm volatile("ldmatrix.sync.aligned.m8n8.x4.shared.b16 {%0,%1,%2,%3}, [%4];"
        : "=r"(r[0]), "=r"(r[1]), "=r"(r[2]), "=r"(r[3]) : "r"(addr));
}
__device__ __forceinline__ void ldx4t(unsigned* r, unsigned addr) {
    asm volatile("ldmatrix.sync.aligned.m8n8.x4.trans.shared.b16 {%0,%1,%2,%3}, [%4];"
        : "=r"(r[0]), "=r"(r[1]), "=r"(r[2]), "=r"(r[3]) : "r"(addr));
}
__device__ __forceinline__ void mma16816(float* d, const unsigned* a, const unsigned* b) {
    asm volatile(
        "mma.sync.aligned.m16n8k16.row.col.f32.bf16.bf16.f32 "
        "{%0,%1,%2,%3}, {%4,%5,%6,%7}, {%8,%9}, {%0,%1,%2,%3};"
        : "+f"(d[0]), "+f"(d[1]), "+f"(d[2]), "+f"(d[3])
        : "r"(a[0]), "r"(a[1]), "r"(a[2]), "r"(a[3]), "r"(b[0]), "r"(b[1]));
}
__device__ __forceinline__ unsigned pack_bf2(float a, float b) {
    __nv_bfloat162 t = __float22bfloat162_rn(make_float2(a, b));
    return *(unsigned*)&t;
}
__device__ __forceinline__ unsigned pack_hi_res(float a, float b, float& ra, float& rb) {
    __nv_bfloat162 t = __float22bfloat162_rn(make_float2(a, b));
    ra = a - __bfloat162float(t.x);
    rb = b - __bfloat162float(t.y);
    return *(unsigned*)&t;
}

// ---------------- fp32 -> bf16 hi/lo split ----------------
struct alignas(8) B4 { __nv_bfloat16 v[4]; };

__global__ void __launch_bounds__(256)
convert_kernel(const float* __restrict__ src, __nv_bfloat16* __restrict__ hi,
               __nv_bfloat16* __restrict__ lo, int n)
{
    int i = (blockIdx.x * 256 + threadIdx.x) * 4;
    if (i >= n) return;
    float4 v = *(const float4*)&src[i];
    B4 h, l;
    float f[4] = {v.x, v.y, v.z, v.w};
#pragma unroll
    for (int j = 0; j < 4; j++) {
        h.v[j] = __float2bfloat16(f[j]);
        l.v[j] = __float2bfloat16(f[j] - __bfloat162float(h.v[j]));
    }
    *(B4*)&hi[i] = h;
    *(B4*)&lo[i] = l;
}

// ---------------- HMMA GEMM: Y = X @ W^T + b  (bf16x3) ----------------
#define GBM 128
#define GBN 64
#define GBK 32
#define KITERS (EMBED / GBK)     // 24
#define ASTR 80
#define A_SZ (128 * ASTR)
#define B_SZ (64 * ASTR)
#define STAGE (2 * A_SZ + 2 * B_SZ)
#define SMEM_GEMM (2 * STAGE)

__global__ void __launch_bounds__(256)
mma_gemm_kernel(const __nv_bfloat16* __restrict__ Ahi, const __nv_bfloat16* __restrict__ Alo,
                const __nv_bfloat16* __restrict__ Bhi, const __nv_bfloat16* __restrict__ Blo,
                const float* __restrict__ bias, float* __restrict__ Yf,
                __nv_bfloat16* __restrict__ Yhi, __nv_bfloat16* __restrict__ Ylo,
                int mode, float scale)
{
    extern __shared__ char smraw[];
    const unsigned sb = smem_u32(smraw);

    const int tid  = threadIdx.x;
    const int lane = tid & 31;
    const int wid  = tid >> 5;
    const int warpM = wid & 3;
    const int warpN = wid >> 2;
    const int m0 = blockIdx.y * GBM;
    const int n0 = blockIdx.x * GBN;

    auto sA_hi = [&](int s) { return sb + s * STAGE; };
    auto sA_lo = [&](int s) { return sb + s * STAGE + A_SZ; };
    auto sB_hi = [&](int s) { return sb + s * STAGE + 2 * A_SZ; };
    auto sB_lo = [&](int s) { return sb + s * STAGE + 2 * A_SZ + B_SZ; };

    const int ar0 = (tid * 2) >> 2, ac0 = (tid * 2) & 3;
    const int ar1 = (tid * 2 + 1) >> 2, ac1 = (tid * 2 + 1) & 3;
    const int br = tid >> 2, bc = tid & 3;

    auto load_stage = [&](int kt, int s) {
        const int k0 = kt * GBK;
        const __nv_bfloat16* pah = Ahi + (size_t)m0 * EMBED + k0;
        const __nv_bfloat16* pal = Alo + (size_t)m0 * EMBED + k0;
        const __nv_bfloat16* pbh = Bhi + (size_t)n0 * EMBED + k0;
        const __nv_bfloat16* pbl = Blo + (size_t)n0 * EMBED + k0;
        cp16(sA_hi(s) + ar0 * ASTR + ac0 * 16, pah + (size_t)ar0 * EMBED + ac0 * 8);
        cp16(sA_hi(s) + ar1 * ASTR + ac1 * 16, pah + (size_t)ar1 * EMBED + ac1 * 8);
        cp16(sA_lo(s) + ar0 * ASTR + ac0 * 16, pal + (size_t)ar0 * EMBED + ac0 * 8);
        cp16(sA_lo(s) + ar1 * ASTR + ac1 * 16, pal + (size_t)ar1 * EMBED + ac1 * 8);
        cp16(sB_hi(s) + br * ASTR + bc * 16,   pbh + (size_t)br * EMBED + bc * 8);
        cp16(sB_lo(s) + br * ASTR + bc * 16,   pbl + (size_t)br * EMBED + bc * 8);
    };

    const unsigned aOff = (unsigned)((warpM * 32 + ((lane >> 3) & 1) * 8 + (lane & 7)) * ASTR
                                     + (lane >> 4) * 16);
    const unsigned bOff = (unsigned)((warpN * 32 + ((lane >> 4) & 1) * 8 + (lane & 7)) * ASTR
                                     + ((lane >> 3) & 1) * 16);

    float acc[2][4][4];
#pragma unroll
    for (int mt = 0; mt < 2; mt++)
#pragma unroll
        for (int nt = 0; nt < 4; nt++)
#pragma unroll
            for (int j = 0; j < 4; j++) acc[mt][nt][j] = 0.f;

    load_stage(0, 0);
    cp_commit();

    for (int kt = 0; kt < KITERS; kt++) {
        const int s = kt & 1;
        if (kt + 1 < KITERS) {
            load_stage(kt + 1, s ^ 1);
            cp_commit();
            cp_wait<1>();
        } else {
            cp_wait<0>();
        }
        __syncthreads();

#pragma unroll
        for (int ks = 0; ks < 2; ks++) {
            unsigned a_h[2][4], a_l[2][4], b_h[2][4], b_l[2][4];
#pragma unroll
            for (int mt = 0; mt < 2; mt++) {
                ldx4(a_h[mt], sA_hi(s) + aOff + mt * (16 * ASTR) + ks * 32);
                ldx4(a_l[mt], sA_lo(s) + aOff + mt * (16 * ASTR) + ks * 32);
            }
#pragma unroll
            for (int p = 0; p < 2; p++) {
                ldx4(b_h[p], sB_hi(s) + bOff + p * (16 * ASTR) + ks * 32);
                ldx4(b_l[p], sB_lo(s) + bOff + p * (16 * ASTR) + ks * 32);
            }
#pragma unroll
            for (int mt = 0; mt < 2; mt++)
#pragma unroll
                for (int p = 0; p < 2; p++)
#pragma unroll
                    for (int j = 0; j < 2; j++) {
                        const int nt = p * 2 + j;
                        mma16816(acc[mt][nt], a_h[mt], &b_h[p][j * 2]);
                        mma16816(acc[mt][nt], a_h[mt], &b_l[p][j * 2]);
                        mma16816(acc[mt][nt], a_l[mt], &b_h[p][j * 2]);
                    }
        }
        __syncthreads();
    }

    const int g  = lane >> 2;
    const int tg = lane & 3;
#pragma unroll
    for (int mt = 0; mt < 2; mt++) {
#pragma unroll
        for (int nt = 0; nt < 4; nt++) {
            const int nl = warpN * 32 + nt * 8 + tg * 2;
            const int n  = n0 + nl;
            float2 bv = *(const float2*)&bias[n];
#pragma unroll
            for (int half = 0; half < 2; half++) {
                const int ml = warpM * 32 + mt * 16 + g + half * 8;
                const int m  = m0 + ml;
                float c0 = acc[mt][nt][half * 2 + 0] + bv.x;
                float c1 = acc[mt][nt][half * 2 + 1] + bv.y;
                if (mode == 0) {
                    const int h = n0 >> 6;
                    const int bb = m >> 11;
                    const int ss = m & 2047;
                    float v0 = c0 * scale, v1 = c1 * scale;
                    float r0, r1;
                    unsigned hp = pack_hi_res(v0, v1, r0, r1);
                    unsigned lp = pack_bf2(r0, r1);
                    size_t idx = ((size_t)(bb * HEADS + h) * SEQ + ss) * HDIM + (n & 63);
                    *(unsigned*)&Yhi[idx] = hp;
                    *(unsigned*)&Ylo[idx] = lp;
                } else {
                    *(float2*)&Yf[(size_t)m * EMBED + n] = make_float2(c0, c1);
                }
            }
        }
    }
}

// ---------------- Flash attention, HMMA bf16x3, double-buffered KV ----------------
// BR=128 q rows per CTA, BC=64 kv per tile; 8 warps x 16 q-rows.
#define QSTR 144                  // 64 bf16 + 8 pad
#define F_oQh 0
#define F_oQl 18432
#define KV_BASE 36864
#define KV_STAGE 36864            // 4 tensors x 9216
#define KV_oKh 0
#define KV_oKl 9216
#define KV_oVh 18432
#define KV_oVl 27648
#define SMEM_FLASH (KV_BASE + 2 * KV_STAGE)   // 110592

__global__ void __launch_bounds__(256)
flash_mma_kernel(const __nv_bfloat16* __restrict__ Qh, const __nv_bfloat16* __restrict__ Ql,
                 const __nv_bfloat16* __restrict__ Kh, const __nv_bfloat16* __restrict__ Kl,
                 const __nv_bfloat16* __restrict__ Vh, const __nv_bfloat16* __restrict__ Vl,
                 __nv_bfloat16* __restrict__ Ahi, __nv_bfloat16* __restrict__ Alo)
{
    extern __shared__ char smf[];
    const unsigned sb = smem_u32(smf);
    const int tid  = threadIdx.x;
    const int lane = tid & 31;
    const int wid  = tid >> 5;
    const int bh   = blockIdx.y;
    const int q0   = blockIdx.x * 128;

    const size_t qoff = ((size_t)bh * SEQ + q0) * HDIM;
    const size_t koff = (size_t)bh * SEQ * HDIM;
    const __nv_bfloat16* pQh = Qh + qoff;
    const __nv_bfloat16* pQl = Ql + qoff;
    const __nv_bfloat16* pKh = Kh + koff;
    const __nv_bfloat16* pKl = Kl + koff;
    const __nv_bfloat16* pVh = Vh + koff;
    const __nv_bfloat16* pVl = Vl + koff;

    // load 128x64 Q hi/lo (its own cp.async group)
#pragma unroll
    for (int i = 0; i < 4; i++) {
        int task = tid + i * 256;
        int r = task >> 3, c = task & 7;
        cp16(sb + F_oQh + r * QSTR + c * 16, pQh + (size_t)r * HDIM + c * 8);
        cp16(sb + F_oQl + r * QSTR + c * 16, pQl + (size_t)r * HDIM + c * 8);
    }
    cp_commit();

    // KV tile loader (one cp.async group per call)
    auto load_kv = [&](int kt, int s) {
        const unsigned st = sb + KV_BASE + s * KV_STAGE;
        const int k0 = kt * 64;
#pragma unroll
        for (int i = 0; i < 2; i++) {
            int task = tid + i * 256;
            int r = task >> 3, c = task & 7;
            size_t go = (size_t)(k0 + r) * HDIM + c * 8;
            unsigned so = r * QSTR + c * 16;
            cp16(st + KV_oKh + so, pKh + go);
            cp16(st + KV_oKl + so, pKl + go);
            cp16(st + KV_oVh + so, pVh + go);
            cp16(st + KV_oVl + so, pVl + go);
        }
        cp_commit();
    };

    const int g  = lane >> 2;
    const int tg = lane & 3;
    const unsigned aAddr = sb + (unsigned)((wid * 16 + ((lane >> 3) & 1) * 8 + (lane & 7)) * QSTR
                                           + (lane >> 4) * 16);
    const unsigned kRel = (unsigned)((((lane >> 4) & 1) * 8 + (lane & 7)) * QSTR
                                     + ((lane >> 3) & 1) * 16);
    const unsigned vRel = (unsigned)((((lane >> 3) & 1) * 8 + (lane & 7)) * QSTR
                                     + (lane >> 4) * 16);

    float m0 = -INFINITY, m1 = -INFINITY, l0 = 0.f, l1 = 0.f;
    float o[8][4];
#pragma unroll
    for (int nf = 0; nf < 8; nf++)
#pragma unroll
        for (int j = 0; j < 4; j++) o[nf][j] = 0.f;

    load_kv(0, 0);

    for (int kt = 0; kt < SEQ / 64; kt++) {
        const int s = kt & 1;
        if (kt + 1 < SEQ / 64) {
            load_kv(kt + 1, s ^ 1);   // prefetch next tile while this one computes
            cp_wait<1>();             // wait for tile kt (and Q on first iter)
        } else {
            cp_wait<0>();
        }
        __syncthreads();

        const unsigned stK = sb + KV_BASE + s * KV_STAGE;

        // ---- S = Q K^T (16 x 64 per warp) ----
        float sc[8][4];
#pragma unroll
        for (int nf = 0; nf < 8; nf++)
#pragma unroll
            for (int j = 0; j < 4; j++) sc[nf][j] = 0.f;

#pragma unroll
        for (int ks = 0; ks < 4; ks++) {
            unsigned qhf[4], qlf[4];
            ldx4(qhf, aAddr + F_oQh + ks * 32);
            ldx4(qlf, aAddr + F_oQl + ks * 32);
#pragma unroll
            for (int p = 0; p < 4; p++) {
                unsigned khf[4], klf[4];
                ldx4(khf, stK + KV_oKh + kRel + p * (16 * QSTR) + ks * 32);
                ldx4(klf, stK + KV_oKl + kRel + p * (16 * QSTR) + ks * 32);
                mma16816(sc[2 * p],     qhf, &khf[0]);
                mma16816(sc[2 * p],     qhf, &klf[0]);
                mma16816(sc[2 * p],     qlf, &khf[0]);
                mma16816(sc[2 * p + 1], qhf, &khf[2]);
                mma16816(sc[2 * p + 1], qhf, &klf[2]);
                mma16816(sc[2 * p + 1], qlf, &khf[2]);
            }
        }

        // ---- online softmax (rows g and g+8) ----
        float pm0 = sc[0][0], pm1 = sc[0][2];
#pragma unroll
        for (int nf = 0; nf < 8; nf++) {
            pm0 = fmaxf(pm0, fmaxf(sc[nf][0], sc[nf][1]));
            pm1 = fmaxf(pm1, fmaxf(sc[nf][2], sc[nf][3]));
        }
        pm0 = fmaxf(pm0, __shfl_xor_sync(0xffffffffu, pm0, 1, 4));
        pm0 = fmaxf(pm0, __shfl_xor_sync(0xffffffffu, pm0, 2, 4));
        pm1 = fmaxf(pm1, __shfl_xor_sync(0xffffffffu, pm1, 1, 4));
        pm1 = fmaxf(pm1, __shfl_xor_sync(0xffffffffu, pm1, 2, 4));
        const float mn0 = fmaxf(m0, pm0);
        const float mn1 = fmaxf(m1, pm1);
        const float al0 = __expf(m0 - mn0);
        const float al1 = __expf(m1 - mn1);
        m0 = mn0; m1 = mn1;
        float ps0 = 0.f, ps1 = 0.f;
#pragma unroll
        for (int nf = 0; nf < 8; nf++) {
            sc[nf][0] = __expf(sc[nf][0] - mn0);
            sc[nf][1] = __expf(sc[nf][1] - mn0);
            sc[nf][2] = __expf(sc[nf][2] - mn1);
            sc[nf][3] = __expf(sc[nf][3] - mn1);
            ps0 += sc[nf][0] + sc[nf][1];
            ps1 += sc[nf][2] + sc[nf][3];
        }
        ps0 += __shfl_xor_sync(0xffffffffu, ps0, 1, 4);
        ps0 += __shfl_xor_sync(0xffffffffu, ps0, 2, 4);
        ps1 += __shfl_xor_sync(0xffffffffu, ps1, 1, 4);
        ps1 += __shfl_xor_sync(0xffffffffu, ps1, 2, 4);
        l0 = l0 * al0 + ps0;
        l1 = l1 * al1 + ps1;
#pragma unroll
        for (int nf = 0; nf < 8; nf++) {
            o[nf][0] *= al0; o[nf][1] *= al0;
            o[nf][2] *= al1; o[nf][3] *= al1;
        }

        // ---- O += P V (bf16x3) ----
#pragma unroll
        for (int kb = 0; kb < 4; kb++) {
            float r0, r1, r2, r3, r4, r5, r6, r7;
            unsigned pa_h[4], pa_l[4];
            pa_h[0] = pack_hi_res(sc[2 * kb][0],     sc[2 * kb][1],     r0, r1);
            pa_h[1] = pack_hi_res(sc[2 * kb][2],     sc[2 * kb][3],     r2, r3);
            pa_h[2] = pack_hi_res(sc[2 * kb + 1][0], sc[2 * kb + 1][1], r4, r5);
            pa_h[3] = pack_hi_res(sc[2 * kb + 1][2], sc[2 * kb + 1][3], r6, r7);
            pa_l[0] = pack_bf2(r0, r1);
            pa_l[1] = pack_bf2(r2, r3);
            pa_l[2] = pack_bf2(r4, r5);
            pa_l[3] = pack_bf2(r6, r7);
#pragma unroll
            for (int du = 0; du < 4; du++) {
                unsigned vhf[4], vlf[4];
                ldx4t(vhf, stK + KV_oVh + vRel + kb * (16 * QSTR) + du * 32);
                ldx4t(vlf, stK + KV_oVl + vRel + kb * (16 * QSTR) + du * 32);
                mma16816(o[du * 2],     pa_h, &vhf[0]);
                mma16816(o[du * 2],     pa_h, &vlf[0]);
                mma16816(o[du * 2],     pa_l, &vhf[0]);
                mma16816(o[du * 2 + 1], pa_h, &vhf[2]);
                mma16816(o[du * 2 + 1], pa_h, &vlf[2]);
                mma16816(o[du * 2 + 1], pa_l, &vhf[2]);
            }
        }
        __syncthreads();   // stage consumed; next iteration may overwrite it
    }

    // ---- finalize ----
    const float inv0 = 1.f / l0;
    const float inv1 = 1.f / l1;
    const int b = bh / HEADS;
    const int h = bh % HEADS;
    const int s0r = q0 + wid * 16 + g;
    const size_t row0 = (size_t)(b * SEQ + s0r) * EMBED;
    const size_t row1 = (size_t)(b * SEQ + s0r + 8) * EMBED;
#pragma unroll
    for (int nf = 0; nf < 8; nf++) {
        const int e = h * HDIM + nf * 8 + tg * 2;
        float a0 = o[nf][0] * inv0, a1 = o[nf][1] * inv0;
        float b0 = o[nf][2] * inv1, b1 = o[nf][3] * inv1;
        float ra0, ra1, rb0, rb1;
        unsigned h0 = pack_hi_res(a0, a1, ra0, ra1);
        unsigned h1 = pack_hi_res(b0, b1, rb0, rb1);
        *(unsigned*)&Ahi[row0 + e] = h0;
        *(unsigned*)&Alo[row0 + e] = pack_bf2(ra0, ra1);
        *(unsigned*)&Ahi[row1 + e] = h1;
        *(unsigned*)&Alo[row1 + e] = pack_bf2(rb0, rb1);
    }
}

// ---------------- driver ----------------
extern "C" void kernel_launch(void* const* d_in, const int* in_sizes, int n_in,
                              void* d_out, int out_size)
{
    const float *x, *w_q, *b_q, *w_k, *b_k, *w_v, *b_v, *w_o, *b_o;
    if (n_in == 9 && in_sizes[0] == EMBED && in_sizes[8] == NX) {
        b_k = (const float*)d_in[0]; b_o = (const float*)d_in[1];
        b_q = (const float*)d_in[2]; b_v = (const float*)d_in[3];
        w_k = (const float*)d_in[4]; w_o = (const float*)d_in[5];
        w_q = (const float*)d_in[6]; w_v = (const float*)d_in[7];
        x   = (const float*)d_in[8];
    } else if (n_in == 9 && in_sizes[0] == NX && in_sizes[2] == NW) {
        x   = (const float*)d_in[0];
        w_q = (const float*)d_in[1]; w_k = (const float*)d_in[2];
        w_v = (const float*)d_in[3]; w_o = (const float*)d_in[4];
        b_q = (const float*)d_in[5]; b_k = (const float*)d_in[6];
        b_v = (const float*)d_in[7]; b_o = (const float*)d_in[8];
    } else {
        x   = (const float*)d_in[0];
        w_q = (const float*)d_in[1]; b_q = (const float*)d_in[2];
        w_k = (const float*)d_in[3]; b_k = (const float*)d_in[4];
        w_v = (const float*)d_in[5]; b_v = (const float*)d_in[6];
        w_o = (const float*)d_in[7]; b_o = (const float*)d_in[8];
    }
    float* out = (float*)d_out;

    __nv_bfloat16 *xh, *xl, *w0h, *w0l, *w1h, *w1l, *w2h, *w2l, *w3h, *w3l;
    __nv_bfloat16 *qh, *ql, *kh, *kl, *vh, *vl, *ah, *al;
    cudaGetSymbolAddress((void**)&xh,  g_Xhi);  cudaGetSymbolAddress((void**)&xl,  g_Xlo);
    cudaGetSymbolAddress((void**)&w0h, g_W0hi); cudaGetSymbolAddress((void**)&w0l, g_W0lo);
    cudaGetSymbolAddress((void**)&w1h, g_W1hi); cudaGetSymbolAddress((void**)&w1l, g_W1lo);
    cudaGetSymbolAddress((void**)&w2h, g_W2hi); cudaGetSymbolAddress((void**)&w2l, g_W2lo);
    cudaGetSymbolAddress((void**)&w3h, g_W3hi); cudaGetSymbolAddress((void**)&w3l, g_W3lo);
    cudaGetSymbolAddress((void**)&qh,  g_Qh);   cudaGetSymbolAddress((void**)&ql,  g_Ql);
    cudaGetSymbolAddress((void**)&kh,  g_Kh);   cudaGetSymbolAddress((void**)&kl,  g_Kl);
    cudaGetSymbolAddress((void**)&vh,  g_Vh);   cudaGetSymbolAddress((void**)&vl,  g_Vl);
    cudaGetSymbolAddress((void**)&ah,  g_Ahi);  cudaGetSymbolAddress((void**)&al,  g_Alo);

    cudaFuncSetAttribute(mma_gemm_kernel,
                         cudaFuncAttributeMaxDynamicSharedMemorySize, SMEM_GEMM);
    cudaFuncSetAttribute(flash_mma_kernel,
                         cudaFuncAttributeMaxDynamicSharedMemorySize, SMEM_FLASH);

    convert_kernel<<<NX / 1024, 256>>>(x,   xh,  xl,  NX);
    convert_kernel<<<NW / 1024, 256>>>(w_q, w0h, w0l, NW);
    convert_kernel<<<NW / 1024, 256>>>(w_k, w1h, w1l, NW);
    convert_kernel<<<NW / 1024, 256>>>(w_v, w2h, w2l, NW);
    convert_kernel<<<NW / 1024, 256>>>(w_o, w3h, w3l, NW);

    dim3 ggrid(EMBED / GBN, MROWS / GBM);   // (12, 32)

    mma_gemm_kernel<<<ggrid, 256, SMEM_GEMM>>>(xh, xl, w0h, w0l, b_q, nullptr, qh, ql, 0, 0.125f);
    mma_gemm_kernel<<<ggrid, 256, SMEM_GEMM>>>(xh, xl, w1h, w1l, b_k, nullptr, kh, kl, 0, 1.0f);
    mma_gemm_kernel<<<ggrid, 256, SMEM_GEMM>>>(xh, xl, w2h, w2l, b_v, nullptr, vh, vl, 0, 1.0f);

    dim3 agrid(SEQ / 128, BH);              // (16, 24)
    flash_mma_kernel<<<agrid, 256, SMEM_FLASH>>>(qh, ql, kh, kl, vh, vl, ah, al);

    mma_gemm_kernel<<<ggrid, 256, SMEM_GEMM>>>(ah, al, w3h, w3l, b_o, out, nullptr, nullptr, 1, 1.0f);
}

// round 8
// speedup vs baseline: 3.3165x; 1.0785x over previous
#include <cuda_runtime.h>
#include <cuda_bf16.h>
#include <math.h>

#define EMBED 768
#define HEADS 12
#define HDIM  64
#define BATCH 2
#define SEQ   2048
#define MROWS (BATCH * SEQ)      // 4096
#define BH    (BATCH * HEADS)    // 24
#define NX (MROWS * EMBED)
#define NW (EMBED * EMBED)
#define BHS (BH * SEQ)           // 49152

// ---------------- scratch ----------------
__device__ __nv_bfloat16 g_Xhi[NX], g_Xlo[NX];
__device__ __nv_bfloat16 g_W0hi[NW], g_W0lo[NW];
__device__ __nv_bfloat16 g_W1hi[NW], g_W1lo[NW];
__device__ __nv_bfloat16 g_W2hi[NW], g_W2lo[NW];
__device__ __nv_bfloat16 g_W3hi[NW], g_W3lo[NW];
__device__ __nv_bfloat16 g_Qh[NX], g_Ql[NX];
__device__ __nv_bfloat16 g_Kh[NX], g_Kl[NX];
__device__ __nv_bfloat16 g_Vh[NX], g_Vl[NX];
__device__ __nv_bfloat16 g_Ahi[NX], g_Alo[NX];
// split-KV partials
__device__ float g_Op[2 * BHS * HDIM];
__device__ float g_Mp[2 * BHS];
__device__ float g_Lp[2 * BHS];

// ---------------- PTX helpers (family-portable sm_80+) ----------------
__device__ __forceinline__ unsigned smem_u32(const void* p) {
    unsigned a;
    asm("{ .reg .u64 t; cvta.to.shared.u64 t, %1; cvt.u32.u64 %0, t; }" : "=r"(a) : "l"(p));
    return a;
}
__device__ __forceinline__ void cp16(unsigned s, const void* g) {
    asm volatile("cp.async.cg.shared.global [%0], [%1], 16;" :: "r"(s), "l"(g));
}
__device__ __forceinline__ void cp_commit() { asm volatile("cp.async.commit_group;" ::: "memory"); }
template <int N> __device__ __forceinline__ void cp_wait() {
    asm volatile("cp.async.wait_group %0;" :: "n"(N) : "memory");
}
__device__ __forceinline__ void ldx4(unsigned* r, unsigned addr) {
    asm volatile("ldmatrix.sync.aligned.m8n8.x4.shared.b16 {%0,%1,%2,%3}, [%4];"
        : "=r"(r[0]), "=r"(r[1]), "=r"(r[2]), "=r"(r[3]) : "r"(addr));
}
__device__ __forceinline__ void ldx4t(unsigned* r, unsigned addr) {
    asm volatile("ldmatrix.sync.aligned.m8n8.x4.trans.shared.b16 {%0,%1,%2,%3}, [%4];"
        : "=r"(r[0]), "=r"(r[1]), "=r"(r[2]), "=r"(r[3]) : "r"(addr));
}
__device__ __forceinline__ void mma16816(float* d, const unsigned* a, const unsigned* b) {
    asm volatile(
        "mma.sync.aligned.m16n8k16.row.col.f32.bf16.bf16.f32 "
        "{%0,%1,%2,%3}, {%4,%5,%6,%7}, {%8,%9}, {%0,%1,%2,%3};"
        : "+f"(d[0]), "+f"(d[1]), "+f"(d[2]), "+f"(d[3])
        : "r"(a[0]), "r"(a[1]), "r"(a[2]), "r"(a[3]), "r"(b[0]), "r"(b[1]));
}
__device__ __forceinline__ unsigned pack_bf2(float a, float b) {
    __nv_bfloat162 t = __float22bfloat162_rn(make_float2(a, b));
    return *(unsigned*)&t;
}
__device__ __forceinline__ unsigned pack_hi_res(float a, float b, float& ra, float& rb) {
    __nv_bfloat162 t = __float22bfloat162_rn(make_float2(a, b));
    ra = a - __bfloat162float(t.x);
    rb = b - __bfloat162float(t.y);
    return *(unsigned*)&t;
}

// ---------------- fused fp32 -> bf16 hi/lo split (all 5 inputs) ----------------
struct alignas(8) B4 { __nv_bfloat16 v[4]; };
#define CONV_TASKS ((NX + 4 * NW) / 4)

__global__ void __launch_bounds__(256)
convert_all_kernel(const float* __restrict__ x,
                   const float* __restrict__ w0, const float* __restrict__ w1,
                   const float* __restrict__ w2, const float* __restrict__ w3,
                   __nv_bfloat16* xh, __nv_bfloat16* xl,
                   __nv_bfloat16* w0h, __nv_bfloat16* w0l,
                   __nv_bfloat16* w1h, __nv_bfloat16* w1l,
                   __nv_bfloat16* w2h, __nv_bfloat16* w2l,
                   __nv_bfloat16* w3h, __nv_bfloat16* w3l)
{
    long long t = (long long)blockIdx.x * 256 + threadIdx.x;
    if (t >= CONV_TASKS) return;
    long long i = t * 4;
    const float* src;
    __nv_bfloat16 *hi, *lo;
    long long off;
    if (i < NX) { src = x; hi = xh; lo = xl; off = i; }
    else {
        long long j = i - NX;
        int w = (int)(j / NW);
        off = j - (long long)w * NW;
        if      (w == 0) { src = w0; hi = w0h; lo = w0l; }
        else if (w == 1) { src = w1; hi = w1h; lo = w1l; }
        else if (w == 2) { src = w2; hi = w2h; lo = w2l; }
        else             { src = w3; hi = w3h; lo = w3l; }
    }
    float4 v = *(const float4*)&src[off];
    B4 h, l;
    float f[4] = {v.x, v.y, v.z, v.w};
#pragma unroll
    for (int j = 0; j < 4; j++) {
        h.v[j] = __float2bfloat16(f[j]);
        l.v[j] = __float2bfloat16(f[j] - __bfloat162float(h.v[j]));
    }
    *(B4*)&hi[off] = h;
    *(B4*)&lo[off] = l;
}

// ---------------- HMMA GEMM body: Y = X @ W^T + b  (bf16x3) ----------------
#define GBM 128
#define GBN 64
#define GBK 32
#define KITERS (EMBED / GBK)
#define ASTR 80
#define A_SZ (128 * ASTR)
#define B_SZ (64 * ASTR)
#define STAGE (2 * A_SZ + 2 * B_SZ)
#define SMEM_GEMM (2 * STAGE)

__device__ __forceinline__ void
gemm_body(unsigned sb,
          const __nv_bfloat16* __restrict__ Ahi, const __nv_bfloat16* __restrict__ Alo,
          const __nv_bfloat16* __restrict__ Bhi, const __nv_bfloat16* __restrict__ Blo,
          const float* __restrict__ bias, float* __restrict__ Yf,
          __nv_bfloat16* __restrict__ Yhi, __nv_bfloat16* __restrict__ Ylo,
          int mode, float scale, int m0, int n0)
{
    const int tid  = threadIdx.x;
    const int lane = tid & 31;
    const int wid  = tid >> 5;
    const int warpM = wid & 3;
    const int warpN = wid >> 2;

    auto sA_hi = [&](int s) { return sb + s * STAGE; };
    auto sA_lo = [&](int s) { return sb + s * STAGE + A_SZ; };
    auto sB_hi = [&](int s) { return sb + s * STAGE + 2 * A_SZ; };
    auto sB_lo = [&](int s) { return sb + s * STAGE + 2 * A_SZ + B_SZ; };

    const int ar0 = (tid * 2) >> 2, ac0 = (tid * 2) & 3;
    const int ar1 = (tid * 2 + 1) >> 2, ac1 = (tid * 2 + 1) & 3;
    const int br = tid >> 2, bc = tid & 3;

    auto load_stage = [&](int kt, int s) {
        const int k0 = kt * GBK;
        const __nv_bfloat16* pah = Ahi + (size_t)m0 * EMBED + k0;
        const __nv_bfloat16* pal = Alo + (size_t)m0 * EMBED + k0;
        const __nv_bfloat16* pbh = Bhi + (size_t)n0 * EMBED + k0;
        const __nv_bfloat16* pbl = Blo + (size_t)n0 * EMBED + k0;
        cp16(sA_hi(s) + ar0 * ASTR + ac0 * 16, pah + (size_t)ar0 * EMBED + ac0 * 8);
        cp16(sA_hi(s) + ar1 * ASTR + ac1 * 16, pah + (size_t)ar1 * EMBED + ac1 * 8);
        cp16(sA_lo(s) + ar0 * ASTR + ac0 * 16, pal + (size_t)ar0 * EMBED + ac0 * 8);
        cp16(sA_lo(s) + ar1 * ASTR + ac1 * 16, pal + (size_t)ar1 * EMBED + ac1 * 8);
        cp16(sB_hi(s) + br * ASTR + bc * 16,   pbh + (size_t)br * EMBED + bc * 8);
        cp16(sB_lo(s) + br * ASTR + bc * 16,   pbl + (size_t)br * EMBED + bc * 8);
    };

    const unsigned aOff = (unsigned)((warpM * 32 + ((lane >> 3) & 1) * 8 + (lane & 7)) * ASTR
                                     + (lane >> 4) * 16);
    const unsigned bOff = (unsigned)((warpN * 32 + ((lane >> 4) & 1) * 8 + (lane & 7)) * ASTR
                                     + ((lane >> 3) & 1) * 16);

    float acc[2][4][4];
#pragma unroll
    for (int mt = 0; mt < 2; mt++)
#pragma unroll
        for (int nt = 0; nt < 4; nt++)
#pragma unroll
            for (int j = 0; j < 4; j++) acc[mt][nt][j] = 0.f;

    load_stage(0, 0);
    cp_commit();

    for (int kt = 0; kt < KITERS; kt++) {
        const int s = kt & 1;
        if (kt + 1 < KITERS) {
            load_stage(kt + 1, s ^ 1);
            cp_commit();
            cp_wait<1>();
        } else {
            cp_wait<0>();
        }
        __syncthreads();

#pragma unroll
        for (int ks = 0; ks < 2; ks++) {
            unsigned a_h[2][4], a_l[2][4], b_h[2][4], b_l[2][4];
#pragma unroll
            for (int mt = 0; mt < 2; mt++) {
                ldx4(a_h[mt], sA_hi(s) + aOff + mt * (16 * ASTR) + ks * 32);
                ldx4(a_l[mt], sA_lo(s) + aOff + mt * (16 * ASTR) + ks * 32);
            }
#pragma unroll
            for (int p = 0; p < 2; p++) {
                ldx4(b_h[p], sB_hi(s) + bOff + p * (16 * ASTR) + ks * 32);
                ldx4(b_l[p], sB_lo(s) + bOff + p * (16 * ASTR) + ks * 32);
            }
#pragma unroll
            for (int mt = 0; mt < 2; mt++)
#pragma unroll
                for (int p = 0; p < 2; p++)
#pragma unroll
                    for (int j = 0; j < 2; j++) {
                        const int nt = p * 2 + j;
                        mma16816(acc[mt][nt], a_h[mt], &b_h[p][j * 2]);
                        mma16816(acc[mt][nt], a_h[mt], &b_l[p][j * 2]);
                        mma16816(acc[mt][nt], a_l[mt], &b_h[p][j * 2]);
                    }
        }
        __syncthreads();
    }

    const int g  = lane >> 2;
    const int tg = lane & 3;
#pragma unroll
    for (int mt = 0; mt < 2; mt++) {
#pragma unroll
        for (int nt = 0; nt < 4; nt++) {
            const int nl = warpN * 32 + nt * 8 + tg * 2;
            const int n  = n0 + nl;
            float2 bv = *(const float2*)&bias[n];
#pragma unroll
            for (int half = 0; half < 2; half++) {
                const int ml = warpM * 32 + mt * 16 + g + half * 8;
                const int m  = m0 + ml;
                float c0 = acc[mt][nt][half * 2 + 0] + bv.x;
                float c1 = acc[mt][nt][half * 2 + 1] + bv.y;
                if (mode == 0) {
                    const int h = n0 >> 6;
                    const int bb = m >> 11;
                    const int ss = m & 2047;
                    float v0 = c0 * scale, v1 = c1 * scale;
                    float r0, r1;
                    unsigned hp = pack_hi_res(v0, v1, r0, r1);
                    unsigned lp = pack_bf2(r0, r1);
                    size_t idx = ((size_t)(bb * HEADS + h) * SEQ + ss) * HDIM + (n & 63);
                    *(unsigned*)&Yhi[idx] = hp;
                    *(unsigned*)&Ylo[idx] = lp;
                } else {
                    *(float2*)&Yf[(size_t)m * EMBED + n] = make_float2(c0, c1);
                }
            }
        }
    }
}

// fused Q/K/V projection: proj = blockIdx.x / 12
__global__ void __launch_bounds__(256)
mma_gemm_qkv_kernel(const __nv_bfloat16* __restrict__ xh, const __nv_bfloat16* __restrict__ xl,
                    const __nv_bfloat16* __restrict__ w0h, const __nv_bfloat16* __restrict__ w0l,
                    const __nv_bfloat16* __restrict__ w1h, const __nv_bfloat16* __restrict__ w1l,
                    const __nv_bfloat16* __restrict__ w2h, const __nv_bfloat16* __restrict__ w2l,
                    const float* __restrict__ b_q, const float* __restrict__ b_k,
                    const float* __restrict__ b_v,
                    __nv_bfloat16* qh, __nv_bfloat16* ql,
                    __nv_bfloat16* kh, __nv_bfloat16* kl,
                    __nv_bfloat16* vh, __nv_bfloat16* vl)
{
    extern __shared__ char smraw[];
    const unsigned sb = smem_u32(smraw);
    const int pj   = blockIdx.x / 12;
    const int nblk = blockIdx.x % 12;
    const __nv_bfloat16 *Bh, *Bl;
    const float* bias;
    __nv_bfloat16 *Yh, *Yl;
    float scale;
    if (pj == 0)      { Bh = w0h; Bl = w0l; bias = b_q; Yh = qh; Yl = ql; scale = 0.125f; }
    else if (pj == 1) { Bh = w1h; Bl = w1l; bias = b_k; Yh = kh; Yl = kl; scale = 1.0f; }
    else              { Bh = w2h; Bl = w2l; bias = b_v; Yh = vh; Yl = vl; scale = 1.0f; }
    gemm_body(sb, xh, xl, Bh, Bl, bias, nullptr, Yh, Yl, 0, scale,
              blockIdx.y * GBM, nblk * GBN);
}

// out-projection
__global__ void __launch_bounds__(256)
mma_gemm_o_kernel(const __nv_bfloat16* __restrict__ ah, const __nv_bfloat16* __restrict__ al,
                  const __nv_bfloat16* __restrict__ w3h, const __nv_bfloat16* __restrict__ w3l,
                  const float* __restrict__ b_o, float* __restrict__ out)
{
    extern __shared__ char smraw[];
    const unsigned sb = smem_u32(smraw);
    gemm_body(sb, ah, al, w3h, w3l, b_o, out, nullptr, nullptr, 1, 1.0f,
              blockIdx.y * GBM, blockIdx.x * GBN);
}

// ---------------- Flash attention, split-KV x2 ----------------
#define QSTR 144
#define F_oQh 0
#define F_oQl 18432
#define KV_BASE 36864
#define KV_STAGE 36864
#define KV_oKh 0
#define KV_oKl 9216
#define KV_oVh 18432
#define KV_oVl 27648
#define SMEM_FLASH (KV_BASE + 2 * KV_STAGE)   // 110592
#define NSPLIT 2
#define TILES_PER_SPLIT (SEQ / 64 / NSPLIT)   // 16

__global__ void __launch_bounds__(256)
flash_mma_kernel(const __nv_bfloat16* __restrict__ Qh, const __nv_bfloat16* __restrict__ Ql,
                 const __nv_bfloat16* __restrict__ Kh, const __nv_bfloat16* __restrict__ Kl,
                 const __nv_bfloat16* __restrict__ Vh, const __nv_bfloat16* __restrict__ Vl)
{
    extern __shared__ char smf[];
    const unsigned sb = smem_u32(smf);
    const int tid  = threadIdx.x;
    const int lane = tid & 31;
    const int wid  = tid >> 5;
    const int bh   = blockIdx.y;
    const int q0   = blockIdx.x * 128;
    const int split = blockIdx.z;

    const size_t qoff = ((size_t)bh * SEQ + q0) * HDIM;
    const size_t koff = (size_t)bh * SEQ * HDIM;
    const __nv_bfloat16* pQh = Qh + qoff;
    const __nv_bfloat16* pQl = Ql + qoff;
    const __nv_bfloat16* pKh = Kh + koff;
    const __nv_bfloat16* pKl = Kl + koff;
    const __nv_bfloat16* pVh = Vh + koff;
    const __nv_bfloat16* pVl = Vl + koff;

#pragma unroll
    for (int i = 0; i < 4; i++) {
        int task = tid + i * 256;
        int r = task >> 3, c = task & 7;
        cp16(sb + F_oQh + r * QSTR + c * 16, pQh + (size_t)r * HDIM + c * 8);
        cp16(sb + F_oQl + r * QSTR + c * 16, pQl + (size_t)r * HDIM + c * 8);
    }
    cp_commit();

    auto load_kv = [&](int kt, int s) {
        const unsigned st = sb + KV_BASE + s * KV_STAGE;
        const int k0 = kt * 64;
#pragma unroll
        for (int i = 0; i < 2; i++) {
            int task = tid + i * 256;
            int r = task >> 3, c = task & 7;
            size_t go = (size_t)(k0 + r) * HDIM + c * 8;
            unsigned so = r * QSTR + c * 16;
            cp16(st + KV_oKh + so, pKh + go);
            cp16(st + KV_oKl + so, pKl + go);
            cp16(st + KV_oVh + so, pVh + go);
            cp16(st + KV_oVl + so, pVl + go);
        }
        cp_commit();
    };

    const int g  = lane >> 2;
    const int tg = lane & 3;
    const unsigned aAddr = sb + (unsigned)((wid * 16 + ((lane >> 3) & 1) * 8 + (lane & 7)) * QSTR
                                           + (lane >> 4) * 16);
    const unsigned kRel = (unsigned)((((lane >> 4) & 1) * 8 + (lane & 7)) * QSTR
                                     + ((lane >> 3) & 1) * 16);
    const unsigned vRel = (unsigned)((((lane >> 3) & 1) * 8 + (lane & 7)) * QSTR
                                     + (lane >> 4) * 16);

    float m0 = -INFINITY, m1 = -INFINITY, l0 = 0.f, l1 = 0.f;
    float o[8][4];
#pragma unroll
    for (int nf = 0; nf < 8; nf++)
#pragma unroll
        for (int j = 0; j < 4; j++) o[nf][j] = 0.f;

    const int kt0 = split * TILES_PER_SPLIT;
    const int kt1 = kt0 + TILES_PER_SPLIT;
    load_kv(kt0, 0);

    for (int kt = kt0; kt < kt1; kt++) {
        const int s = kt & 1;
        if (kt + 1 < kt1) {
            load_kv(kt + 1, s ^ 1);
            cp_wait<1>();
        } else {
            cp_wait<0>();
        }
        __syncthreads();

        const unsigned stK = sb + KV_BASE + s * KV_STAGE;

        float sc[8][4];
#pragma unroll
        for (int nf = 0; nf < 8; nf++)
#pragma unroll
            for (int j = 0; j < 4; j++) sc[nf][j] = 0.f;

#pragma unroll
        for (int ks = 0; ks < 4; ks++) {
            unsigned qhf[4], qlf[4];
            ldx4(qhf, aAddr + F_oQh + ks * 32);
            ldx4(qlf, aAddr + F_oQl + ks * 32);
#pragma unroll
            for (int p = 0; p < 4; p++) {
                unsigned khf[4], klf[4];
                ldx4(khf, stK + KV_oKh + kRel + p * (16 * QSTR) + ks * 32);
                ldx4(klf, stK + KV_oKl + kRel + p * (16 * QSTR) + ks * 32);
                mma16816(sc[2 * p],     qhf, &khf[0]);
                mma16816(sc[2 * p],     qhf, &klf[0]);
                mma16816(sc[2 * p],     qlf, &khf[0]);
                mma16816(sc[2 * p + 1], qhf, &khf[2]);
                mma16816(sc[2 * p + 1], qhf, &klf[2]);
                mma16816(sc[2 * p + 1], qlf, &khf[2]);
            }
        }

        float pm0 = sc[0][0], pm1 = sc[0][2];
#pragma unroll
        for (int nf = 0; nf < 8; nf++) {
            pm0 = fmaxf(pm0, fmaxf(sc[nf][0], sc[nf][1]));
            pm1 = fmaxf(pm1, fmaxf(sc[nf][2], sc[nf][3]));
        }
        pm0 = fmaxf(pm0, __shfl_xor_sync(0xffffffffu, pm0, 1, 4));
        pm0 = fmaxf(pm0, __shfl_xor_sync(0xffffffffu, pm0, 2, 4));
        pm1 = fmaxf(pm1, __shfl_xor_sync(0xffffffffu, pm1, 1, 4));
        pm1 = fmaxf(pm1, __shfl_xor_sync(0xffffffffu, pm1, 2, 4));
        const float mn0 = fmaxf(m0, pm0);
        const float mn1 = fmaxf(m1, pm1);
        const float al0 = __expf(m0 - mn0);
        const float al1 = __expf(m1 - mn1);
        m0 = mn0; m1 = mn1;
        float ps0 = 0.f, ps1 = 0.f;
#pragma unroll
        for (int nf = 0; nf < 8; nf++) {
            sc[nf][0] = __expf(sc[nf][0] - mn0);
            sc[nf][1] = __expf(sc[nf][1] - mn0);
            sc[nf][2] = __expf(sc[nf][2] - mn1);
            sc[nf][3] = __expf(sc[nf][3] - mn1);
            ps0 += sc[nf][0] + sc[nf][1];
            ps1 += sc[nf][2] + sc[nf][3];
        }
        ps0 += __shfl_xor_sync(0xffffffffu, ps0, 1, 4);
        ps0 += __shfl_xor_sync(0xffffffffu, ps0, 2, 4);
        ps1 += __shfl_xor_sync(0xffffffffu, ps1, 1, 4);
        ps1 += __shfl_xor_sync(0xffffffffu, ps1, 2, 4);
        l0 = l0 * al0 + ps0;
        l1 = l1 * al1 + ps1;
#pragma unroll
        for (int nf = 0; nf < 8; nf++) {
            o[nf][0] *= al0; o[nf][1] *= al0;
            o[nf][2] *= al1; o[nf][3] *= al1;
        }

#pragma unroll
        for (int kb = 0; kb < 4; kb++) {
            float r0, r1, r2, r3, r4, r5, r6, r7;
            unsigned pa_h[4], pa_l[4];
            pa_h[0] = pack_hi_res(sc[2 * kb][0],     sc[2 * kb][1],     r0, r1);
            pa_h[1] = pack_hi_res(sc[2 * kb][2],     sc[2 * kb][3],     r2, r3);
            pa_h[2] = pack_hi_res(sc[2 * kb + 1][0], sc[2 * kb + 1][1], r4, r5);
            pa_h[3] = pack_hi_res(sc[2 * kb + 1][2], sc[2 * kb + 1][3], r6, r7);
            pa_l[0] = pack_bf2(r0, r1);
            pa_l[1] = pack_bf2(r2, r3);
            pa_l[2] = pack_bf2(r4, r5);
            pa_l[3] = pack_bf2(r6, r7);
#pragma unroll
            for (int du = 0; du < 4; du++) {
                unsigned vhf[4], vlf[4];
                ldx4t(vhf, stK + KV_oVh + vRel + kb * (16 * QSTR) + du * 32);
                ldx4t(vlf, stK + KV_oVl + vRel + kb * (16 * QSTR) + du * 32);
                mma16816(o[du * 2],     pa_h, &vhf[0]);
                mma16816(o[du * 2],     pa_h, &vlf[0]);
                mma16816(o[du * 2],     pa_l, &vhf[0]);
                mma16816(o[du * 2 + 1], pa_h, &vhf[2]);
                mma16816(o[du * 2 + 1], pa_h, &vlf[2]);
                mma16816(o[du * 2 + 1], pa_l, &vhf[2]);
            }
        }
        __syncthreads();
    }

    // ---- store unnormalized partials + (m, l) ----
    const int r0 = q0 + wid * 16 + g;          // row within [0, SEQ)
    const size_t prow = (size_t)(split * BH + bh) * SEQ + r0;
    float* Op0 = &g_Op[prow * HDIM];
    float* Op1 = &g_Op[(prow + 8) * HDIM];
#pragma unroll
    for (int nf = 0; nf < 8; nf++) {
        const int e = nf * 8 + tg * 2;
        *(float2*)&Op0[e] = make_float2(o[nf][0], o[nf][1]);
        *(float2*)&Op1[e] = make_float2(o[nf][2], o[nf][3]);
    }
    if (tg == 0) {
        g_Mp[prow] = m0;     g_Lp[prow] = l0;
        g_Mp[prow + 8] = m1; g_Lp[prow + 8] = l1;
    }
}

// ---------------- split-KV merge: combine 2 partials -> bf16 hi/lo A ----------------
__global__ void __launch_bounds__(256)
merge_kernel(__nv_bfloat16* __restrict__ Ahi, __nv_bfloat16* __restrict__ Alo)
{
    int t = blockIdx.x * 256 + threadIdx.x;     // BHS * 16 tasks
    if (t >= BHS * (HDIM / 4)) return;
    const int c4  = t & 15;
    const size_t row = (size_t)(t >> 4);        // [0, BHS)
    const int bh = (int)(row / SEQ);
    const int s  = (int)(row - (size_t)bh * SEQ);

    float m0 = g_Mp[row], m1 = g_Mp[BHS + row];
    float l0 = g_Lp[row], l1 = g_Lp[BHS + row];
    float M = fmaxf(m0, m1);
    float w0 = __expf(m0 - M), w1 = __expf(m1 - M);
    float inv = 1.f / (l0 * w0 + l1 * w1);
    w0 *= inv; w1 *= inv;

    float4 a = *(const float4*)&g_Op[row * HDIM + c4 * 4];
    float4 b = *(const float4*)&g_Op[(BHS + row) * HDIM + c4 * 4];
    float r0 = a.x * w0 + b.x * w1;
    float r1 = a.y * w0 + b.y * w1;
    float r2 = a.z * w0 + b.z * w1;
    float r3 = a.w * w0 + b.w * w1;

    const int bb = bh / HEADS;
    const int h  = bh % HEADS;
    const size_t dst = ((size_t)(bb * SEQ + s)) * EMBED + h * HDIM + c4 * 4;
    float x0, x1, x2, x3;
    unsigned h0 = pack_hi_res(r0, r1, x0, x1);
    unsigned h1 = pack_hi_res(r2, r3, x2, x3);
    *(unsigned*)&Ahi[dst]     = h0;
    *(unsigned*)&Ahi[dst + 2] = h1;
    *(unsigned*)&Alo[dst]     = pack_bf2(x0, x1);
    *(unsigned*)&Alo[dst + 2] = pack_bf2(x2, x3);
}

// ---------------- driver ----------------
extern "C" void kernel_launch(void* const* d_in, const int* in_sizes, int n_in,
                              void* d_out, int out_size)
{
    const float *x, *w_q, *b_q, *w_k, *b_k, *w_v, *b_v, *w_o, *b_o;
    if (n_in == 9 && in_sizes[0] == EMBED && in_sizes[8] == NX) {
        b_k = (const float*)d_in[0]; b_o = (const float*)d_in[1];
        b_q = (const float*)d_in[2]; b_v = (const float*)d_in[3];
        w_k = (const float*)d_in[4]; w_o = (const float*)d_in[5];
        w_q = (const float*)d_in[6]; w_v = (const float*)d_in[7];
        x   = (const float*)d_in[8];
    } else if (n_in == 9 && in_sizes[0] == NX && in_sizes[2] == NW) {
        x   = (const float*)d_in[0];
        w_q = (const float*)d_in[1]; w_k = (const float*)d_in[2];
        w_v = (const float*)d_in[3]; w_o = (const float*)d_in[4];
        b_q = (const float*)d_in[5]; b_k = (const float*)d_in[6];
        b_v = (const float*)d_in[7]; b_o = (const float*)d_in[8];
    } else {
        x   = (const float*)d_in[0];
        w_q = (const float*)d_in[1]; b_q = (const float*)d_in[2];
        w_k = (const float*)d_in[3]; b_k = (const float*)d_in[4];
        w_v = (const float*)d_in[5]; b_v = (const float*)d_in[6];
        w_o = (const float*)d_in[7]; b_o = (const float*)d_in[8];
    }
    float* out = (float*)d_out;

    __nv_bfloat16 *xh, *xl, *w0h, *w0l, *w1h, *w1l, *w2h, *w2l, *w3h, *w3l;
    __nv_bfloat16 *qh, *ql, *kh, *kl, *vh, *vl, *ah, *al;
    cudaGetSymbolAddress((void**)&xh,  g_Xhi);  cudaGetSymbolAddress((void**)&xl,  g_Xlo);
    cudaGetSymbolAddress((void**)&w0h, g_W0hi); cudaGetSymbolAddress((void**)&w0l, g_W0lo);
    cudaGetSymbolAddress((void**)&w1h, g_W1hi); cudaGetSymbolAddress((void**)&w1l, g_W1lo);
    cudaGetSymbolAddress((void**)&w2h, g_W2hi); cudaGetSymbolAddress((void**)&w2l, g_W2lo);
    cudaGetSymbolAddress((void**)&w3h, g_W3hi); cudaGetSymbolAddress((void**)&w3l, g_W3lo);
    cudaGetSymbolAddress((void**)&qh,  g_Qh);   cudaGetSymbolAddress((void**)&ql,  g_Ql);
    cudaGetSymbolAddress((void**)&kh,  g_Kh);   cudaGetSymbolAddress((void**)&kl,  g_Kl);
    cudaGetSymbolAddress((void**)&vh,  g_Vh);   cudaGetSymbolAddress((void**)&vl,  g_Vl);
    cudaGetSymbolAddress((void**)&ah,  g_Ahi);  cudaGetSymbolAddress((void**)&al,  g_Alo);

    cudaFuncSetAttribute(mma_gemm_qkv_kernel,
                         cudaFuncAttributeMaxDynamicSharedMemorySize, SMEM_GEMM);
    cudaFuncSetAttribute(mma_gemm_o_kernel,
                         cudaFuncAttributeMaxDynamicSharedMemorySize, SMEM_GEMM);
    cudaFuncSetAttribute(flash_mma_kernel,
                         cudaFuncAttributeMaxDynamicSharedMemorySize, SMEM_FLASH);

    convert_all_kernel<<<(CONV_TASKS + 255) / 256, 256>>>(
        x, w_q, w_k, w_v, w_o,
        xh, xl, w0h, w0l, w1h, w1l, w2h, w2l, w3h, w3l);

    dim3 qkvgrid(3 * (EMBED / GBN), MROWS / GBM);   // (36, 32)
    mma_gemm_qkv_kernel<<<qkvgrid, 256, SMEM_GEMM>>>(
        xh, xl, w0h, w0l, w1h, w1l, w2h, w2l,
        b_q, b_k, b_v, qh, ql, kh, kl, vh, vl);

    dim3 agrid(SEQ / 128, BH, NSPLIT);              // (16, 24, 2)
    flash_mma_kernel<<<agrid, 256, SMEM_FLASH>>>(qh, ql, kh, kl, vh, vl);

    merge_kernel<<<(BHS * (HDIM / 4) + 255) / 256, 256>>>(ah, al);

    dim3 ogrid(EMBED / GBN, MROWS / GBM);           // (12, 32)
    mma_gemm_o_kernel<<<ogrid, 256, SMEM_GEMM>>>(ah, al, w3h, w3l, b_o, out);
}

// round 10
// speedup vs baseline: 3.5684x; 1.0759x over previous
#include <cuda_runtime.h>
#include <cuda_bf16.h>
#include <math.h>

#define EMBED 768
#define HEADS 12
#define HDIM  64
#define BATCH 2
#define SEQ   2048
#define MROWS (BATCH * SEQ)      // 4096
#define BH    (BATCH * HEADS)    // 24
#define NX (MROWS * EMBED)
#define NW (EMBED * EMBED)
#define BHS (BH * SEQ)           // 49152
#define NSPLIT 3

// ---------------- scratch ----------------
__device__ __nv_bfloat16 g_Xhi[NX], g_Xlo[NX];
__device__ __nv_bfloat16 g_W0hi[NW], g_W0lo[NW];
__device__ __nv_bfloat16 g_W1hi[NW], g_W1lo[NW];
__device__ __nv_bfloat16 g_W2hi[NW], g_W2lo[NW];
__device__ __nv_bfloat16 g_W3hi[NW], g_W3lo[NW];
__device__ __nv_bfloat16 g_Qh[NX], g_Ql[NX];
__device__ __nv_bfloat16 g_Kh[NX], g_Kl[NX];
__device__ __nv_bfloat16 g_Vh[NX], g_Vl[NX];
__device__ __nv_bfloat16 g_Ahi[NX], g_Alo[NX];
// split-KV partials
__device__ float g_Op[NSPLIT * BHS * HDIM];
__device__ float g_Mp[NSPLIT * BHS];
__device__ float g_Lp[NSPLIT * BHS];

// ---------------- PTX helpers (family-portable sm_80+) ----------------
__device__ __forceinline__ unsigned smem_u32(const void* p) {
    unsigned a;
    asm("{ .reg .u64 t; cvta.to.shared.u64 t, %1; cvt.u32.u64 %0, t; }" : "=r"(a) : "l"(p));
    return a;
}
__device__ __forceinline__ void cp16(unsigned s, const void* g) {
    asm volatile("cp.async.cg.shared.global [%0], [%1], 16;" :: "r"(s), "l"(g));
}
__device__ __forceinline__ void cp_commit() { asm volatile("cp.async.commit_group;" ::: "memory"); }
template <int N> __device__ __forceinline__ void cp_wait() {
    asm volatile("cp.async.wait_group %0;" :: "n"(N) : "memory");
}
__device__ __forceinline__ void ldx4(unsigned* r, unsigned addr) {
    asm volatile("ldmatrix.sync.aligned.m8n8.x4.shared.b16 {%0,%1,%2,%3}, [%4];"
        : "=r"(r[0]), "=r"(r[1]), "=r"(r[2]), "=r"(r[3]) : "r"(addr));
}
__device__ __forceinline__ void ldx4t(unsigned* r, unsigned addr) {
    asm volatile("ldmatrix.sync.aligned.m8n8.x4.trans.shared.b16 {%0,%1,%2,%3}, [%4];"
        : "=r"(r[0]), "=r"(r[1]), "=r"(r[2]), "=r"(r[3]) : "r"(addr));
}
__device__ __forceinline__ void mma16816(float* d, const unsigned* a, const unsigned* b) {
    asm volatile(
        "mma.sync.aligned.m16n8k16.row.col.f32.bf16.bf16.f32 "
        "{%0,%1,%2,%3}, {%4,%5,%6,%7}, {%8,%9}, {%0,%1,%2,%3};"
        : "+f"(d[0]), "+f"(d[1]), "+f"(d[2]), "+f"(d[3])
        : "r"(a[0]), "r"(a[1]), "r"(a[2]), "r"(a[3]), "r"(b[0]), "r"(b[1]));
}
__device__ __forceinline__ unsigned pack_bf2(float a, float b) {
    __nv_bfloat162 t = __float22bfloat162_rn(make_float2(a, b));
    return *(unsigned*)&t;
}
__device__ __forceinline__ unsigned pack_hi_res(float a, float b, float& ra, float& rb) {
    __nv_bfloat162 t = __float22bfloat162_rn(make_float2(a, b));
    ra = a - __bfloat162float(t.x);
    rb = b - __bfloat162float(t.y);
    return *(unsigned*)&t;
}

// ---------------- fused fp32 -> bf16 hi/lo split (all 5 inputs) ----------------
struct alignas(8) B4 { __nv_bfloat16 v[4]; };
#define CONV_TASKS ((NX + 4 * NW) / 4)

__global__ void __launch_bounds__(256)
convert_all_kernel(const float* __restrict__ x,
                   const float* __restrict__ w0, const float* __restrict__ w1,
                   const float* __restrict__ w2, const float* __restrict__ w3,
                   __nv_bfloat16* xh, __nv_bfloat16* xl,
                   __nv_bfloat16* w0h, __nv_bfloat16* w0l,
                   __nv_bfloat16* w1h, __nv_bfloat16* w1l,
                   __nv_bfloat16* w2h, __nv_bfloat16* w2l,
                   __nv_bfloat16* w3h, __nv_bfloat16* w3l)
{
    long long t = (long long)blockIdx.x * 256 + threadIdx.x;
    if (t >= CONV_TASKS) return;
    long long i = t * 4;
    const float* src;
    __nv_bfloat16 *hi, *lo;
    long long off;
    if (i < NX) { src = x; hi = xh; lo = xl; off = i; }
    else {
        long long j = i - NX;
        int w = (int)(j / NW);
        off = j - (long long)w * NW;
        if      (w == 0) { src = w0; hi = w0h; lo = w0l; }
        else if (w == 1) { src = w1; hi = w1h; lo = w1l; }
        else if (w == 2) { src = w2; hi = w2h; lo = w2l; }
        else             { src = w3; hi = w3h; lo = w3l; }
    }
    float4 v = *(const float4*)&src[off];
    B4 h, l;
    float f[4] = {v.x, v.y, v.z, v.w};
#pragma unroll
    for (int j = 0; j < 4; j++) {
        h.v[j] = __float2bfloat16(f[j]);
        l.v[j] = __float2bfloat16(f[j] - __bfloat162float(h.v[j]));
    }
    *(B4*)&hi[off] = h;
    *(B4*)&lo[off] = l;
}

// ---------------- HMMA GEMM body: Y = X @ W^T + b  (bf16x3) ----------------
#define GBM 128
#define GBN 64
#define GBK 32
#define KITERS (EMBED / GBK)
#define ASTR 80
#define A_SZ (128 * ASTR)
#define B_SZ (64 * ASTR)
#define STAGE (2 * A_SZ + 2 * B_SZ)
#define SMEM_GEMM (2 * STAGE)

__device__ __forceinline__ void
gemm_body(unsigned sb,
          const __nv_bfloat16* __restrict__ Ahi, const __nv_bfloat16* __restrict__ Alo,
          const __nv_bfloat16* __restrict__ Bhi, const __nv_bfloat16* __restrict__ Blo,
          const float* __restrict__ bias, float* __restrict__ Yf,
          __nv_bfloat16* __restrict__ Yhi, __nv_bfloat16* __restrict__ Ylo,
          int mode, float scale, int m0, int n0)
{
    const int tid  = threadIdx.x;
    const int lane = tid & 31;
    const int wid  = tid >> 5;
    const int warpM = wid & 3;
    const int warpN = wid >> 2;

    auto sA_hi = [&](int s) { return sb + s * STAGE; };
    auto sA_lo = [&](int s) { return sb + s * STAGE + A_SZ; };
    auto sB_hi = [&](int s) { return sb + s * STAGE + 2 * A_SZ; };
    auto sB_lo = [&](int s) { return sb + s * STAGE + 2 * A_SZ + B_SZ; };

    const int ar0 = (tid * 2) >> 2, ac0 = (tid * 2) & 3;
    const int ar1 = (tid * 2 + 1) >> 2, ac1 = (tid * 2 + 1) & 3;
    const int br = tid >> 2, bc = tid & 3;

    auto load_stage = [&](int kt, int s) {
        const int k0 = kt * GBK;
        const __nv_bfloat16* pah = Ahi + (size_t)m0 * EMBED + k0;
        const __nv_bfloat16* pal = Alo + (size_t)m0 * EMBED + k0;
        const __nv_bfloat16* pbh = Bhi + (size_t)n0 * EMBED + k0;
        const __nv_bfloat16* pbl = Blo + (size_t)n0 * EMBED + k0;
        cp16(sA_hi(s) + ar0 * ASTR + ac0 * 16, pah + (size_t)ar0 * EMBED + ac0 * 8);
        cp16(sA_hi(s) + ar1 * ASTR + ac1 * 16, pah + (size_t)ar1 * EMBED + ac1 * 8);
        cp16(sA_lo(s) + ar0 * ASTR + ac0 * 16, pal + (size_t)ar0 * EMBED + ac0 * 8);
        cp16(sA_lo(s) + ar1 * ASTR + ac1 * 16, pal + (size_t)ar1 * EMBED + ac1 * 8);
        cp16(sB_hi(s) + br * ASTR + bc * 16,   pbh + (size_t)br * EMBED + bc * 8);
        cp16(sB_lo(s) + br * ASTR + bc * 16,   pbl + (size_t)br * EMBED + bc * 8);
    };

    const unsigned aOff = (unsigned)((warpM * 32 + ((lane >> 3) & 1) * 8 + (lane & 7)) * ASTR
                                     + (lane >> 4) * 16);
    const unsigned bOff = (unsigned)((warpN * 32 + ((lane >> 4) & 1) * 8 + (lane & 7)) * ASTR
                                     + ((lane >> 3) & 1) * 16);

    float acc[2][4][4];
#pragma unroll
    for (int mt = 0; mt < 2; mt++)
#pragma unroll
        for (int nt = 0; nt < 4; nt++)
#pragma unroll
            for (int j = 0; j < 4; j++) acc[mt][nt][j] = 0.f;

    load_stage(0, 0);
    cp_commit();

    for (int kt = 0; kt < KITERS; kt++) {
        const int s = kt & 1;
        if (kt + 1 < KITERS) {
            load_stage(kt + 1, s ^ 1);
            cp_commit();
            cp_wait<1>();
        } else {
            cp_wait<0>();
        }
        __syncthreads();

#pragma unroll
        for (int ks = 0; ks < 2; ks++) {
            unsigned a_h[2][4], a_l[2][4], b_h[2][4], b_l[2][4];
#pragma unroll
            for (int mt = 0; mt < 2; mt++) {
                ldx4(a_h[mt], sA_hi(s) + aOff + mt * (16 * ASTR) + ks * 32);
                ldx4(a_l[mt], sA_lo(s) + aOff + mt * (16 * ASTR) + ks * 32);
            }
#pragma unroll
            for (int p = 0; p < 2; p++) {
                ldx4(b_h[p], sB_hi(s) + bOff + p * (16 * ASTR) + ks * 32);
                ldx4(b_l[p], sB_lo(s) + bOff + p * (16 * ASTR) + ks * 32);
            }
#pragma unroll
            for (int mt = 0; mt < 2; mt++)
#pragma unroll
                for (int p = 0; p < 2; p++)
#pragma unroll
                    for (int j = 0; j < 2; j++) {
                        const int nt = p * 2 + j;
                        mma16816(acc[mt][nt], a_h[mt], &b_h[p][j * 2]);
                        mma16816(acc[mt][nt], a_h[mt], &b_l[p][j * 2]);
                        mma16816(acc[mt][nt], a_l[mt], &b_h[p][j * 2]);
                    }
        }
        __syncthreads();
    }

    const int g  = lane >> 2;
    const int tg = lane & 3;
#pragma unroll
    for (int mt = 0; mt < 2; mt++) {
#pragma unroll
        for (int nt = 0; nt < 4; nt++) {
            const int nl = warpN * 32 + nt * 8 + tg * 2;
            const int n  = n0 + nl;
            float2 bv = *(const float2*)&bias[n];
#pragma unroll
            for (int half = 0; half < 2; half++) {
                const int ml = warpM * 32 + mt * 16 + g + half * 8;
                const int m  = m0 + ml;
                float c0 = acc[mt][nt][half * 2 + 0] + bv.x;
                float c1 = acc[mt][nt][half * 2 + 1] + bv.y;
                if (mode == 0) {
                    const int h = n0 >> 6;
                    const int bb = m >> 11;
                    const int ss = m & 2047;
                    float v0 = c0 * scale, v1 = c1 * scale;
                    float r0, r1;
                    unsigned hp = pack_hi_res(v0, v1, r0, r1);
                    unsigned lp = pack_bf2(r0, r1);
                    size_t idx = ((size_t)(bb * HEADS + h) * SEQ + ss) * HDIM + (n & 63);
                    *(unsigned*)&Yhi[idx] = hp;
                    *(unsigned*)&Ylo[idx] = lp;
                } else {
                    *(float2*)&Yf[(size_t)m * EMBED + n] = make_float2(c0, c1);
                }
            }
        }
    }
}

// fused Q/K/V projection: proj = blockIdx.x / 12
__global__ void __launch_bounds__(256, 3)
mma_gemm_qkv_kernel(const __nv_bfloat16* __restrict__ xh, const __nv_bfloat16* __restrict__ xl,
                    const __nv_bfloat16* __restrict__ w0h, const __nv_bfloat16* __restrict__ w0l,
                    const __nv_bfloat16* __restrict__ w1h, const __nv_bfloat16* __restrict__ w1l,
                    const __nv_bfloat16* __restrict__ w2h, const __nv_bfloat16* __restrict__ w2l,
                    const float* __restrict__ b_q, const float* __restrict__ b_k,
                    const float* __restrict__ b_v,
                    __nv_bfloat16* qh, __nv_bfloat16* ql,
                    __nv_bfloat16* kh, __nv_bfloat16* kl,
                    __nv_bfloat16* vh, __nv_bfloat16* vl)
{
    extern __shared__ char smraw[];
    const unsigned sb = smem_u32(smraw);
    const int pj   = blockIdx.x / 12;
    const int nblk = blockIdx.x % 12;
    const __nv_bfloat16 *Bh, *Bl;
    const float* bias;
    __nv_bfloat16 *Yh, *Yl;
    float scale;
    if (pj == 0)      { Bh = w0h; Bl = w0l; bias = b_q; Yh = qh; Yl = ql; scale = 0.125f; }
    else if (pj == 1) { Bh = w1h; Bl = w1l; bias = b_k; Yh = kh; Yl = kl; scale = 1.0f; }
    else              { Bh = w2h; Bl = w2l; bias = b_v; Yh = vh; Yl = vl; scale = 1.0f; }
    gemm_body(sb, xh, xl, Bh, Bl, bias, nullptr, Yh, Yl, 0, scale,
              blockIdx.y * GBM, nblk * GBN);
}

// out-projection
__global__ void __launch_bounds__(256, 3)
mma_gemm_o_kernel(const __nv_bfloat16* __restrict__ ah, const __nv_bfloat16* __restrict__ al,
                  const __nv_bfloat16* __restrict__ w3h, const __nv_bfloat16* __restrict__ w3l,
                  const float* __restrict__ b_o, float* __restrict__ out)
{
    extern __shared__ char smraw[];
    const unsigned sb = smem_u32(smraw);
    gemm_body(sb, ah, al, w3h, w3l, b_o, out, nullptr, nullptr, 1, 1.0f,
              blockIdx.y * GBM, blockIdx.x * GBN);
}

// ---------------- Flash attention, split-KV x3 ----------------
#define QSTR 144
#define F_oQh 0
#define F_oQl 18432
#define KV_BASE 36864
#define KV_STAGE 36864
#define KV_oKh 0
#define KV_oKl 9216
#define KV_oVh 18432
#define KV_oVl 27648
#define SMEM_FLASH (KV_BASE + 2 * KV_STAGE)   // 110592

__global__ void __launch_bounds__(256)
flash_mma_kernel(const __nv_bfloat16* __restrict__ Qh, const __nv_bfloat16* __restrict__ Ql,
                 const __nv_bfloat16* __restrict__ Kh, const __nv_bfloat16* __restrict__ Kl,
                 const __nv_bfloat16* __restrict__ Vh, const __nv_bfloat16* __restrict__ Vl)
{
    extern __shared__ char smf[];
    const unsigned sb = smem_u32(smf);
    const int tid  = threadIdx.x;
    const int lane = tid & 31;
    const int wid  = tid >> 5;
    const int bh   = blockIdx.y;
    const int q0   = blockIdx.x * 128;
    const int split = blockIdx.z;

    const size_t qoff = ((size_t)bh * SEQ + q0) * HDIM;
    const size_t koff = (size_t)bh * SEQ * HDIM;
    const __nv_bfloat16* pQh = Qh + qoff;
    const __nv_bfloat16* pQl = Ql + qoff;
    const __nv_bfloat16* pKh = Kh + koff;
    const __nv_bfloat16* pKl = Kl + koff;
    const __nv_bfloat16* pVh = Vh + koff;
    const __nv_bfloat16* pVl = Vl + koff;

#pragma unroll
    for (int i = 0; i < 4; i++) {
        int task = tid + i * 256;
        int r = task >> 3, c = task & 7;
        cp16(sb + F_oQh + r * QSTR + c * 16, pQh + (size_t)r * HDIM + c * 8);
        cp16(sb + F_oQl + r * QSTR + c * 16, pQl + (size_t)r * HDIM + c * 8);
    }
    cp_commit();

    auto load_kv = [&](int kt, int s) {
        const unsigned st = sb + KV_BASE + s * KV_STAGE;
        const int k0 = kt * 64;
#pragma unroll
        for (int i = 0; i < 2; i++) {
            int task = tid + i * 256;
            int r = task >> 3, c = task & 7;
            size_t go = (size_t)(k0 + r) * HDIM + c * 8;
            unsigned so = r * QSTR + c * 16;
            cp16(st + KV_oKh + so, pKh + go);
            cp16(st + KV_oKl + so, pKl + go);
            cp16(st + KV_oVh + so, pVh + go);
            cp16(st + KV_oVl + so, pVl + go);
        }
        cp_commit();
    };

    const int g  = lane >> 2;
    const int tg = lane & 3;
    const unsigned aAddr = sb + (unsigned)((wid * 16 + ((lane >> 3) & 1) * 8 + (lane & 7)) * QSTR
                                           + (lane >> 4) * 16);
    const unsigned kRel = (unsigned)((((lane >> 4) & 1) * 8 + (lane & 7)) * QSTR
                                     + ((lane >> 3) & 1) * 16);
    const unsigned vRel = (unsigned)((((lane >> 3) & 1) * 8 + (lane & 7)) * QSTR
                                     + (lane >> 4) * 16);

    float m0 = -INFINITY, m1 = -INFINITY, l0 = 0.f, l1 = 0.f;
    float o[8][4];
#pragma unroll
    for (int nf = 0; nf < 8; nf++)
#pragma unroll
        for (int j = 0; j < 4; j++) o[nf][j] = 0.f;

    // splits: 11 / 11 / 10 KV tiles
    const int kt0 = split * 11;
    const int kt1 = (split == 2) ? 32 : kt0 + 11;
    load_kv(kt0, 0);

    for (int kt = kt0; kt < kt1; kt++) {
        const int s = (kt - kt0) & 1;            // stage parity RELATIVE to split start
        if (kt + 1 < kt1) {
            load_kv(kt + 1, s ^ 1);
            cp_wait<1>();
        } else {
            cp_wait<0>();
        }
        __syncthreads();

        const unsigned stK = sb + KV_BASE + s * KV_STAGE;

        float sc[8][4];
#pragma unroll
        for (int nf = 0; nf < 8; nf++)
#pragma unroll
            for (int j = 0; j < 4; j++) sc[nf][j] = 0.f;

#pragma unroll
        for (int ks = 0; ks < 4; ks++) {
            unsigned qhf[4], qlf[4];
            ldx4(qhf, aAddr + F_oQh + ks * 32);
            ldx4(qlf, aAddr + F_oQl + ks * 32);
#pragma unroll
            for (int p = 0; p < 4; p++) {
                unsigned khf[4], klf[4];
                ldx4(khf, stK + KV_oKh + kRel + p * (16 * QSTR) + ks * 32);
                ldx4(klf, stK + KV_oKl + kRel + p * (16 * QSTR) + ks * 32);
                mma16816(sc[2 * p],     qhf, &khf[0]);
                mma16816(sc[2 * p],     qhf, &klf[0]);
                mma16816(sc[2 * p],     qlf, &khf[0]);
                mma16816(sc[2 * p + 1], qhf, &khf[2]);
                mma16816(sc[2 * p + 1], qhf, &klf[2]);
                mma16816(sc[2 * p + 1], qlf, &khf[2]);
            }
        }

        float pm0 = sc[0][0], pm1 = sc[0][2];
#pragma unroll
        for (int nf = 0; nf < 8; nf++) {
            pm0 = fmaxf(pm0, fmaxf(sc[nf][0], sc[nf][1]));
            pm1 = fmaxf(pm1, fmaxf(sc[nf][2], sc[nf][3]));
        }
        pm0 = fmaxf(pm0, __shfl_xor_sync(0xffffffffu, pm0, 1, 4));
        pm0 = fmaxf(pm0, __shfl_xor_sync(0xffffffffu, pm0, 2, 4));
        pm1 = fmaxf(pm1, __shfl_xor_sync(0xffffffffu, pm1, 1, 4));
        pm1 = fmaxf(pm1, __shfl_xor_sync(0xffffffffu, pm1, 2, 4));
        const float mn0 = fmaxf(m0, pm0);
        const float mn1 = fmaxf(m1, pm1);
        const float al0 = __expf(m0 - mn0);
        const float al1 = __expf(m1 - mn1);
        m0 = mn0; m1 = mn1;
        float ps0 = 0.f, ps1 = 0.f;
#pragma unroll
        for (int nf = 0; nf < 8; nf++) {
            sc[nf][0] = __expf(sc[nf][0] - mn0);
            sc[nf][1] = __expf(sc[nf][1] - mn0);
            sc[nf][2] = __expf(sc[nf][2] - mn1);
            sc[nf][3] = __expf(sc[nf][3] - mn1);
            ps0 += sc[nf][0] + sc[nf][1];
            ps1 += sc[nf][2] + sc[nf][3];
        }
        ps0 += __shfl_xor_sync(0xffffffffu, ps0, 1, 4);
        ps0 += __shfl_xor_sync(0xffffffffu, ps0, 2, 4);
        ps1 += __shfl_xor_sync(0xffffffffu, ps1, 1, 4);
        ps1 += __shfl_xor_sync(0xffffffffu, ps1, 2, 4);
        l0 = l0 * al0 + ps0;
        l1 = l1 * al1 + ps1;
#pragma unroll
        for (int nf = 0; nf < 8; nf++) {
            o[nf][0] *= al0; o[nf][1] *= al0;
            o[nf][2] *= al1; o[nf][3] *= al1;
        }

#pragma unroll
        for (int kb = 0; kb < 4; kb++) {
            float r0, r1, r2, r3, r4, r5, r6, r7;
            unsigned pa_h[4], pa_l[4];
            pa_h[0] = pack_hi_res(sc[2 * kb][0],     sc[2 * kb][1],     r0, r1);
            pa_h[1] = pack_hi_res(sc[2 * kb][2],     sc[2 * kb][3],     r2, r3);
            pa_h[2] = pack_hi_res(sc[2 * kb + 1][0], sc[2 * kb + 1][1], r4, r5);
            pa_h[3] = pack_hi_res(sc[2 * kb + 1][2], sc[2 * kb + 1][3], r6, r7);
            pa_l[0] = pack_bf2(r0, r1);
            pa_l[1] = pack_bf2(r2, r3);
            pa_l[2] = pack_bf2(r4, r5);
            pa_l[3] = pack_bf2(r6, r7);
#pragma unroll
            for (int du = 0; du < 4; du++) {
                unsigned vhf[4], vlf[4];
                ldx4t(vhf, stK + KV_oVh + vRel + kb * (16 * QSTR) + du * 32);
                ldx4t(vlf, stK + KV_oVl + vRel + kb * (16 * QSTR) + du * 32);
                mma16816(o[du * 2],     pa_h, &vhf[0]);
                mma16816(o[du * 2],     pa_h, &vlf[0]);
                mma16816(o[du * 2],     pa_l, &vhf[0]);
                mma16816(o[du * 2 + 1], pa_h, &vhf[2]);
                mma16816(o[du * 2 + 1], pa_h, &vlf[2]);
                mma16816(o[du * 2 + 1], pa_l, &vhf[2]);
            }
        }
        __syncthreads();
    }

    // ---- store unnormalized partials + (m, l) ----
    const int r0 = q0 + wid * 16 + g;
    const size_t prow = (size_t)(split * BH + bh) * SEQ + r0;
    float* Op0 = &g_Op[prow * HDIM];
    float* Op1 = &g_Op[(prow + 8) * HDIM];
#pragma unroll
    for (int nf = 0; nf < 8; nf++) {
        const int e = nf * 8 + tg * 2;
        *(float2*)&Op0[e] = make_float2(o[nf][0], o[nf][1]);
        *(float2*)&Op1[e] = make_float2(o[nf][2], o[nf][3]);
    }
    if (tg == 0) {
        g_Mp[prow] = m0;     g_Lp[prow] = l0;
        g_Mp[prow + 8] = m1; g_Lp[prow + 8] = l1;
    }
}

// ---------------- split-KV merge: combine NSPLIT partials -> bf16 hi/lo A ----------------
__global__ void __launch_bounds__(256)
merge_kernel(__nv_bfloat16* __restrict__ Ahi, __nv_bfloat16* __restrict__ Alo)
{
    int t = blockIdx.x * 256 + threadIdx.x;     // BHS * 16 tasks
    if (t >= BHS * (HDIM / 4)) return;
    const int c4  = t & 15;
    const size_t row = (size_t)(t >> 4);        // [0, BHS)
    const int bh = (int)(row / SEQ);
    const int s  = (int)(row - (size_t)bh * SEQ);

    float mm[NSPLIT], ll[NSPLIT];
    float M = -INFINITY;
#pragma unroll
    for (int i = 0; i < NSPLIT; i++) {
        mm[i] = g_Mp[(size_t)i * BHS + row];
        ll[i] = g_Lp[(size_t)i * BHS + row];
        M = fmaxf(M, mm[i]);
    }
    float w[NSPLIT], denom = 0.f;
#pragma unroll
    for (int i = 0; i < NSPLIT; i++) {
        w[i] = __expf(mm[i] - M);
        denom += ll[i] * w[i];
    }
    float inv = 1.f / denom;
#pragma unroll
    for (int i = 0; i < NSPLIT; i++) w[i] *= inv;

    float r0 = 0.f, r1 = 0.f, r2 = 0.f, r3 = 0.f;
#pragma unroll
    for (int i = 0; i < NSPLIT; i++) {
        float4 a = *(const float4*)&g_Op[((size_t)i * BHS + row) * HDIM + c4 * 4];
        r0 += a.x * w[i];
        r1 += a.y * w[i];
        r2 += a.z * w[i];
        r3 += a.w * w[i];
    }

    const int bb = bh / HEADS;
    const int h  = bh % HEADS;
    const size_t dst = ((size_t)(bb * SEQ + s)) * EMBED + h * HDIM + c4 * 4;
    float x0, x1, x2, x3;
    unsigned h0 = pack_hi_res(r0, r1, x0, x1);
    unsigned h1 = pack_hi_res(r2, r3, x2, x3);
    *(unsigned*)&Ahi[dst]     = h0;
    *(unsigned*)&Ahi[dst + 2] = h1;
    *(unsigned*)&Alo[dst]     = pack_bf2(x0, x1);
    *(unsigned*)&Alo[dst + 2] = pack_bf2(x2, x3);
}

// ---------------- driver ----------------
extern "C" void kernel_launch(void* const* d_in, const int* in_sizes, int n_in,
                              void* d_out, int out_size)
{
    const float *x, *w_q, *b_q, *w_k, *b_k, *w_v, *b_v, *w_o, *b_o;
    if (n_in == 9 && in_sizes[0] == EMBED && in_sizes[8] == NX) {
        b_k = (const float*)d_in[0]; b_o = (const float*)d_in[1];
        b_q = (const float*)d_in[2]; b_v = (const float*)d_in[3];
        w_k = (const float*)d_in[4]; w_o = (const float*)d_in[5];
        w_q = (const float*)d_in[6]; w_v = (const float*)d_in[7];
        x   = (const float*)d_in[8];
    } else if (n_in == 9 && in_sizes[0] == NX && in_sizes[2] == NW) {
        x   = (const float*)d_in[0];
        w_q = (const float*)d_in[1]; w_k = (const float*)d_in[2];
        w_v = (const float*)d_in[3]; w_o = (const float*)d_in[4];
        b_q = (const float*)d_in[5]; b_k = (const float*)d_in[6];
        b_v = (const float*)d_in[7]; b_o = (const float*)d_in[8];
    } else {
        x   = (const float*)d_in[0];
        w_q = (const float*)d_in[1]; b_q = (const float*)d_in[2];
        w_k = (const float*)d_in[3]; b_k = (const float*)d_in[4];
        w_v = (const float*)d_in[5]; b_v = (const float*)d_in[6];
        w_o = (const float*)d_in[7]; b_o = (const float*)d_in[8];
    }
    float* out = (float*)d_out;

    __nv_bfloat16 *xh, *xl, *w0h, *w0l, *w1h, *w1l, *w2h, *w2l, *w3h, *w3l;
    __nv_bfloat16 *qh, *ql, *kh, *kl, *vh, *vl, *ah, *al;
    cudaGetSymbolAddress((void**)&xh,  g_Xhi);  cudaGetSymbolAddress((void**)&xl,  g_Xlo);
    cudaGetSymbolAddress((void**)&w0h, g_W0hi); cudaGetSymbolAddress((void**)&w0l, g_W0lo);
    cudaGetSymbolAddress((void**)&w1h, g_W1hi); cudaGetSymbolAddress((void**)&w1l, g_W1lo);
    cudaGetSymbolAddress((void**)&w2h, g_W2hi); cudaGetSymbolAddress((void**)&w2l, g_W2lo);
    cudaGetSymbolAddress((void**)&w3h, g_W3hi); cudaGetSymbolAddress((void**)&w3l, g_W3lo);
    cudaGetSymbolAddress((void**)&qh,  g_Qh);   cudaGetSymbolAddress((void**)&ql,  g_Ql);
    cudaGetSymbolAddress((void**)&kh,  g_Kh);   cudaGetSymbolAddress((void**)&kl,  g_Kl);
    cudaGetSymbolAddress((void**)&vh,  g_Vh);   cudaGetSymbolAddress((void**)&vl,  g_Vl);
    cudaGetSymbolAddress((void**)&ah,  g_Ahi);  cudaGetSymbolAddress((void**)&al,  g_Alo);

    cudaFuncSetAttribute(mma_gemm_qkv_kernel,
                         cudaFuncAttributeMaxDynamicSharedMemorySize, SMEM_GEMM);
    cudaFuncSetAttribute(mma_gemm_o_kernel,
                         cudaFuncAttributeMaxDynamicSharedMemorySize, SMEM_GEMM);
    cudaFuncSetAttribute(flash_mma_kernel,
                         cudaFuncAttributeMaxDynamicSharedMemorySize, SMEM_FLASH);

    convert_all_kernel<<<(CONV_TASKS + 255) / 256, 256>>>(
        x, w_q, w_k, w_v, w_o,
        xh, xl, w0h, w0l, w1h, w1l, w2h, w2l, w3h, w3l);

    dim3 qkvgrid(3 * (EMBED / GBN), MROWS / GBM);   // (36, 32)
    mma_gemm_qkv_kernel<<<qkvgrid, 256, SMEM_GEMM>>>(
        xh, xl, w0h, w0l, w1h, w1l, w2h, w2l,
        b_q, b_k, b_v, qh, ql, kh, kl, vh, vl);

    dim3 agrid(SEQ / 128, BH, NSPLIT);              // (16, 24, 3)
    flash_mma_kernel<<<agrid, 256, SMEM_FLASH>>>(qh, ql, kh, kl, vh, vl);

    merge_kernel<<<(BHS * (HDIM / 4) + 255) / 256, 256>>>(ah, al);

    dim3 ogrid(EMBED / GBN, MROWS / GBM);           // (12, 32)
    mma_gemm_o_kernel<<<ogrid, 256, SMEM_GEMM>>>(ah, al, w3h, w3l, b_o, out);
}

// round 11
// speedup vs baseline: 3.6756x; 1.0300x over previous
#include <cuda_runtime.h>
#include <cuda_bf16.h>
#include <math.h>

#define EMBED 768
#define HEADS 12
#define HDIM  64
#define BATCH 2
#define SEQ   2048
#define MROWS (BATCH * SEQ)      // 4096
#define BH    (BATCH * HEADS)    // 24
#define NX (MROWS * EMBED)
#define NW (EMBED * EMBED)
#define BHS (BH * SEQ)           // 49152
#define NSPLIT 3

// ---------------- scratch ----------------
__device__ __nv_bfloat16 g_Xhi[NX], g_Xlo[NX];
__device__ __nv_bfloat16 g_W0hi[NW], g_W0lo[NW];
__device__ __nv_bfloat16 g_W1hi[NW], g_W1lo[NW];
__device__ __nv_bfloat16 g_W2hi[NW], g_W2lo[NW];
__device__ __nv_bfloat16 g_W3hi[NW], g_W3lo[NW];
__device__ __nv_bfloat16 g_Qh[NX], g_Ql[NX];
__device__ __nv_bfloat16 g_Kh[NX], g_Kl[NX];
__device__ __nv_bfloat16 g_Vh[NX], g_Vl[NX];
__device__ __nv_bfloat16 g_Ahi[NX], g_Alo[NX];
// split-KV partials
__device__ float g_Op[NSPLIT * BHS * HDIM];
__device__ float g_Mp[NSPLIT * BHS];
__device__ float g_Lp[NSPLIT * BHS];

// ---------------- PTX helpers (family-portable sm_80+) ----------------
__device__ __forceinline__ unsigned smem_u32(const void* p) {
    unsigned a;
    asm("{ .reg .u64 t; cvta.to.shared.u64 t, %1; cvt.u32.u64 %0, t; }" : "=r"(a) : "l"(p));
    return a;
}
__device__ __forceinline__ void cp16(unsigned s, const void* g) {
    asm volatile("cp.async.cg.shared.global [%0], [%1], 16;" :: "r"(s), "l"(g));
}
__device__ __forceinline__ void cp_commit() { asm volatile("cp.async.commit_group;" ::: "memory"); }
template <int N> __device__ __forceinline__ void cp_wait() {
    asm volatile("cp.async.wait_group %0;" :: "n"(N) : "memory");
}
__device__ __forceinline__ void ldx4(unsigned* r, unsigned addr) {
    asm volatile("ldmatrix.sync.aligned.m8n8.x4.shared.b16 {%0,%1,%2,%3}, [%4];"
        : "=r"(r[0]), "=r"(r[1]), "=r"(r[2]), "=r"(r[3]) : "r"(addr));
}
__device__ __forceinline__ void ldx4t(unsigned* r, unsigned addr) {
    asm volatile("ldmatrix.sync.aligned.m8n8.x4.trans.shared.b16 {%0,%1,%2,%3}, [%4];"
        : "=r"(r[0]), "=r"(r[1]), "=r"(r[2]), "=r"(r[3]) : "r"(addr));
}
__device__ __forceinline__ void mma16816(float* d, const unsigned* a, const unsigned* b) {
    asm volatile(
        "mma.sync.aligned.m16n8k16.row.col.f32.bf16.bf16.f32 "
        "{%0,%1,%2,%3}, {%4,%5,%6,%7}, {%8,%9}, {%0,%1,%2,%3};"
        : "+f"(d[0]), "+f"(d[1]), "+f"(d[2]), "+f"(d[3])
        : "r"(a[0]), "r"(a[1]), "r"(a[2]), "r"(a[3]), "r"(b[0]), "r"(b[1]));
}
__device__ __forceinline__ unsigned pack_bf2(float a, float b) {
    __nv_bfloat162 t = __float22bfloat162_rn(make_float2(a, b));
    return *(unsigned*)&t;
}
__device__ __forceinline__ unsigned pack_hi_res(float a, float b, float& ra, float& rb) {
    __nv_bfloat162 t = __float22bfloat162_rn(make_float2(a, b));
    ra = a - __bfloat162float(t.x);
    rb = b - __bfloat162float(t.y);
    return *(unsigned*)&t;
}

// ---------------- fused fp32 -> bf16 hi/lo split (all 5 inputs) ----------------
struct alignas(8) B4 { __nv_bfloat16 v[4]; };
#define CONV_TASKS ((NX + 4 * NW) / 8)

__global__ void __launch_bounds__(256)
convert_all_kernel(const float* __restrict__ x,
                   const float* __restrict__ w0, const float* __restrict__ w1,
                   const float* __restrict__ w2, const float* __restrict__ w3,
                   __nv_bfloat16* xh, __nv_bfloat16* xl,
                   __nv_bfloat16* w0h, __nv_bfloat16* w0l,
                   __nv_bfloat16* w1h, __nv_bfloat16* w1l,
                   __nv_bfloat16* w2h, __nv_bfloat16* w2l,
                   __nv_bfloat16* w3h, __nv_bfloat16* w3l)
{
    long long t = (long long)blockIdx.x * 256 + threadIdx.x;
    if (t >= CONV_TASKS) return;
    long long i = t * 8;
    const float* src;
    __nv_bfloat16 *hi, *lo;
    long long off;
    if (i < NX) { src = x; hi = xh; lo = xl; off = i; }
    else {
        long long j = i - NX;
        int w = (int)(j / NW);
        off = j - (long long)w * NW;
        if      (w == 0) { src = w0; hi = w0h; lo = w0l; }
        else if (w == 1) { src = w1; hi = w1h; lo = w1l; }
        else if (w == 2) { src = w2; hi = w2h; lo = w2l; }
        else             { src = w3; hi = w3h; lo = w3l; }
    }
#pragma unroll
    for (int half = 0; half < 2; half++) {
        float4 v = *(const float4*)&src[off + half * 4];
        B4 h, l;
        float f[4] = {v.x, v.y, v.z, v.w};
#pragma unroll
        for (int j = 0; j < 4; j++) {
            h.v[j] = __float2bfloat16(f[j]);
            l.v[j] = __float2bfloat16(f[j] - __bfloat162float(h.v[j]));
        }
        *(B4*)&hi[off + half * 4] = h;
        *(B4*)&lo[off + half * 4] = l;
    }
}

// ---------------- HMMA GEMM body: Y = X @ W^T + b  (bf16x3) ----------------
#define GBM 128
#define GBN 64
#define GBK 32
#define KITERS (EMBED / GBK)
#define ASTR 80
#define A_SZ (128 * ASTR)
#define B_SZ (64 * ASTR)
#define STAGE (2 * A_SZ + 2 * B_SZ)
#define SMEM_GEMM (2 * STAGE)

__device__ __forceinline__ void
gemm_body(unsigned sb,
          const __nv_bfloat16* __restrict__ Ahi, const __nv_bfloat16* __restrict__ Alo,
          const __nv_bfloat16* __restrict__ Bhi, const __nv_bfloat16* __restrict__ Blo,
          const float* __restrict__ bias, float* __restrict__ Yf,
          __nv_bfloat16* __restrict__ Yhi, __nv_bfloat16* __restrict__ Ylo,
          int mode, float scale, int m0, int n0)
{
    const int tid  = threadIdx.x;
    const int lane = tid & 31;
    const int wid  = tid >> 5;
    const int warpM = wid & 3;
    const int warpN = wid >> 2;

    auto sA_hi = [&](int s) { return sb + s * STAGE; };
    auto sA_lo = [&](int s) { return sb + s * STAGE + A_SZ; };
    auto sB_hi = [&](int s) { return sb + s * STAGE + 2 * A_SZ; };
    auto sB_lo = [&](int s) { return sb + s * STAGE + 2 * A_SZ + B_SZ; };

    const int ar0 = (tid * 2) >> 2, ac0 = (tid * 2) & 3;
    const int ar1 = (tid * 2 + 1) >> 2, ac1 = (tid * 2 + 1) & 3;
    const int br = tid >> 2, bc = tid & 3;

    auto load_stage = [&](int kt, int s) {
        const int k0 = kt * GBK;
        const __nv_bfloat16* pah = Ahi + (size_t)m0 * EMBED + k0;
        const __nv_bfloat16* pal = Alo + (size_t)m0 * EMBED + k0;
        const __nv_bfloat16* pbh = Bhi + (size_t)n0 * EMBED + k0;
        const __nv_bfloat16* pbl = Blo + (size_t)n0 * EMBED + k0;
        cp16(sA_hi(s) + ar0 * ASTR + ac0 * 16, pah + (size_t)ar0 * EMBED + ac0 * 8);
        cp16(sA_hi(s) + ar1 * ASTR + ac1 * 16, pah + (size_t)ar1 * EMBED + ac1 * 8);
        cp16(sA_lo(s) + ar0 * ASTR + ac0 * 16, pal + (size_t)ar0 * EMBED + ac0 * 8);
        cp16(sA_lo(s) + ar1 * ASTR + ac1 * 16, pal + (size_t)ar1 * EMBED + ac1 * 8);
        cp16(sB_hi(s) + br * ASTR + bc * 16,   pbh + (size_t)br * EMBED + bc * 8);
        cp16(sB_lo(s) + br * ASTR + bc * 16,   pbl + (size_t)br * EMBED + bc * 8);
        cp_commit();
    };

    const unsigned aOff = (unsigned)((warpM * 32 + ((lane >> 3) & 1) * 8 + (lane & 7)) * ASTR
                                     + (lane >> 4) * 16);
    const unsigned bOff = (unsigned)((warpN * 32 + ((lane >> 4) & 1) * 8 + (lane & 7)) * ASTR
                                     + ((lane >> 3) & 1) * 16);

    float acc[2][4][4];
#pragma unroll
    for (int mt = 0; mt < 2; mt++)
#pragma unroll
        for (int nt = 0; nt < 4; nt++)
#pragma unroll
            for (int j = 0; j < 4; j++) acc[mt][nt][j] = 0.f;

    load_stage(0, 0);

    for (int kt = 0; kt < KITERS; kt++) {
        const int s = kt & 1;
        // wait for stage s data (this thread's portion), then barrier:
        // barrier also guarantees every thread is done computing on s^1,
        // so issuing load(kt+1) into s^1 after it is safe. ONE sync per tile.
        cp_wait<0>();
        __syncthreads();
        if (kt + 1 < KITERS) load_stage(kt + 1, s ^ 1);

#pragma unroll
        for (int ks = 0; ks < 2; ks++) {
            unsigned a_h[2][4], a_l[2][4], b_h[2][4], b_l[2][4];
#pragma unroll
            for (int mt = 0; mt < 2; mt++) {
                ldx4(a_h[mt], sA_hi(s) + aOff + mt * (16 * ASTR) + ks * 32);
                ldx4(a_l[mt], sA_lo(s) + aOff + mt * (16 * ASTR) + ks * 32);
            }
#pragma unroll
            for (int p = 0; p < 2; p++) {
                ldx4(b_h[p], sB_hi(s) + bOff + p * (16 * ASTR) + ks * 32);
                ldx4(b_l[p], sB_lo(s) + bOff + p * (16 * ASTR) + ks * 32);
            }
#pragma unroll
            for (int mt = 0; mt < 2; mt++)
#pragma unroll
                for (int p = 0; p < 2; p++)
#pragma unroll
                    for (int j = 0; j < 2; j++) {
                        const int nt = p * 2 + j;
                        mma16816(acc[mt][nt], a_h[mt], &b_h[p][j * 2]);
                        mma16816(acc[mt][nt], a_h[mt], &b_l[p][j * 2]);
                        mma16816(acc[mt][nt], a_l[mt], &b_h[p][j * 2]);
                    }
        }
    }

    const int g  = lane >> 2;
    const int tg = lane & 3;
#pragma unroll
    for (int mt = 0; mt < 2; mt++) {
#pragma unroll
        for (int nt = 0; nt < 4; nt++) {
            const int nl = warpN * 32 + nt * 8 + tg * 2;
            const int n  = n0 + nl;
            float2 bv = *(const float2*)&bias[n];
#pragma unroll
            for (int half = 0; half < 2; half++) {
                const int ml = warpM * 32 + mt * 16 + g + half * 8;
                const int m  = m0 + ml;
                float c0 = acc[mt][nt][half * 2 + 0] + bv.x;
                float c1 = acc[mt][nt][half * 2 + 1] + bv.y;
                if (mode == 0) {
                    const int h = n0 >> 6;
                    const int bb = m >> 11;
                    const int ss = m & 2047;
                    float v0 = c0 * scale, v1 = c1 * scale;
                    float r0, r1;
                    unsigned hp = pack_hi_res(v0, v1, r0, r1);
                    unsigned lp = pack_bf2(r0, r1);
                    size_t idx = ((size_t)(bb * HEADS + h) * SEQ + ss) * HDIM + (n & 63);
                    *(unsigned*)&Yhi[idx] = hp;
                    *(unsigned*)&Ylo[idx] = lp;
                } else {
                    *(float2*)&Yf[(size_t)m * EMBED + n] = make_float2(c0, c1);
                }
            }
        }
    }
}

// fused Q/K/V projection: proj = blockIdx.x / 12
__global__ void __launch_bounds__(256, 3)
mma_gemm_qkv_kernel(const __nv_bfloat16* __restrict__ xh, const __nv_bfloat16* __restrict__ xl,
                    const __nv_bfloat16* __restrict__ w0h, const __nv_bfloat16* __restrict__ w0l,
                    const __nv_bfloat16* __restrict__ w1h, const __nv_bfloat16* __restrict__ w1l,
                    const __nv_bfloat16* __restrict__ w2h, const __nv_bfloat16* __restrict__ w2l,
                    const float* __restrict__ b_q, const float* __restrict__ b_k,
                    const float* __restrict__ b_v,
                    __nv_bfloat16* qh, __nv_bfloat16* ql,
                    __nv_bfloat16* kh, __nv_bfloat16* kl,
                    __nv_bfloat16* vh, __nv_bfloat16* vl)
{
    extern __shared__ char smraw[];
    const unsigned sb = smem_u32(smraw);
    const int pj   = blockIdx.x / 12;
    const int nblk = blockIdx.x % 12;
    const __nv_bfloat16 *Bh, *Bl;
    const float* bias;
    __nv_bfloat16 *Yh, *Yl;
    float scale;
    if (pj == 0)      { Bh = w0h; Bl = w0l; bias = b_q; Yh = qh; Yl = ql; scale = 0.125f; }
    else if (pj == 1) { Bh = w1h; Bl = w1l; bias = b_k; Yh = kh; Yl = kl; scale = 1.0f; }
    else              { Bh = w2h; Bl = w2l; bias = b_v; Yh = vh; Yl = vl; scale = 1.0f; }
    gemm_body(sb, xh, xl, Bh, Bl, bias, nullptr, Yh, Yl, 0, scale,
              blockIdx.y * GBM, nblk * GBN);
}

// out-projection
__global__ void __launch_bounds__(256, 3)
mma_gemm_o_kernel(const __nv_bfloat16* __restrict__ ah, const __nv_bfloat16* __restrict__ al,
                  const __nv_bfloat16* __restrict__ w3h, const __nv_bfloat16* __restrict__ w3l,
                  const float* __restrict__ b_o, float* __restrict__ out)
{
    extern __shared__ char smraw[];
    const unsigned sb = smem_u32(smraw);
    gemm_body(sb, ah, al, w3h, w3l, b_o, out, nullptr, nullptr, 1, 1.0f,
              blockIdx.y * GBM, blockIdx.x * GBN);
}

// ---------------- Flash attention, split-KV x3, single-sync mainloop ----------------
#define QSTR 144
#define F_oQh 0
#define F_oQl 18432
#define KV_BASE 36864
#define KV_STAGE 36864
#define KV_oKh 0
#define KV_oKl 9216
#define KV_oVh 18432
#define KV_oVl 27648
#define SMEM_FLASH (KV_BASE + 2 * KV_STAGE)   // 110592

__global__ void __launch_bounds__(256)
flash_mma_kernel(const __nv_bfloat16* __restrict__ Qh, const __nv_bfloat16* __restrict__ Ql,
                 const __nv_bfloat16* __restrict__ Kh, const __nv_bfloat16* __restrict__ Kl,
                 const __nv_bfloat16* __restrict__ Vh, const __nv_bfloat16* __restrict__ Vl)
{
    extern __shared__ char smf[];
    const unsigned sb = smem_u32(smf);
    const int tid  = threadIdx.x;
    const int lane = tid & 31;
    const int wid  = tid >> 5;
    const int bh   = blockIdx.y;
    const int q0   = blockIdx.x * 128;
    const int split = blockIdx.z;

    const size_t qoff = ((size_t)bh * SEQ + q0) * HDIM;
    const size_t koff = (size_t)bh * SEQ * HDIM;
    const __nv_bfloat16* pQh = Qh + qoff;
    const __nv_bfloat16* pQl = Ql + qoff;
    const __nv_bfloat16* pKh = Kh + koff;
    const __nv_bfloat16* pKl = Kl + koff;
    const __nv_bfloat16* pVh = Vh + koff;
    const __nv_bfloat16* pVl = Vl + koff;

#pragma unroll
    for (int i = 0; i < 4; i++) {
        int task = tid + i * 256;
        int r = task >> 3, c = task & 7;
        cp16(sb + F_oQh + r * QSTR + c * 16, pQh + (size_t)r * HDIM + c * 8);
        cp16(sb + F_oQl + r * QSTR + c * 16, pQl + (size_t)r * HDIM + c * 8);
    }
    cp_commit();

    auto load_kv = [&](int kt, int s) {
        const unsigned st = sb + KV_BASE + s * KV_STAGE;
        const int k0 = kt * 64;
#pragma unroll
        for (int i = 0; i < 2; i++) {
            int task = tid + i * 256;
            int r = task >> 3, c = task & 7;
            size_t go = (size_t)(k0 + r) * HDIM + c * 8;
            unsigned so = r * QSTR + c * 16;
            cp16(st + KV_oKh + so, pKh + go);
            cp16(st + KV_oKl + so, pKl + go);
            cp16(st + KV_oVh + so, pVh + go);
            cp16(st + KV_oVl + so, pVl + go);
        }
        cp_commit();
    };

    const int g  = lane >> 2;
    const int tg = lane & 3;
    const unsigned aAddr = sb + (unsigned)((wid * 16 + ((lane >> 3) & 1) * 8 + (lane & 7)) * QSTR
                                           + (lane >> 4) * 16);
    const unsigned kRel = (unsigned)((((lane >> 4) & 1) * 8 + (lane & 7)) * QSTR
                                     + ((lane >> 3) & 1) * 16);
    const unsigned vRel = (unsigned)((((lane >> 3) & 1) * 8 + (lane & 7)) * QSTR
                                     + (lane >> 4) * 16);

    float m0 = -INFINITY, m1 = -INFINITY, l0 = 0.f, l1 = 0.f;
    float o[8][4];
#pragma unroll
    for (int nf = 0; nf < 8; nf++)
#pragma unroll
        for (int j = 0; j < 4; j++) o[nf][j] = 0.f;

    // splits: 11 / 11 / 10 KV tiles
    const int kt0 = split * 11;
    const int kt1 = (split == 2) ? 32 : kt0 + 11;
    load_kv(kt0, 0);

    for (int kt = kt0; kt < kt1; kt++) {
        const int s = (kt - kt0) & 1;   // stage parity relative to split start
        // single barrier per tile: wait own async portion, then barrier makes
        // (a) stage s fully populated and (b) stage s^1 free to overwrite.
        cp_wait<0>();
        __syncthreads();
        if (kt + 1 < kt1) load_kv(kt + 1, s ^ 1);

        const unsigned stK = sb + KV_BASE + s * KV_STAGE;

        float sc[8][4];
#pragma unroll
        for (int nf = 0; nf < 8; nf++)
#pragma unroll
            for (int j = 0; j < 4; j++) sc[nf][j] = 0.f;

#pragma unroll
        for (int ks = 0; ks < 4; ks++) {
            unsigned qhf[4], qlf[4];
            ldx4(qhf, aAddr + F_oQh + ks * 32);
            ldx4(qlf, aAddr + F_oQl + ks * 32);
#pragma unroll
            for (int p = 0; p < 4; p++) {
                unsigned khf[4], klf[4];
                ldx4(khf, stK + KV_oKh + kRel + p * (16 * QSTR) + ks * 32);
                ldx4(klf, stK + KV_oKl + kRel + p * (16 * QSTR) + ks * 32);
                mma16816(sc[2 * p],     qhf, &khf[0]);
                mma16816(sc[2 * p],     qhf, &klf[0]);
                mma16816(sc[2 * p],     qlf, &khf[0]);
                mma16816(sc[2 * p + 1], qhf, &khf[2]);
                mma16816(sc[2 * p + 1], qhf, &klf[2]);
                mma16816(sc[2 * p + 1], qlf, &khf[2]);
            }
        }

        float pm0 = sc[0][0], pm1 = sc[0][2];
#pragma unroll
        for (int nf = 0; nf < 8; nf++) {
            pm0 = fmaxf(pm0, fmaxf(sc[nf][0], sc[nf][1]));
            pm1 = fmaxf(pm1, fmaxf(sc[nf][2], sc[nf][3]));
        }
        pm0 = fmaxf(pm0, __shfl_xor_sync(0xffffffffu, pm0, 1, 4));
        pm0 = fmaxf(pm0, __shfl_xor_sync(0xffffffffu, pm0, 2, 4));
        pm1 = fmaxf(pm1, __shfl_xor_sync(0xffffffffu, pm1, 1, 4));
        pm1 = fmaxf(pm1, __shfl_xor_sync(0xffffffffu, pm1, 2, 4));
        const float mn0 = fmaxf(m0, pm0);
        const float mn1 = fmaxf(m1, pm1);
        const float al0 = __expf(m0 - mn0);
        const float al1 = __expf(m1 - mn1);
        m0 = mn0; m1 = mn1;
        float ps0 = 0.f, ps1 = 0.f;
#pragma unroll
        for (int nf = 0; nf < 8; nf++) {
            sc[nf][0] = __expf(sc[nf][0] - mn0);
            sc[nf][1] = __expf(sc[nf][1] - mn0);
            sc[nf][2] = __expf(sc[nf][2] - mn1);
            sc[nf][3] = __expf(sc[nf][3] - mn1);
            ps0 += sc[nf][0] + sc[nf][1];
            ps1 += sc[nf][2] + sc[nf][3];
        }
        ps0 += __shfl_xor_sync(0xffffffffu, ps0, 1, 4);
        ps0 += __shfl_xor_sync(0xffffffffu, ps0, 2, 4);
        ps1 += __shfl_xor_sync(0xffffffffu, ps1, 1, 4);
        ps1 += __shfl_xor_sync(0xffffffffu, ps1, 2, 4);
        l0 = l0 * al0 + ps0;
        l1 = l1 * al1 + ps1;
#pragma unroll
        for (int nf = 0; nf < 8; nf++) {
            o[nf][0] *= al0; o[nf][1] *= al0;
            o[nf][2] *= al1; o[nf][3] *= al1;
        }

#pragma unroll
        for (int kb = 0; kb < 4; kb++) {
            float r0, r1, r2, r3, r4, r5, r6, r7;
            unsigned pa_h[4], pa_l[4];
            pa_h[0] = pack_hi_res(sc[2 * kb][0],     sc[2 * kb][1],     r0, r1);
            pa_h[1] = pack_hi_res(sc[2 * kb][2],     sc[2 * kb][3],     r2, r3);
            pa_h[2] = pack_hi_res(sc[2 * kb + 1][0], sc[2 * kb + 1][1], r4, r5);
            pa_h[3] = pack_hi_res(sc[2 * kb + 1][2], sc[2 * kb + 1][3], r6, r7);
            pa_l[0] = pack_bf2(r0, r1);
            pa_l[1] = pack_bf2(r2, r3);
            pa_l[2] = pack_bf2(r4, r5);
            pa_l[3] = pack_bf2(r6, r7);
#pragma unroll
            for (int du = 0; du < 4; du++) {
                unsigned vhf[4], vlf[4];
                ldx4t(vhf, stK + KV_oVh + vRel + kb * (16 * QSTR) + du * 32);
                ldx4t(vlf, stK + KV_oVl + vRel + kb * (16 * QSTR) + du * 32);
                mma16816(o[du * 2],     pa_h, &vhf[0]);
                mma16816(o[du * 2],     pa_h, &vlf[0]);
                mma16816(o[du * 2],     pa_l, &vhf[0]);
                mma16816(o[du * 2 + 1], pa_h, &vhf[2]);
                mma16816(o[du * 2 + 1], pa_h, &vlf[2]);
                mma16816(o[du * 2 + 1], pa_l, &vhf[2]);
            }
        }
    }

    // ---- store unnormalized partials + (m, l) ----
    const int r0 = q0 + wid * 16 + g;
    const size_t prow = (size_t)(split * BH + bh) * SEQ + r0;
    float* Op0 = &g_Op[prow * HDIM];
    float* Op1 = &g_Op[(prow + 8) * HDIM];
#pragma unroll
    for (int nf = 0; nf < 8; nf++) {
        const int e = nf * 8 + tg * 2;
        *(float2*)&Op0[e] = make_float2(o[nf][0], o[nf][1]);
        *(float2*)&Op1[e] = make_float2(o[nf][2], o[nf][3]);
    }
    if (tg == 0) {
        g_Mp[prow] = m0;     g_Lp[prow] = l0;
        g_Mp[prow + 8] = m1; g_Lp[prow + 8] = l1;
    }
}

// ---------------- split-KV merge: combine NSPLIT partials -> bf16 hi/lo A ----------------
__global__ void __launch_bounds__(256)
merge_kernel(__nv_bfloat16* __restrict__ Ahi, __nv_bfloat16* __restrict__ Alo)
{
    int t = blockIdx.x * 256 + threadIdx.x;     // BHS * 16 tasks
    if (t >= BHS * (HDIM / 4)) return;
    const int c4  = t & 15;
    const size_t row = (size_t)(t >> 4);        // [0, BHS)
    const int bh = (int)(row / SEQ);
    const int s  = (int)(row - (size_t)bh * SEQ);

    float mm[NSPLIT], ll[NSPLIT];
    float M = -INFINITY;
#pragma unroll
    for (int i = 0; i < NSPLIT; i++) {
        mm[i] = g_Mp[(size_t)i * BHS + row];
        ll[i] = g_Lp[(size_t)i * BHS + row];
        M = fmaxf(M, mm[i]);
    }
    float w[NSPLIT], denom = 0.f;
#pragma unroll
    for (int i = 0; i < NSPLIT; i++) {
        w[i] = __expf(mm[i] - M);
        denom += ll[i] * w[i];
    }
    float inv = 1.f / denom;
#pragma unroll
    for (int i = 0; i < NSPLIT; i++) w[i] *= inv;

    float r0 = 0.f, r1 = 0.f, r2 = 0.f, r3 = 0.f;
#pragma unroll
    for (int i = 0; i < NSPLIT; i++) {
        float4 a = *(const float4*)&g_Op[((size_t)i * BHS + row) * HDIM + c4 * 4];
        r0 += a.x * w[i];
        r1 += a.y * w[i];
        r2 += a.z * w[i];
        r3 += a.w * w[i];
    }

    const int bb = bh / HEADS;
    const int h  = bh % HEADS;
    const size_t dst = ((size_t)(bb * SEQ + s)) * EMBED + h * HDIM + c4 * 4;
    float x0, x1, x2, x3;
    unsigned h0 = pack_hi_res(r0, r1, x0, x1);
    unsigned h1 = pack_hi_res(r2, r3, x2, x3);
    *(unsigned*)&Ahi[dst]     = h0;
    *(unsigned*)&Ahi[dst + 2] = h1;
    *(unsigned*)&Alo[dst]     = pack_bf2(x0, x1);
    *(unsigned*)&Alo[dst + 2] = pack_bf2(x2, x3);
}

// ---------------- driver ----------------
extern "C" void kernel_launch(void* const* d_in, const int* in_sizes, int n_in,
                              void* d_out, int out_size)
{
    const float *x, *w_q, *b_q, *w_k, *b_k, *w_v, *b_v, *w_o, *b_o;
    if (n_in == 9 && in_sizes[0] == EMBED && in_sizes[8] == NX) {
        b_k = (const float*)d_in[0]; b_o = (const float*)d_in[1];
        b_q = (const float*)d_in[2]; b_v = (const float*)d_in[3];
        w_k = (const float*)d_in[4]; w_o = (const float*)d_in[5];
        w_q = (const float*)d_in[6]; w_v = (const float*)d_in[7];
        x   = (const float*)d_in[8];
    } else if (n_in == 9 && in_sizes[0] == NX && in_sizes[2] == NW) {
        x   = (const float*)d_in[0];
        w_q = (const float*)d_in[1]; w_k = (const float*)d_in[2];
        w_v = (const float*)d_in[3]; w_o = (const float*)d_in[4];
        b_q = (const float*)d_in[5]; b_k = (const float*)d_in[6];
        b_v = (const float*)d_in[7]; b_o = (const float*)d_in[8];
    } else {
        x   = (const float*)d_in[0];
        w_q = (const float*)d_in[1]; b_q = (const float*)d_in[2];
        w_k = (const float*)d_in[3]; b_k = (const float*)d_in[4];
        w_v = (const float*)d_in[5]; b_v = (const float*)d_in[6];
        w_o = (const float*)d_in[7]; b_o = (const float*)d_in[8];
    }
    float* out = (float*)d_out;

    __nv_bfloat16 *xh, *xl, *w0h, *w0l, *w1h, *w1l, *w2h, *w2l, *w3h, *w3l;
    __nv_bfloat16 *qh, *ql, *kh, *kl, *vh, *vl, *ah, *al;
    cudaGetSymbolAddress((void**)&xh,  g_Xhi);  cudaGetSymbolAddress((void**)&xl,  g_Xlo);
    cudaGetSymbolAddress((void**)&w0h, g_W0hi); cudaGetSymbolAddress((void**)&w0l, g_W0lo);
    cudaGetSymbolAddress((void**)&w1h, g_W1hi); cudaGetSymbolAddress((void**)&w1l, g_W1lo);
    cudaGetSymbolAddress((void**)&w2h, g_W2hi); cudaGetSymbolAddress((void**)&w2l, g_W2lo);
    cudaGetSymbolAddress((void**)&w3h, g_W3hi); cudaGetSymbolAddress((void**)&w3l, g_W3lo);
    cudaGetSymbolAddress((void**)&qh,  g_Qh);   cudaGetSymbolAddress((void**)&ql,  g_Ql);
    cudaGetSymbolAddress((void**)&kh,  g_Kh);   cudaGetSymbolAddress((void**)&kl,  g_Kl);
    cudaGetSymbolAddress((void**)&vh,  g_Vh);   cudaGetSymbolAddress((void**)&vl,  g_Vl);
    cudaGetSymbolAddress((void**)&ah,  g_Ahi);  cudaGetSymbolAddress((void**)&al,  g_Alo);

    cudaFuncSetAttribute(mma_gemm_qkv_kernel,
                         cudaFuncAttributeMaxDynamicSharedMemorySize, SMEM_GEMM);
    cudaFuncSetAttribute(mma_gemm_o_kernel,
                         cudaFuncAttributeMaxDynamicSharedMemorySize, SMEM_GEMM);
    cudaFuncSetAttribute(flash_mma_kernel,
                         cudaFuncAttributeMaxDynamicSharedMemorySize, SMEM_FLASH);

    convert_all_kernel<<<(CONV_TASKS + 255) / 256, 256>>>(
        x, w_q, w_k, w_v, w_o,
        xh, xl, w0h, w0l, w1h, w1l, w2h, w2l, w3h, w3l);

    dim3 qkvgrid(3 * (EMBED / GBN), MROWS / GBM);   // (36, 32)
    mma_gemm_qkv_kernel<<<qkvgrid, 256, SMEM_GEMM>>>(
        xh, xl, w0h, w0l, w1h, w1l, w2h, w2l,
        b_q, b_k, b_v, qh, ql, kh, kl, vh, vl);

    dim3 agrid(SEQ / 128, BH, NSPLIT);              // (16, 24, 3)
    flash_mma_kernel<<<agrid, 256, SMEM_FLASH>>>(qh, ql, kh, kl, vh, vl);

    merge_kernel<<<(BHS * (HDIM / 4) + 255) / 256, 256>>>(ah, al);

    dim3 ogrid(EMBED / GBN, MROWS / GBM);           // (12, 32)
    mma_gemm_o_kernel<<<ogrid, 256, SMEM_GEMM>>>(ah, al, w3h, w3l, b_o, out);
}

// round 12
// speedup vs baseline: 3.6823x; 1.0018x over previous
#include <cuda_runtime.h>
#include <cuda_bf16.h>
#include <math.h>

#define EMBED 768
#define HEADS 12
#define HDIM  64
#define BATCH 2
#define SEQ   2048
#define MROWS (BATCH * SEQ)      // 4096
#define BH    (BATCH * HEADS)    // 24
#define NX (MROWS * EMBED)
#define NW (EMBED * EMBED)
#define BHS (BH * SEQ)           // 49152
#define NSPLIT 3

// ---------------- scratch ----------------
__device__ __nv_bfloat16 g_Xhi[NX], g_Xlo[NX];
__device__ __nv_bfloat16 g_W0hi[NW], g_W0lo[NW];
__device__ __nv_bfloat16 g_W1hi[NW], g_W1lo[NW];
__device__ __nv_bfloat16 g_W2hi[NW], g_W2lo[NW];
__device__ __nv_bfloat16 g_W3hi[NW], g_W3lo[NW];
__device__ __nv_bfloat16 g_Qh[NX], g_Ql[NX];
__device__ __nv_bfloat16 g_Kh[NX], g_Kl[NX];
__device__ __nv_bfloat16 g_Vh[NX], g_Vl[NX];
__device__ __nv_bfloat16 g_Ahi[NX], g_Alo[NX];
// split-KV partials
__device__ float g_Op[NSPLIT * BHS * HDIM];
__device__ float g_Mp[NSPLIT * BHS];
__device__ float g_Lp[NSPLIT * BHS];

// ---------------- PTX helpers (family-portable sm_80+) ----------------
__device__ __forceinline__ unsigned smem_u32(const void* p) {
    unsigned a;
    asm("{ .reg .u64 t; cvta.to.shared.u64 t, %1; cvt.u32.u64 %0, t; }" : "=r"(a) : "l"(p));
    return a;
}
__device__ __forceinline__ void cp16(unsigned s, const void* g) {
    asm volatile("cp.async.cg.shared.global [%0], [%1], 16;" :: "r"(s), "l"(g));
}
__device__ __forceinline__ void cp_commit() { asm volatile("cp.async.commit_group;" ::: "memory"); }
template <int N> __device__ __forceinline__ void cp_wait() {
    asm volatile("cp.async.wait_group %0;" :: "n"(N) : "memory");
}
__device__ __forceinline__ void ldx4(unsigned* r, unsigned addr) {
    asm volatile("ldmatrix.sync.aligned.m8n8.x4.shared.b16 {%0,%1,%2,%3}, [%4];"
        : "=r"(r[0]), "=r"(r[1]), "=r"(r[2]), "=r"(r[3]) : "r"(addr));
}
__device__ __forceinline__ void ldx4t(unsigned* r, unsigned addr) {
    asm volatile("ldmatrix.sync.aligned.m8n8.x4.trans.shared.b16 {%0,%1,%2,%3}, [%4];"
        : "=r"(r[0]), "=r"(r[1]), "=r"(r[2]), "=r"(r[3]) : "r"(addr));
}
__device__ __forceinline__ void mma16816(float* d, const unsigned* a, const unsigned* b) {
    asm volatile(
        "mma.sync.aligned.m16n8k16.row.col.f32.bf16.bf16.f32 "
        "{%0,%1,%2,%3}, {%4,%5,%6,%7}, {%8,%9}, {%0,%1,%2,%3};"
        : "+f"(d[0]), "+f"(d[1]), "+f"(d[2]), "+f"(d[3])
        : "r"(a[0]), "r"(a[1]), "r"(a[2]), "r"(a[3]), "r"(b[0]), "r"(b[1]));
}
__device__ __forceinline__ unsigned pack_bf2(float a, float b) {
    __nv_bfloat162 t = __float22bfloat162_rn(make_float2(a, b));
    return *(unsigned*)&t;
}
__device__ __forceinline__ unsigned pack_hi_res(float a, float b, float& ra, float& rb) {
    __nv_bfloat162 t = __float22bfloat162_rn(make_float2(a, b));
    ra = a - __bfloat162float(t.x);
    rb = b - __bfloat162float(t.y);
    return *(unsigned*)&t;
}

// ---------------- fused fp32 -> bf16 hi/lo split (all 5 inputs) ----------------
struct alignas(8) B4 { __nv_bfloat16 v[4]; };
#define CONV_TASKS ((NX + 4 * NW) / 8)

__global__ void __launch_bounds__(256)
convert_all_kernel(const float* __restrict__ x,
                   const float* __restrict__ w0, const float* __restrict__ w1,
                   const float* __restrict__ w2, const float* __restrict__ w3,
                   __nv_bfloat16* xh, __nv_bfloat16* xl,
                   __nv_bfloat16* w0h, __nv_bfloat16* w0l,
                   __nv_bfloat16* w1h, __nv_bfloat16* w1l,
                   __nv_bfloat16* w2h, __nv_bfloat16* w2l,
                   __nv_bfloat16* w3h, __nv_bfloat16* w3l)
{
    long long t = (long long)blockIdx.x * 256 + threadIdx.x;
    if (t >= CONV_TASKS) return;
    long long i = t * 8;
    const float* src;
    __nv_bfloat16 *hi, *lo;
    long long off;
    if (i < NX) { src = x; hi = xh; lo = xl; off = i; }
    else {
        long long j = i - NX;
        int w = (int)(j / NW);
        off = j - (long long)w * NW;
        if      (w == 0) { src = w0; hi = w0h; lo = w0l; }
        else if (w == 1) { src = w1; hi = w1h; lo = w1l; }
        else if (w == 2) { src = w2; hi = w2h; lo = w2l; }
        else             { src = w3; hi = w3h; lo = w3l; }
    }
#pragma unroll
    for (int half = 0; half < 2; half++) {
        float4 v = *(const float4*)&src[off + half * 4];
        B4 h, l;
        float f[4] = {v.x, v.y, v.z, v.w};
#pragma unroll
        for (int j = 0; j < 4; j++) {
            h.v[j] = __float2bfloat16(f[j]);
            l.v[j] = __float2bfloat16(f[j] - __bfloat162float(h.v[j]));
        }
        *(B4*)&hi[off + half * 4] = h;
        *(B4*)&lo[off + half * 4] = l;
    }
}

// ---------------- HMMA GEMM body: Y = X @ W^T + b  (bf16x3, CTA 128x128) ----------------
#define GBM 128
#define GBN 128
#define GBK 32
#define KITERS (EMBED / GBK)     // 24
#define ASTR 80
#define A_SZ (128 * ASTR)        // 10240
#define B_SZ (128 * ASTR)        // 10240
#define STAGE (2 * A_SZ + 2 * B_SZ)   // 40960
#define SMEM_GEMM (2 * STAGE)         // 81920
#define NBLK (EMBED / GBN)       // 6

__device__ __forceinline__ void
gemm_body(unsigned sb,
          const __nv_bfloat16* __restrict__ Ahi, const __nv_bfloat16* __restrict__ Alo,
          const __nv_bfloat16* __restrict__ Bhi, const __nv_bfloat16* __restrict__ Blo,
          const float* __restrict__ bias, float* __restrict__ Yf,
          __nv_bfloat16* __restrict__ Yhi, __nv_bfloat16* __restrict__ Ylo,
          int mode, float scale, int m0, int n0)
{
    const int tid  = threadIdx.x;
    const int lane = tid & 31;
    const int wid  = tid >> 5;
    const int warpM = wid & 3;        // 4 along M (32 rows each)
    const int warpN = wid >> 2;       // 2 along N (64 cols each)

    auto sA_hi = [&](int s) { return sb + s * STAGE; };
    auto sA_lo = [&](int s) { return sb + s * STAGE + A_SZ; };
    auto sB_hi = [&](int s) { return sb + s * STAGE + 2 * A_SZ; };
    auto sB_lo = [&](int s) { return sb + s * STAGE + 2 * A_SZ + B_SZ; };

    // 512 16B-chunks per tensor (128 rows x 4), 2 per thread
    const int r0_ = (tid * 2) >> 2, c0_ = (tid * 2) & 3;
    const int r1_ = (tid * 2 + 1) >> 2, c1_ = (tid * 2 + 1) & 3;

    auto load_stage = [&](int kt, int s) {
        const int k0 = kt * GBK;
        const __nv_bfloat16* pah = Ahi + (size_t)m0 * EMBED + k0;
        const __nv_bfloat16* pal = Alo + (size_t)m0 * EMBED + k0;
        const __nv_bfloat16* pbh = Bhi + (size_t)n0 * EMBED + k0;
        const __nv_bfloat16* pbl = Blo + (size_t)n0 * EMBED + k0;
        cp16(sA_hi(s) + r0_ * ASTR + c0_ * 16, pah + (size_t)r0_ * EMBED + c0_ * 8);
        cp16(sA_hi(s) + r1_ * ASTR + c1_ * 16, pah + (size_t)r1_ * EMBED + c1_ * 8);
        cp16(sA_lo(s) + r0_ * ASTR + c0_ * 16, pal + (size_t)r0_ * EMBED + c0_ * 8);
        cp16(sA_lo(s) + r1_ * ASTR + c1_ * 16, pal + (size_t)r1_ * EMBED + c1_ * 8);
        cp16(sB_hi(s) + r0_ * ASTR + c0_ * 16, pbh + (size_t)r0_ * EMBED + c0_ * 8);
        cp16(sB_hi(s) + r1_ * ASTR + c1_ * 16, pbh + (size_t)r1_ * EMBED + c1_ * 8);
        cp16(sB_lo(s) + r0_ * ASTR + c0_ * 16, pbl + (size_t)r0_ * EMBED + c0_ * 8);
        cp16(sB_lo(s) + r1_ * ASTR + c1_ * 16, pbl + (size_t)r1_ * EMBED + c1_ * 8);
        cp_commit();
    };

    const unsigned aOff = (unsigned)((warpM * 32 + ((lane >> 3) & 1) * 8 + (lane & 7)) * ASTR
                                     + (lane >> 4) * 16);
    const unsigned bOff = (unsigned)((warpN * 64 + ((lane >> 4) & 1) * 8 + (lane & 7)) * ASTR
                                     + ((lane >> 3) & 1) * 16);

    float acc[2][8][4];
#pragma unroll
    for (int mt = 0; mt < 2; mt++)
#pragma unroll
        for (int nt = 0; nt < 8; nt++)
#pragma unroll
            for (int j = 0; j < 4; j++) acc[mt][nt][j] = 0.f;

    load_stage(0, 0);

    for (int kt = 0; kt < KITERS; kt++) {
        const int s = kt & 1;
        cp_wait<0>();
        __syncthreads();
        if (kt + 1 < KITERS) load_stage(kt + 1, s ^ 1);

#pragma unroll
        for (int ks = 0; ks < 2; ks++) {
            unsigned a_h[2][4], a_l[2][4];
#pragma unroll
            for (int mt = 0; mt < 2; mt++) {
                ldx4(a_h[mt], sA_hi(s) + aOff + mt * (16 * ASTR) + ks * 32);
                ldx4(a_l[mt], sA_lo(s) + aOff + mt * (16 * ASTR) + ks * 32);
            }
#pragma unroll
            for (int p = 0; p < 4; p++) {
                unsigned b_h[4], b_l[4];
                ldx4(b_h, sB_hi(s) + bOff + p * (16 * ASTR) + ks * 32);
                ldx4(b_l, sB_lo(s) + bOff + p * (16 * ASTR) + ks * 32);
#pragma unroll
                for (int mt = 0; mt < 2; mt++)
#pragma unroll
                    for (int j = 0; j < 2; j++) {
                        const int nt = p * 2 + j;
                        mma16816(acc[mt][nt], a_h[mt], &b_h[j * 2]);
                        mma16816(acc[mt][nt], a_h[mt], &b_l[j * 2]);
                        mma16816(acc[mt][nt], a_l[mt], &b_h[j * 2]);
                    }
            }
        }
    }

    const int g  = lane >> 2;
    const int tg = lane & 3;
#pragma unroll
    for (int mt = 0; mt < 2; mt++) {
#pragma unroll
        for (int nt = 0; nt < 8; nt++) {
            const int nl = warpN * 64 + nt * 8 + tg * 2;
            const int n  = n0 + nl;
            float2 bv = *(const float2*)&bias[n];
#pragma unroll
            for (int half = 0; half < 2; half++) {
                const int ml = warpM * 32 + mt * 16 + g + half * 8;
                const int m  = m0 + ml;
                float c0 = acc[mt][nt][half * 2 + 0] + bv.x;
                float c1 = acc[mt][nt][half * 2 + 1] + bv.y;
                if (mode == 0) {
                    const int h = n >> 6;          // head from full n (2 heads per CTA)
                    const int bb = m >> 11;
                    const int ss = m & 2047;
                    float v0 = c0 * scale, v1 = c1 * scale;
                    float r0, r1;
                    unsigned hp = pack_hi_res(v0, v1, r0, r1);
                    unsigned lp = pack_bf2(r0, r1);
                    size_t idx = ((size_t)(bb * HEADS + h) * SEQ + ss) * HDIM + (n & 63);
                    *(unsigned*)&Yhi[idx] = hp;
                    *(unsigned*)&Ylo[idx] = lp;
                } else {
                    *(float2*)&Yf[(size_t)m * EMBED + n] = make_float2(c0, c1);
                }
            }
        }
    }
}

// fused Q/K/V projection: proj = blockIdx.x / NBLK
__global__ void __launch_bounds__(256, 2)
mma_gemm_qkv_kernel(const __nv_bfloat16* __restrict__ xh, const __nv_bfloat16* __restrict__ xl,
                    const __nv_bfloat16* __restrict__ w0h, const __nv_bfloat16* __restrict__ w0l,
                    const __nv_bfloat16* __restrict__ w1h, const __nv_bfloat16* __restrict__ w1l,
                    const __nv_bfloat16* __restrict__ w2h, const __nv_bfloat16* __restrict__ w2l,
                    const float* __restrict__ b_q, const float* __restrict__ b_k,
                    const float* __restrict__ b_v,
                    __nv_bfloat16* qh, __nv_bfloat16* ql,
                    __nv_bfloat16* kh, __nv_bfloat16* kl,
                    __nv_bfloat16* vh, __nv_bfloat16* vl)
{
    extern __shared__ char smraw[];
    const unsigned sb = smem_u32(smraw);
    const int pj   = blockIdx.x / NBLK;
    const int nblk = blockIdx.x % NBLK;
    const __nv_bfloat16 *Bh, *Bl;
    const float* bias;
    __nv_bfloat16 *Yh, *Yl;
    float scale;
    if (pj == 0)      { Bh = w0h; Bl = w0l; bias = b_q; Yh = qh; Yl = ql; scale = 0.125f; }
    else if (pj == 1) { Bh = w1h; Bl = w1l; bias = b_k; Yh = kh; Yl = kl; scale = 1.0f; }
    else              { Bh = w2h; Bl = w2l; bias = b_v; Yh = vh; Yl = vl; scale = 1.0f; }
    gemm_body(sb, xh, xl, Bh, Bl, bias, nullptr, Yh, Yl, 0, scale,
              blockIdx.y * GBM, nblk * GBN);
}

// out-projection
__global__ void __launch_bounds__(256, 2)
mma_gemm_o_kernel(const __nv_bfloat16* __restrict__ ah, const __nv_bfloat16* __restrict__ al,
                  const __nv_bfloat16* __restrict__ w3h, const __nv_bfloat16* __restrict__ w3l,
                  const float* __restrict__ b_o, float* __restrict__ out)
{
    extern __shared__ char smraw[];
    const unsigned sb = smem_u32(smraw);
    gemm_body(sb, ah, al, w3h, w3l, b_o, out, nullptr, nullptr, 1, 1.0f,
              blockIdx.y * GBM, blockIdx.x * GBN);
}

// ---------------- Flash attention, split-KV x3, single-sync mainloop ----------------
#define QSTR 144
#define F_oQh 0
#define F_oQl 18432
#define KV_BASE 36864
#define KV_STAGE 36864
#define KV_oKh 0
#define KV_oKl 9216
#define KV_oVh 18432
#define KV_oVl 27648
#define SMEM_FLASH (KV_BASE + 2 * KV_STAGE)   // 110592

__global__ void __launch_bounds__(256)
flash_mma_kernel(const __nv_bfloat16* __restrict__ Qh, const __nv_bfloat16* __restrict__ Ql,
                 const __nv_bfloat16* __restrict__ Kh, const __nv_bfloat16* __restrict__ Kl,
                 const __nv_bfloat16* __restrict__ Vh, const __nv_bfloat16* __restrict__ Vl)
{
    extern __shared__ char smf[];
    const unsigned sb = smem_u32(smf);
    const int tid  = threadIdx.x;
    const int lane = tid & 31;
    const int wid  = tid >> 5;
    const int bh   = blockIdx.y;
    const int q0   = blockIdx.x * 128;
    const int split = blockIdx.z;

    const size_t qoff = ((size_t)bh * SEQ + q0) * HDIM;
    const size_t koff = (size_t)bh * SEQ * HDIM;
    const __nv_bfloat16* pQh = Qh + qoff;
    const __nv_bfloat16* pQl = Ql + qoff;
    const __nv_bfloat16* pKh = Kh + koff;
    const __nv_bfloat16* pKl = Kl + koff;
    const __nv_bfloat16* pVh = Vh + koff;
    const __nv_bfloat16* pVl = Vl + koff;

#pragma unroll
    for (int i = 0; i < 4; i++) {
        int task = tid + i * 256;
        int r = task >> 3, c = task & 7;
        cp16(sb + F_oQh + r * QSTR + c * 16, pQh + (size_t)r * HDIM + c * 8);
        cp16(sb + F_oQl + r * QSTR + c * 16, pQl + (size_t)r * HDIM + c * 8);
    }
    cp_commit();

    auto load_kv = [&](int kt, int s) {
        const unsigned st = sb + KV_BASE + s * KV_STAGE;
        const int k0 = kt * 64;
#pragma unroll
        for (int i = 0; i < 2; i++) {
            int task = tid + i * 256;
            int r = task >> 3, c = task & 7;
            size_t go = (size_t)(k0 + r) * HDIM + c * 8;
            unsigned so = r * QSTR + c * 16;
            cp16(st + KV_oKh + so, pKh + go);
            cp16(st + KV_oKl + so, pKl + go);
            cp16(st + KV_oVh + so, pVh + go);
            cp16(st + KV_oVl + so, pVl + go);
        }
        cp_commit();
    };

    const int g  = lane >> 2;
    const int tg = lane & 3;
    const unsigned aAddr = sb + (unsigned)((wid * 16 + ((lane >> 3) & 1) * 8 + (lane & 7)) * QSTR
                                           + (lane >> 4) * 16);
    const unsigned kRel = (unsigned)((((lane >> 4) & 1) * 8 + (lane & 7)) * QSTR
                                     + ((lane >> 3) & 1) * 16);
    const unsigned vRel = (unsigned)((((lane >> 3) & 1) * 8 + (lane & 7)) * QSTR
                                     + (lane >> 4) * 16);

    float m0 = -INFINITY, m1 = -INFINITY, l0 = 0.f, l1 = 0.f;
    float o[8][4];
#pragma unroll
    for (int nf = 0; nf < 8; nf++)
#pragma unroll
        for (int j = 0; j < 4; j++) o[nf][j] = 0.f;

    // splits: 11 / 11 / 10 KV tiles
    const int kt0 = split * 11;
    const int kt1 = (split == 2) ? 32 : kt0 + 11;
    load_kv(kt0, 0);

    for (int kt = kt0; kt < kt1; kt++) {
        const int s = (kt - kt0) & 1;
        cp_wait<0>();
        __syncthreads();
        if (kt + 1 < kt1) load_kv(kt + 1, s ^ 1);

        const unsigned stK = sb + KV_BASE + s * KV_STAGE;

        float sc[8][4];
#pragma unroll
        for (int nf = 0; nf < 8; nf++)
#pragma unroll
            for (int j = 0; j < 4; j++) sc[nf][j] = 0.f;

#pragma unroll
        for (int ks = 0; ks < 4; ks++) {
            unsigned qhf[4], qlf[4];
            ldx4(qhf, aAddr + F_oQh + ks * 32);
            ldx4(qlf, aAddr + F_oQl + ks * 32);
#pragma unroll
            for (int p = 0; p < 4; p++) {
                unsigned khf[4], klf[4];
                ldx4(khf, stK + KV_oKh + kRel + p * (16 * QSTR) + ks * 32);
                ldx4(klf, stK + KV_oKl + kRel + p * (16 * QSTR) + ks * 32);
                mma16816(sc[2 * p],     qhf, &khf[0]);
                mma16816(sc[2 * p],     qhf, &klf[0]);
                mma16816(sc[2 * p],     qlf, &khf[0]);
                mma16816(sc[2 * p + 1], qhf, &khf[2]);
                mma16816(sc[2 * p + 1], qhf, &klf[2]);
                mma16816(sc[2 * p + 1], qlf, &khf[2]);
            }
        }

        float pm0 = sc[0][0], pm1 = sc[0][2];
#pragma unroll
        for (int nf = 0; nf < 8; nf++) {
            pm0 = fmaxf(pm0, fmaxf(sc[nf][0], sc[nf][1]));
            pm1 = fmaxf(pm1, fmaxf(sc[nf][2], sc[nf][3]));
        }
        pm0 = fmaxf(pm0, __shfl_xor_sync(0xffffffffu, pm0, 1, 4));
        pm0 = fmaxf(pm0, __shfl_xor_sync(0xffffffffu, pm0, 2, 4));
        pm1 = fmaxf(pm1, __shfl_xor_sync(0xffffffffu, pm1, 1, 4));
        pm1 = fmaxf(pm1, __shfl_xor_sync(0xffffffffu, pm1, 2, 4));
        const float mn0 = fmaxf(m0, pm0);
        const float mn1 = fmaxf(m1, pm1);
        const float al0 = __expf(m0 - mn0);
        const float al1 = __expf(m1 - mn1);
        m0 = mn0; m1 = mn1;
        float ps0 = 0.f, ps1 = 0.f;
#pragma unroll
        for (int nf = 0; nf < 8; nf++) {
            sc[nf][0] = __expf(sc[nf][0] - mn0);
            sc[nf][1] = __expf(sc[nf][1] - mn0);
            sc[nf][2] = __expf(sc[nf][2] - mn1);
            sc[nf][3] = __expf(sc[nf][3] - mn1);
            ps0 += sc[nf][0] + sc[nf][1];
            ps1 += sc[nf][2] + sc[nf][3];
        }
        ps0 += __shfl_xor_sync(0xffffffffu, ps0, 1, 4);
        ps0 += __shfl_xor_sync(0xffffffffu, ps0, 2, 4);
        ps1 += __shfl_xor_sync(0xffffffffu, ps1, 1, 4);
        ps1 += __shfl_xor_sync(0xffffffffu, ps1, 2, 4);
        l0 = l0 * al0 + ps0;
        l1 = l1 * al1 + ps1;
#pragma unroll
        for (int nf = 0; nf < 8; nf++) {
            o[nf][0] *= al0; o[nf][1] *= al0;
            o[nf][2] *= al1; o[nf][3] *= al1;
        }

#pragma unroll
        for (int kb = 0; kb < 4; kb++) {
            float r0, r1, r2, r3, r4, r5, r6, r7;
            unsigned pa_h[4], pa_l[4];
            pa_h[0] = pack_hi_res(sc[2 * kb][0],     sc[2 * kb][1],     r0, r1);
            pa_h[1] = pack_hi_res(sc[2 * kb][2],     sc[2 * kb][3],     r2, r3);
            pa_h[2] = pack_hi_res(sc[2 * kb + 1][0], sc[2 * kb + 1][1], r4, r5);
            pa_h[3] = pack_hi_res(sc[2 * kb + 1][2], sc[2 * kb + 1][3], r6, r7);
            pa_l[0] = pack_bf2(r0, r1);
            pa_l[1] = pack_bf2(r2, r3);
            pa_l[2] = pack_bf2(r4, r5);
            pa_l[3] = pack_bf2(r6, r7);
#pragma unroll
            for (int du = 0; du < 4; du++) {
                unsigned vhf[4], vlf[4];
                ldx4t(vhf, stK + KV_oVh + vRel + kb * (16 * QSTR) + du * 32);
                ldx4t(vlf, stK + KV_oVl + vRel + kb * (16 * QSTR) + du * 32);
                mma16816(o[du * 2],     pa_h, &vhf[0]);
                mma16816(o[du * 2],     pa_h, &vlf[0]);
                mma16816(o[du * 2],     pa_l, &vhf[0]);
                mma16816(o[du * 2 + 1], pa_h, &vhf[2]);
                mma16816(o[du * 2 + 1], pa_h, &vlf[2]);
                mma16816(o[du * 2 + 1], pa_l, &vhf[2]);
            }
        }
    }

    // ---- store unnormalized partials + (m, l) ----
    const int r0 = q0 + wid * 16 + g;
    const size_t prow = (size_t)(split * BH + bh) * SEQ + r0;
    float* Op0 = &g_Op[prow * HDIM];
    float* Op1 = &g_Op[(prow + 8) * HDIM];
#pragma unroll
    for (int nf = 0; nf < 8; nf++) {
        const int e = nf * 8 + tg * 2;
        *(float2*)&Op0[e] = make_float2(o[nf][0], o[nf][1]);
        *(float2*)&Op1[e] = make_float2(o[nf][2], o[nf][3]);
    }
    if (tg == 0) {
        g_Mp[prow] = m0;     g_Lp[prow] = l0;
        g_Mp[prow + 8] = m1; g_Lp[prow + 8] = l1;
    }
}

// ---------------- split-KV merge: combine NSPLIT partials -> bf16 hi/lo A ----------------
__global__ void __launch_bounds__(256)
merge_kernel(__nv_bfloat16* __restrict__ Ahi, __nv_bfloat16* __restrict__ Alo)
{
    int t = blockIdx.x * 256 + threadIdx.x;     // BHS * 16 tasks
    if (t >= BHS * (HDIM / 4)) return;
    const int c4  = t & 15;
    const size_t row = (size_t)(t >> 4);        // [0, BHS)
    const int bh = (int)(row / SEQ);
    const int s  = (int)(row - (size_t)bh * SEQ);

    float mm[NSPLIT], ll[NSPLIT];
    float M = -INFINITY;
#pragma unroll
    for (int i = 0; i < NSPLIT; i++) {
        mm[i] = g_Mp[(size_t)i * BHS + row];
        ll[i] = g_Lp[(size_t)i * BHS + row];
        M = fmaxf(M, mm[i]);
    }
    float w[NSPLIT], denom = 0.f;
#pragma unroll
    for (int i = 0; i < NSPLIT; i++) {
        w[i] = __expf(mm[i] - M);
        denom += ll[i] * w[i];
    }
    float inv = 1.f / denom;
#pragma unroll
    for (int i = 0; i < NSPLIT; i++) w[i] *= inv;

    float r0 = 0.f, r1 = 0.f, r2 = 0.f, r3 = 0.f;
#pragma unroll
    for (int i = 0; i < NSPLIT; i++) {
        float4 a = *(const float4*)&g_Op[((size_t)i * BHS + row) * HDIM + c4 * 4];
        r0 += a.x * w[i];
        r1 += a.y * w[i];
        r2 += a.z * w[i];
        r3 += a.w * w[i];
    }

    const int bb = bh / HEADS;
    const int h  = bh % HEADS;
    const size_t dst = ((size_t)(bb * SEQ + s)) * EMBED + h * HDIM + c4 * 4;
    float x0, x1, x2, x3;
    unsigned h0 = pack_hi_res(r0, r1, x0, x1);
    unsigned h1 = pack_hi_res(r2, r3, x2, x3);
    *(unsigned*)&Ahi[dst]     = h0;
    *(unsigned*)&Ahi[dst + 2] = h1;
    *(unsigned*)&Alo[dst]     = pack_bf2(x0, x1);
    *(unsigned*)&Alo[dst + 2] = pack_bf2(x2, x3);
}

// ---------------- driver ----------------
extern "C" void kernel_launch(void* const* d_in, const int* in_sizes, int n_in,
                              void* d_out, int out_size)
{
    const float *x, *w_q, *b_q, *w_k, *b_k, *w_v, *b_v, *w_o, *b_o;
    if (n_in == 9 && in_sizes[0] == EMBED && in_sizes[8] == NX) {
        b_k = (const float*)d_in[0]; b_o = (const float*)d_in[1];
        b_q = (const float*)d_in[2]; b_v = (const float*)d_in[3];
        w_k = (const float*)d_in[4]; w_o = (const float*)d_in[5];
        w_q = (const float*)d_in[6]; w_v = (const float*)d_in[7];
        x   = (const float*)d_in[8];
    } else if (n_in == 9 && in_sizes[0] == NX && in_sizes[2] == NW) {
        x   = (const float*)d_in[0];
        w_q = (const float*)d_in[1]; w_k = (const float*)d_in[2];
        w_v = (const float*)d_in[3]; w_o = (const float*)d_in[4];
        b_q = (const float*)d_in[5]; b_k = (const float*)d_in[6];
        b_v = (const float*)d_in[7]; b_o = (const float*)d_in[8];
    } else {
        x   = (const float*)d_in[0];
        w_q = (const float*)d_in[1]; b_q = (const float*)d_in[2];
        w_k = (const float*)d_in[3]; b_k = (const float*)d_in[4];
        w_v = (const float*)d_in[5]; b_v = (const float*)d_in[6];
        w_o = (const float*)d_in[7]; b_o = (const float*)d_in[8];
    }
    float* out = (float*)d_out;

    __nv_bfloat16 *xh, *xl, *w0h, *w0l, *w1h, *w1l, *w2h, *w2l, *w3h, *w3l;
    __nv_bfloat16 *qh, *ql, *kh, *kl, *vh, *vl, *ah, *al;
    cudaGetSymbolAddress((void**)&xh,  g_Xhi);  cudaGetSymbolAddress((void**)&xl,  g_Xlo);
    cudaGetSymbolAddress((void**)&w0h, g_W0hi); cudaGetSymbolAddress((void**)&w0l, g_W0lo);
    cudaGetSymbolAddress((void**)&w1h, g_W1hi); cudaGetSymbolAddress((void**)&w1l, g_W1lo);
    cudaGetSymbolAddress((void**)&w2h, g_W2hi); cudaGetSymbolAddress((void**)&w2l, g_W2lo);
    cudaGetSymbolAddress((void**)&w3h, g_W3hi); cudaGetSymbolAddress((void**)&w3l, g_W3lo);
    cudaGetSymbolAddress((void**)&qh,  g_Qh);   cudaGetSymbolAddress((void**)&ql,  g_Ql);
    cudaGetSymbolAddress((void**)&kh,  g_Kh);   cudaGetSymbolAddress((void**)&kl,  g_Kl);
    cudaGetSymbolAddress((void**)&vh,  g_Vh);   cudaGetSymbolAddress((void**)&vl,  g_Vl);
    cudaGetSymbolAddress((void**)&ah,  g_Ahi);  cudaGetSymbolAddress((void**)&al,  g_Alo);

    cudaFuncSetAttribute(mma_gemm_qkv_kernel,
                         cudaFuncAttributeMaxDynamicSharedMemorySize, SMEM_GEMM);
    cudaFuncSetAttribute(mma_gemm_o_kernel,
                         cudaFuncAttributeMaxDynamicSharedMemorySize, SMEM_GEMM);
    cudaFuncSetAttribute(flash_mma_kernel,
                         cudaFuncAttributeMaxDynamicSharedMemorySize, SMEM_FLASH);

    convert_all_kernel<<<(CONV_TASKS + 255) / 256, 256>>>(
        x, w_q, w_k, w_v, w_o,
        xh, xl, w0h, w0l, w1h, w1l, w2h, w2l, w3h, w3l);

    dim3 qkvgrid(3 * NBLK, MROWS / GBM);            // (18, 32)
    mma_gemm_qkv_kernel<<<qkvgrid, 256, SMEM_GEMM>>>(
        xh, xl, w0h, w0l, w1h, w1l, w2h, w2l,
        b_q, b_k, b_v, qh, ql, kh, kl, vh, vl);

    dim3 agrid(SEQ / 128, BH, NSPLIT);              // (16, 24, 3)
    flash_mma_kernel<<<agrid, 256, SMEM_FLASH>>>(qh, ql, kh, kl, vh, vl);

    merge_kernel<<<(BHS * (HDIM / 4) + 255) / 256, 256>>>(ah, al);

    dim3 ogrid(NBLK, MROWS / GBM);                  // (6, 32)
    mma_gemm_o_kernel<<<ogrid, 256, SMEM_GEMM>>>(ah, al, w3h, w3l, b_o, out);
}

// round 13
// speedup vs baseline: 3.7612x; 1.0214x over previous
#include <cuda_runtime.h>
#include <cuda_bf16.h>
#include <math.h>

#define EMBED 768
#define HEADS 12
#define HDIM  64
#define BATCH 2
#define SEQ   2048
#define MROWS (BATCH * SEQ)      // 4096
#define BH    (BATCH * HEADS)    // 24
#define NX (MROWS * EMBED)
#define NW (EMBED * EMBED)
#define BHS (BH * SEQ)           // 49152
#define NSPLIT 3

// ---------------- scratch ----------------
__device__ __nv_bfloat16 g_Xhi[NX], g_Xlo[NX];
__device__ __nv_bfloat16 g_W0hi[NW], g_W0lo[NW];
__device__ __nv_bfloat16 g_W1hi[NW], g_W1lo[NW];
__device__ __nv_bfloat16 g_W2hi[NW], g_W2lo[NW];
__device__ __nv_bfloat16 g_W3hi[NW], g_W3lo[NW];
__device__ __nv_bfloat16 g_Qh[NX], g_Ql[NX];
__device__ __nv_bfloat16 g_Kh[NX], g_Kl[NX];
__device__ __nv_bfloat16 g_Vh[NX], g_Vl[NX];
__device__ __nv_bfloat16 g_Ahi[NX], g_Alo[NX];
// split-KV partials
__device__ float g_Op[NSPLIT * BHS * HDIM];
__device__ float g_Mp[NSPLIT * BHS];
__device__ float g_Lp[NSPLIT * BHS];

// ---------------- PTX helpers (family-portable sm_80+) ----------------
__device__ __forceinline__ unsigned smem_u32(const void* p) {
    unsigned a;
    asm("{ .reg .u64 t; cvta.to.shared.u64 t, %1; cvt.u32.u64 %0, t; }" : "=r"(a) : "l"(p));
    return a;
}
__device__ __forceinline__ void cp16(unsigned s, const void* g) {
    asm volatile("cp.async.cg.shared.global [%0], [%1], 16;" :: "r"(s), "l"(g));
}
__device__ __forceinline__ void cp_commit() { asm volatile("cp.async.commit_group;" ::: "memory"); }
template <int N> __device__ __forceinline__ void cp_wait() {
    asm volatile("cp.async.wait_group %0;" :: "n"(N) : "memory");
}
__device__ __forceinline__ void ldx4(unsigned* r, unsigned addr) {
    asm volatile("ldmatrix.sync.aligned.m8n8.x4.shared.b16 {%0,%1,%2,%3}, [%4];"
        : "=r"(r[0]), "=r"(r[1]), "=r"(r[2]), "=r"(r[3]) : "r"(addr));
}
__device__ __forceinline__ void ldx4t(unsigned* r, unsigned addr) {
    asm volatile("ldmatrix.sync.aligned.m8n8.x4.trans.shared.b16 {%0,%1,%2,%3}, [%4];"
        : "=r"(r[0]), "=r"(r[1]), "=r"(r[2]), "=r"(r[3]) : "r"(addr));
}
__device__ __forceinline__ void mma16816(float* d, const unsigned* a, const unsigned* b) {
    asm volatile(
        "mma.sync.aligned.m16n8k16.row.col.f32.bf16.bf16.f32 "
        "{%0,%1,%2,%3}, {%4,%5,%6,%7}, {%8,%9}, {%0,%1,%2,%3};"
        : "+f"(d[0]), "+f"(d[1]), "+f"(d[2]), "+f"(d[3])
        : "r"(a[0]), "r"(a[1]), "r"(a[2]), "r"(a[3]), "r"(b[0]), "r"(b[1]));
}
__device__ __forceinline__ unsigned pack_bf2(float a, float b) {
    __nv_bfloat162 t = __float22bfloat162_rn(make_float2(a, b));
    return *(unsigned*)&t;
}
__device__ __forceinline__ unsigned pack_hi_res(float a, float b, float& ra, float& rb) {
    __nv_bfloat162 t = __float22bfloat162_rn(make_float2(a, b));
    ra = a - __bfloat162float(t.x);
    rb = b - __bfloat162float(t.y);
    return *(unsigned*)&t;
}

// ---------------- fused fp32 -> bf16 hi/lo split (all 5 inputs) ----------------
struct alignas(8) B4 { __nv_bfloat16 v[4]; };
#define CONV_TASKS ((NX + 4 * NW) / 8)

__global__ void __launch_bounds__(256)
convert_all_kernel(const float* __restrict__ x,
                   const float* __restrict__ w0, const float* __restrict__ w1,
                   const float* __restrict__ w2, const float* __restrict__ w3,
                   __nv_bfloat16* xh, __nv_bfloat16* xl,
                   __nv_bfloat16* w0h, __nv_bfloat16* w0l,
                   __nv_bfloat16* w1h, __nv_bfloat16* w1l,
                   __nv_bfloat16* w2h, __nv_bfloat16* w2l,
                   __nv_bfloat16* w3h, __nv_bfloat16* w3l)
{
    long long t = (long long)blockIdx.x * 256 + threadIdx.x;
    if (t >= CONV_TASKS) return;
    long long i = t * 8;
    const float* src;
    __nv_bfloat16 *hi, *lo;
    long long off;
    if (i < NX) { src = x; hi = xh; lo = xl; off = i; }
    else {
        long long j = i - NX;
        int w = (int)(j / NW);
        off = j - (long long)w * NW;
        if      (w == 0) { src = w0; hi = w0h; lo = w0l; }
        else if (w == 1) { src = w1; hi = w1h; lo = w1l; }
        else if (w == 2) { src = w2; hi = w2h; lo = w2l; }
        else             { src = w3; hi = w3h; lo = w3l; }
    }
#pragma unroll
    for (int half = 0; half < 2; half++) {
        float4 v = *(const float4*)&src[off + half * 4];
        B4 h, l;
        float f[4] = {v.x, v.y, v.z, v.w};
#pragma unroll
        for (int j = 0; j < 4; j++) {
            h.v[j] = __float2bfloat16(f[j]);
            l.v[j] = __float2bfloat16(f[j] - __bfloat162float(h.v[j]));
        }
        *(B4*)&hi[off + half * 4] = h;
        *(B4*)&lo[off + half * 4] = l;
    }
}

// ---------------- HMMA GEMM body, templated on N tile (bf16x3) ----------------
#define GBM 128
#define GBK 32
#define KITERS (EMBED / GBK)     // 24
#define ASTR 80
#define A_SZ (128 * ASTR)        // 10240

template <int BN>
__device__ __forceinline__ void
gemm_body(unsigned sb,
          const __nv_bfloat16* __restrict__ Ahi, const __nv_bfloat16* __restrict__ Alo,
          const __nv_bfloat16* __restrict__ Bhi, const __nv_bfloat16* __restrict__ Blo,
          const float* __restrict__ bias, float* __restrict__ Yf,
          __nv_bfloat16* __restrict__ Yhi, __nv_bfloat16* __restrict__ Ylo,
          int mode, float scale, int m0, int n0)
{
    constexpr int B_SZ  = BN * ASTR;
    constexpr int STAGE = 2 * A_SZ + 2 * B_SZ;
    constexpr int NT    = BN / 16;       // n-frags per warp (warp tile = 32 x BN/2)
    constexpr int WNSP  = BN / 2;        // warpN span in cols

    const int tid  = threadIdx.x;
    const int lane = tid & 31;
    const int wid  = tid >> 5;
    const int warpM = wid & 3;
    const int warpN = wid >> 2;

    auto sA_hi = [&](int s) { return sb + s * STAGE; };
    auto sA_lo = [&](int s) { return sb + s * STAGE + A_SZ; };
    auto sB_hi = [&](int s) { return sb + s * STAGE + 2 * A_SZ; };
    auto sB_lo = [&](int s) { return sb + s * STAGE + 2 * A_SZ + B_SZ; };

    const int r0_ = (tid * 2) >> 2, c0_ = (tid * 2) & 3;
    const int r1_ = (tid * 2 + 1) >> 2, c1_ = (tid * 2 + 1) & 3;
    const int br = tid >> 2, bc = tid & 3;

    auto load_stage = [&](int kt, int s) {
        const int k0 = kt * GBK;
        const __nv_bfloat16* pah = Ahi + (size_t)m0 * EMBED + k0;
        const __nv_bfloat16* pal = Alo + (size_t)m0 * EMBED + k0;
        const __nv_bfloat16* pbh = Bhi + (size_t)n0 * EMBED + k0;
        const __nv_bfloat16* pbl = Blo + (size_t)n0 * EMBED + k0;
        cp16(sA_hi(s) + r0_ * ASTR + c0_ * 16, pah + (size_t)r0_ * EMBED + c0_ * 8);
        cp16(sA_hi(s) + r1_ * ASTR + c1_ * 16, pah + (size_t)r1_ * EMBED + c1_ * 8);
        cp16(sA_lo(s) + r0_ * ASTR + c0_ * 16, pal + (size_t)r0_ * EMBED + c0_ * 8);
        cp16(sA_lo(s) + r1_ * ASTR + c1_ * 16, pal + (size_t)r1_ * EMBED + c1_ * 8);
        if (BN == 128) {
            cp16(sB_hi(s) + r0_ * ASTR + c0_ * 16, pbh + (size_t)r0_ * EMBED + c0_ * 8);
            cp16(sB_hi(s) + r1_ * ASTR + c1_ * 16, pbh + (size_t)r1_ * EMBED + c1_ * 8);
            cp16(sB_lo(s) + r0_ * ASTR + c0_ * 16, pbl + (size_t)r0_ * EMBED + c0_ * 8);
            cp16(sB_lo(s) + r1_ * ASTR + c1_ * 16, pbl + (size_t)r1_ * EMBED + c1_ * 8);
        } else {
            cp16(sB_hi(s) + br * ASTR + bc * 16, pbh + (size_t)br * EMBED + bc * 8);
            cp16(sB_lo(s) + br * ASTR + bc * 16, pbl + (size_t)br * EMBED + bc * 8);
        }
        cp_commit();
    };

    const unsigned aOff = (unsigned)((warpM * 32 + ((lane >> 3) & 1) * 8 + (lane & 7)) * ASTR
                                     + (lane >> 4) * 16);
    const unsigned bOff = (unsigned)((warpN * WNSP + ((lane >> 4) & 1) * 8 + (lane & 7)) * ASTR
                                     + ((lane >> 3) & 1) * 16);

    float acc[2][NT][4];
#pragma unroll
    for (int mt = 0; mt < 2; mt++)
#pragma unroll
        for (int nt = 0; nt < NT; nt++)
#pragma unroll
            for (int j = 0; j < 4; j++) acc[mt][nt][j] = 0.f;

    load_stage(0, 0);

    for (int kt = 0; kt < KITERS; kt++) {
        const int s = kt & 1;
        cp_wait<0>();
        __syncthreads();
        if (kt + 1 < KITERS) load_stage(kt + 1, s ^ 1);

#pragma unroll
        for (int ks = 0; ks < 2; ks++) {
            unsigned a_h[2][4], a_l[2][4];
#pragma unroll
            for (int mt = 0; mt < 2; mt++) {
                ldx4(a_h[mt], sA_hi(s) + aOff + mt * (16 * ASTR) + ks * 32);
                ldx4(a_l[mt], sA_lo(s) + aOff + mt * (16 * ASTR) + ks * 32);
            }
#pragma unroll
            for (int p = 0; p < NT / 2; p++) {
                unsigned b_h[4], b_l[4];
                ldx4(b_h, sB_hi(s) + bOff + p * (16 * ASTR) + ks * 32);
                ldx4(b_l, sB_lo(s) + bOff + p * (16 * ASTR) + ks * 32);
#pragma unroll
                for (int mt = 0; mt < 2; mt++)
#pragma unroll
                    for (int j = 0; j < 2; j++) {
                        const int nt = p * 2 + j;
                        mma16816(acc[mt][nt], a_h[mt], &b_h[j * 2]);
                        mma16816(acc[mt][nt], a_h[mt], &b_l[j * 2]);
                        mma16816(acc[mt][nt], a_l[mt], &b_h[j * 2]);
                    }
            }
        }
    }

    const int g  = lane >> 2;
    const int tg = lane & 3;
#pragma unroll
    for (int mt = 0; mt < 2; mt++) {
#pragma unroll
        for (int nt = 0; nt < NT; nt++) {
            const int nl = warpN * WNSP + nt * 8 + tg * 2;
            const int n  = n0 + nl;
            float2 bv = *(const float2*)&bias[n];
#pragma unroll
            for (int half = 0; half < 2; half++) {
                const int ml = warpM * 32 + mt * 16 + g + half * 8;
                const int m  = m0 + ml;
                float c0 = acc[mt][nt][half * 2 + 0] + bv.x;
                float c1 = acc[mt][nt][half * 2 + 1] + bv.y;
                if (mode == 0) {
                    const int h = n >> 6;
                    const int bb = m >> 11;
                    const int ss = m & 2047;
                    float v0 = c0 * scale, v1 = c1 * scale;
                    float r0, r1;
                    unsigned hp = pack_hi_res(v0, v1, r0, r1);
                    unsigned lp = pack_bf2(r0, r1);
                    size_t idx = ((size_t)(bb * HEADS + h) * SEQ + ss) * HDIM + (n & 63);
                    *(unsigned*)&Yhi[idx] = hp;
                    *(unsigned*)&Ylo[idx] = lp;
                } else {
                    *(float2*)&Yf[(size_t)m * EMBED + n] = make_float2(c0, c1);
                }
            }
        }
    }
}

#define QKV_BN 128
#define QKV_NBLK (EMBED / QKV_BN)   // 6
#define SMEM_GEMM_QKV (2 * (2 * A_SZ + 2 * QKV_BN * ASTR))   // 81920
#define O_BN 64
#define O_NBLK (EMBED / O_BN)       // 12
#define SMEM_GEMM_O (2 * (2 * A_SZ + 2 * O_BN * ASTR))       // 61440

// fused Q/K/V projection: proj = blockIdx.x / QKV_NBLK
__global__ void __launch_bounds__(256, 2)
mma_gemm_qkv_kernel(const __nv_bfloat16* __restrict__ xh, const __nv_bfloat16* __restrict__ xl,
                    const __nv_bfloat16* __restrict__ w0h, const __nv_bfloat16* __restrict__ w0l,
                    const __nv_bfloat16* __restrict__ w1h, const __nv_bfloat16* __restrict__ w1l,
                    const __nv_bfloat16* __restrict__ w2h, const __nv_bfloat16* __restrict__ w2l,
                    const float* __restrict__ b_q, const float* __restrict__ b_k,
                    const float* __restrict__ b_v,
                    __nv_bfloat16* qh, __nv_bfloat16* ql,
                    __nv_bfloat16* kh, __nv_bfloat16* kl,
                    __nv_bfloat16* vh, __nv_bfloat16* vl)
{
    extern __shared__ char smraw[];
    const unsigned sb = smem_u32(smraw);
    const int pj   = blockIdx.x / QKV_NBLK;
    const int nblk = blockIdx.x % QKV_NBLK;
    const __nv_bfloat16 *Bh, *Bl;
    const float* bias;
    __nv_bfloat16 *Yh, *Yl;
    float scale;
    if (pj == 0)      { Bh = w0h; Bl = w0l; bias = b_q; Yh = qh; Yl = ql; scale = 0.125f; }
    else if (pj == 1) { Bh = w1h; Bl = w1l; bias = b_k; Yh = kh; Yl = kl; scale = 1.0f; }
    else              { Bh = w2h; Bl = w2l; bias = b_v; Yh = vh; Yl = vl; scale = 1.0f; }
    gemm_body<QKV_BN>(sb, xh, xl, Bh, Bl, bias, nullptr, Yh, Yl, 0, scale,
                      blockIdx.y * GBM, nblk * QKV_BN);
}

// out-projection (64-wide N tiles, 3 CTAs/SM -> single ~86% wave)
__global__ void __launch_bounds__(256, 3)
mma_gemm_o_kernel(const __nv_bfloat16* __restrict__ ah, const __nv_bfloat16* __restrict__ al,
                  const __nv_bfloat16* __restrict__ w3h, const __nv_bfloat16* __restrict__ w3l,
                  const float* __restrict__ b_o, float* __restrict__ out)
{
    extern __shared__ char smraw[];
    const unsigned sb = smem_u32(smraw);
    gemm_body<O_BN>(sb, ah, al, w3h, w3l, b_o, out, nullptr, nullptr, 1, 1.0f,
                    blockIdx.y * GBM, blockIdx.x * O_BN);
}

// ---------------- Flash attention, split-KV x3, single-sync mainloop ----------------
#define QSTR 144
#define F_oQh 0
#define F_oQl 18432
#define KV_BASE 36864
#define KV_STAGE 36864
#define KV_oKh 0
#define KV_oKl 9216
#define KV_oVh 18432
#define KV_oVl 27648
#define SMEM_FLASH (KV_BASE + 2 * KV_STAGE)   // 110592

__global__ void __launch_bounds__(256)
flash_mma_kernel(const __nv_bfloat16* __restrict__ Qh, const __nv_bfloat16* __restrict__ Ql,
                 const __nv_bfloat16* __restrict__ Kh, const __nv_bfloat16* __restrict__ Kl,
                 const __nv_bfloat16* __restrict__ Vh, const __nv_bfloat16* __restrict__ Vl)
{
    extern __shared__ char smf[];
    const unsigned sb = smem_u32(smf);
    const int tid  = threadIdx.x;
    const int lane = tid & 31;
    const int wid  = tid >> 5;
    const int bh   = blockIdx.y;
    const int q0   = blockIdx.x * 128;
    const int split = blockIdx.z;

    const size_t qoff = ((size_t)bh * SEQ + q0) * HDIM;
    const size_t koff = (size_t)bh * SEQ * HDIM;
    const __nv_bfloat16* pQh = Qh + qoff;
    const __nv_bfloat16* pQl = Ql + qoff;
    const __nv_bfloat16* pKh = Kh + koff;
    const __nv_bfloat16* pKl = Kl + koff;
    const __nv_bfloat16* pVh = Vh + koff;
    const __nv_bfloat16* pVl = Vl + koff;

#pragma unroll
    for (int i = 0; i < 4; i++) {
        int task = tid + i * 256;
        int r = task >> 3, c = task & 7;
        cp16(sb + F_oQh + r * QSTR + c * 16, pQh + (size_t)r * HDIM + c * 8);
        cp16(sb + F_oQl + r * QSTR + c * 16, pQl + (size_t)r * HDIM + c * 8);
    }
    cp_commit();

    auto load_kv = [&](int kt, int s) {
        const unsigned st = sb + KV_BASE + s * KV_STAGE;
        const int k0 = kt * 64;
#pragma unroll
        for (int i = 0; i < 2; i++) {
            int task = tid + i * 256;
            int r = task >> 3, c = task & 7;
            size_t go = (size_t)(k0 + r) * HDIM + c * 8;
            unsigned so = r * QSTR + c * 16;
            cp16(st + KV_oKh + so, pKh + go);
            cp16(st + KV_oKl + so, pKl + go);
            cp16(st + KV_oVh + so, pVh + go);
            cp16(st + KV_oVl + so, pVl + go);
        }
        cp_commit();
    };

    const int g  = lane >> 2;
    const int tg = lane & 3;
    const unsigned aAddr = sb + (unsigned)((wid * 16 + ((lane >> 3) & 1) * 8 + (lane & 7)) * QSTR
                                           + (lane >> 4) * 16);
    const unsigned kRel = (unsigned)((((lane >> 4) & 1) * 8 + (lane & 7)) * QSTR
                                     + ((lane >> 3) & 1) * 16);
    const unsigned vRel = (unsigned)((((lane >> 3) & 1) * 8 + (lane & 7)) * QSTR
                                     + (lane >> 4) * 16);

    float m0 = -INFINITY, m1 = -INFINITY, l0 = 0.f, l1 = 0.f;
    float o[8][4];
#pragma unroll
    for (int nf = 0; nf < 8; nf++)
#pragma unroll
        for (int j = 0; j < 4; j++) o[nf][j] = 0.f;

    // splits: 11 / 11 / 10 KV tiles
    const int kt0 = split * 11;
    const int kt1 = (split == 2) ? 32 : kt0 + 11;
    load_kv(kt0, 0);

    for (int kt = kt0; kt < kt1; kt++) {
        const int s = (kt - kt0) & 1;
        cp_wait<0>();
        __syncthreads();
        if (kt + 1 < kt1) load_kv(kt + 1, s ^ 1);

        const unsigned stK = sb + KV_BASE + s * KV_STAGE;

        float sc[8][4];
#pragma unroll
        for (int nf = 0; nf < 8; nf++)
#pragma unroll
            for (int j = 0; j < 4; j++) sc[nf][j] = 0.f;

#pragma unroll
        for (int ks = 0; ks < 4; ks++) {
            unsigned qhf[4], qlf[4];
            ldx4(qhf, aAddr + F_oQh + ks * 32);
            ldx4(qlf, aAddr + F_oQl + ks * 32);
#pragma unroll
            for (int p = 0; p < 4; p++) {
                unsigned khf[4], klf[4];
                ldx4(khf, stK + KV_oKh + kRel + p * (16 * QSTR) + ks * 32);
                ldx4(klf, stK + KV_oKl + kRel + p * (16 * QSTR) + ks * 32);
                mma16816(sc[2 * p],     qhf, &khf[0]);
                mma16816(sc[2 * p],     qhf, &klf[0]);
                mma16816(sc[2 * p],     qlf, &khf[0]);
                mma16816(sc[2 * p + 1], qhf, &khf[2]);
                mma16816(sc[2 * p + 1], qhf, &klf[2]);
                mma16816(sc[2 * p + 1], qlf, &khf[2]);
            }
        }

        float pm0 = sc[0][0], pm1 = sc[0][2];
#pragma unroll
        for (int nf = 0; nf < 8; nf++) {
            pm0 = fmaxf(pm0, fmaxf(sc[nf][0], sc[nf][1]));
            pm1 = fmaxf(pm1, fmaxf(sc[nf][2], sc[nf][3]));
        }
        pm0 = fmaxf(pm0, __shfl_xor_sync(0xffffffffu, pm0, 1, 4));
        pm0 = fmaxf(pm0, __shfl_xor_sync(0xffffffffu, pm0, 2, 4));
        pm1 = fmaxf(pm1, __shfl_xor_sync(0xffffffffu, pm1, 1, 4));
        pm1 = fmaxf(pm1, __shfl_xor_sync(0xffffffffu, pm1, 2, 4));
        const float mn0 = fmaxf(m0, pm0);
        const float mn1 = fmaxf(m1, pm1);
        const float al0 = __expf(m0 - mn0);
        const float al1 = __expf(m1 - mn1);
        m0 = mn0; m1 = mn1;
        float ps0 = 0.f, ps1 = 0.f;
#pragma unroll
        for (int nf = 0; nf < 8; nf++) {
            sc[nf][0] = __expf(sc[nf][0] - mn0);
            sc[nf][1] = __expf(sc[nf][1] - mn0);
            sc[nf][2] = __expf(sc[nf][2] - mn1);
            sc[nf][3] = __expf(sc[nf][3] - mn1);
            ps0 += sc[nf][0] + sc[nf][1];
            ps1 += sc[nf][2] + sc[nf][3];
        }
        ps0 += __shfl_xor_sync(0xffffffffu, ps0, 1, 4);
        ps0 += __shfl_xor_sync(0xffffffffu, ps0, 2, 4);
        ps1 += __shfl_xor_sync(0xffffffffu, ps1, 1, 4);
        ps1 += __shfl_xor_sync(0xffffffffu, ps1, 2, 4);
        l0 = l0 * al0 + ps0;
        l1 = l1 * al1 + ps1;
#pragma unroll
        for (int nf = 0; nf < 8; nf++) {
            o[nf][0] *= al0; o[nf][1] *= al0;
            o[nf][2] *= al1; o[nf][3] *= al1;
        }

#pragma unroll
        for (int kb = 0; kb < 4; kb++) {
            float r0, r1, r2, r3, r4, r5, r6, r7;
            unsigned pa_h[4], pa_l[4];
            pa_h[0] = pack_hi_res(sc[2 * kb][0],     sc[2 * kb][1],     r0, r1);
            pa_h[1] = pack_hi_res(sc[2 * kb][2],     sc[2 * kb][3],     r2, r3);
            pa_h[2] = pack_hi_res(sc[2 * kb + 1][0], sc[2 * kb + 1][1], r4, r5);
            pa_h[3] = pack_hi_res(sc[2 * kb + 1][2], sc[2 * kb + 1][3], r6, r7);
            pa_l[0] = pack_bf2(r0, r1);
            pa_l[1] = pack_bf2(r2, r3);
            pa_l[2] = pack_bf2(r4, r5);
            pa_l[3] = pack_bf2(r6, r7);
#pragma unroll
            for (int du = 0; du < 4; du++) {
                unsigned vhf[4], vlf[4];
                ldx4t(vhf, stK + KV_oVh + vRel + kb * (16 * QSTR) + du * 32);
                ldx4t(vlf, stK + KV_oVl + vRel + kb * (16 * QSTR) + du * 32);
                mma16816(o[du * 2],     pa_h, &vhf[0]);
                mma16816(o[du * 2],     pa_h, &vlf[0]);
                mma16816(o[du * 2],     pa_l, &vhf[0]);
                mma16816(o[du * 2 + 1], pa_h, &vhf[2]);
                mma16816(o[du * 2 + 1], pa_h, &vlf[2]);
                mma16816(o[du * 2 + 1], pa_l, &vhf[2]);
            }
        }
    }

    // ---- store unnormalized partials + (m, l) ----
    const int r0 = q0 + wid * 16 + g;
    const size_t prow = (size_t)(split * BH + bh) * SEQ + r0;
    float* Op0 = &g_Op[prow * HDIM];
    float* Op1 = &g_Op[(prow + 8) * HDIM];
#pragma unroll
    for (int nf = 0; nf < 8; nf++) {
        const int e = nf * 8 + tg * 2;
        *(float2*)&Op0[e] = make_float2(o[nf][0], o[nf][1]);
        *(float2*)&Op1[e] = make_float2(o[nf][2], o[nf][3]);
    }
    if (tg == 0) {
        g_Mp[prow] = m0;     g_Lp[prow] = l0;
        g_Mp[prow + 8] = m1; g_Lp[prow + 8] = l1;
    }
}

// ---------------- split-KV merge: combine NSPLIT partials -> bf16 hi/lo A ----------------
__global__ void __launch_bounds__(256)
merge_kernel(__nv_bfloat16* __restrict__ Ahi, __nv_bfloat16* __restrict__ Alo)
{
    int t = blockIdx.x * 256 + threadIdx.x;     // BHS * 16 tasks
    if (t >= BHS * (HDIM / 4)) return;
    const int c4  = t & 15;
    const size_t row = (size_t)(t >> 4);        // [0, BHS)
    const int bh = (int)(row / SEQ);
    const int s  = (int)(row - (size_t)bh * SEQ);

    float mm[NSPLIT], ll[NSPLIT];
    float M = -INFINITY;
#pragma unroll
    for (int i = 0; i < NSPLIT; i++) {
        mm[i] = g_Mp[(size_t)i * BHS + row];
        ll[i] = g_Lp[(size_t)i * BHS + row];
        M = fmaxf(M, mm[i]);
    }
    float w[NSPLIT], denom = 0.f;
#pragma unroll
    for (int i = 0; i < NSPLIT; i++) {
        w[i] = __expf(mm[i] - M);
        denom += ll[i] * w[i];
    }
    float inv = 1.f / denom;
#pragma unroll
    for (int i = 0; i < NSPLIT; i++) w[i] *= inv;

    float r0 = 0.f, r1 = 0.f, r2 = 0.f, r3 = 0.f;
#pragma unroll
    for (int i = 0; i < NSPLIT; i++) {
        float4 a = *(const float4*)&g_Op[((size_t)i * BHS + row) * HDIM + c4 * 4];
        r0 += a.x * w[i];
        r1 += a.y * w[i];
        r2 += a.z * w[i];
        r3 += a.w * w[i];
    }

    const int bb = bh / HEADS;
    const int h  = bh % HEADS;
    const size_t dst = ((size_t)(bb * SEQ + s)) * EMBED + h * HDIM + c4 * 4;
    float x0, x1, x2, x3;
    unsigned h0 = pack_hi_res(r0, r1, x0, x1);
    unsigned h1 = pack_hi_res(r2, r3, x2, x3);
    *(unsigned*)&Ahi[dst]     = h0;
    *(unsigned*)&Ahi[dst + 2] = h1;
    *(unsigned*)&Alo[dst]     = pack_bf2(x0, x1);
    *(unsigned*)&Alo[dst + 2] = pack_bf2(x2, x3);
}

// ---------------- driver ----------------
extern "C" void kernel_launch(void* const* d_in, const int* in_sizes, int n_in,
                              void* d_out, int out_size)
{
    const float *x, *w_q, *b_q, *w_k, *b_k, *w_v, *b_v, *w_o, *b_o;
    if (n_in == 9 && in_sizes[0] == EMBED && in_sizes[8] == NX) {
        b_k = (const float*)d_in[0]; b_o = (const float*)d_in[1];
        b_q = (const float*)d_in[2]; b_v = (const float*)d_in[3];
        w_k = (const float*)d_in[4]; w_o = (const float*)d_in[5];
        w_q = (const float*)d_in[6]; w_v = (const float*)d_in[7];
        x   = (const float*)d_in[8];
    } else if (n_in == 9 && in_sizes[0] == NX && in_sizes[2] == NW) {
        x   = (const float*)d_in[0];
        w_q = (const float*)d_in[1]; w_k = (const float*)d_in[2];
        w_v = (const float*)d_in[3]; w_o = (const float*)d_in[4];
        b_q = (const float*)d_in[5]; b_k = (const float*)d_in[6];
        b_v = (const float*)d_in[7]; b_o = (const float*)d_in[8];
    } else {
        x   = (const float*)d_in[0];
        w_q = (const float*)d_in[1]; b_q = (const float*)d_in[2];
        w_k = (const float*)d_in[3]; b_k = (const float*)d_in[4];
        w_v = (const float*)d_in[5]; b_v = (const float*)d_in[6];
        w_o = (const float*)d_in[7]; b_o = (const float*)d_in[8];
    }
    float* out = (float*)d_out;

    __nv_bfloat16 *xh, *xl, *w0h, *w0l, *w1h, *w1l, *w2h, *w2l, *w3h, *w3l;
    __nv_bfloat16 *qh, *ql, *kh, *kl, *vh, *vl, *ah, *al;
    cudaGetSymbolAddress((void**)&xh,  g_Xhi);  cudaGetSymbolAddress((void**)&xl,  g_Xlo);
    cudaGetSymbolAddress((void**)&w0h, g_W0hi); cudaGetSymbolAddress((void**)&w0l, g_W0lo);
    cudaGetSymbolAddress((void**)&w1h, g_W1hi); cudaGetSymbolAddress((void**)&w1l, g_W1lo);
    cudaGetSymbolAddress((void**)&w2h, g_W2hi); cudaGetSymbolAddress((void**)&w2l, g_W2lo);
    cudaGetSymbolAddress((void**)&w3h, g_W3hi); cudaGetSymbolAddress((void**)&w3l, g_W3lo);
    cudaGetSymbolAddress((void**)&qh,  g_Qh);   cudaGetSymbolAddress((void**)&ql,  g_Ql);
    cudaGetSymbolAddress((void**)&kh,  g_Kh);   cudaGetSymbolAddress((void**)&kl,  g_Kl);
    cudaGetSymbolAddress((void**)&vh,  g_Vh);   cudaGetSymbolAddress((void**)&vl,  g_Vl);
    cudaGetSymbolAddress((void**)&ah,  g_Ahi);  cudaGetSymbolAddress((void**)&al,  g_Alo);

    cudaFuncSetAttribute(mma_gemm_qkv_kernel,
                         cudaFuncAttributeMaxDynamicSharedMemorySize, SMEM_GEMM_QKV);
    cudaFuncSetAttribute(mma_gemm_o_kernel,
                         cudaFuncAttributeMaxDynamicSharedMemorySize, SMEM_GEMM_O);
    cudaFuncSetAttribute(flash_mma_kernel,
                         cudaFuncAttributeMaxDynamicSharedMemorySize, SMEM_FLASH);

    convert_all_kernel<<<(CONV_TASKS + 255) / 256, 256>>>(
        x, w_q, w_k, w_v, w_o,
        xh, xl, w0h, w0l, w1h, w1l, w2h, w2l, w3h, w3l);

    dim3 qkvgrid(3 * QKV_NBLK, MROWS / GBM);        // (18, 32)
    mma_gemm_qkv_kernel<<<qkvgrid, 256, SMEM_GEMM_QKV>>>(
        xh, xl, w0h, w0l, w1h, w1l, w2h, w2l,
        b_q, b_k, b_v, qh, ql, kh, kl, vh, vl);

    dim3 agrid(SEQ / 128, BH, NSPLIT);              // (16, 24, 3)
    flash_mma_kernel<<<agrid, 256, SMEM_FLASH>>>(qh, ql, kh, kl, vh, vl);

    merge_kernel<<<(BHS * (HDIM / 4) + 255) / 256, 256>>>(ah, al);

    dim3 ogrid(O_NBLK, MROWS / GBM);                // (12, 32)
    mma_gemm_o_kernel<<<ogrid, 256, SMEM_GEMM_O>>>(ah, al, w3h, w3l, b_o, out);
}